// round 7
// baseline (speedup 1.0000x reference)
#include <cuda_runtime.h>
#include <cuda_bf16.h>
#include <math.h>
#include <stdint.h>

#define L_SEQ   4096
#define D_MODEL 1024
#define N_HEADS 16
#define HEAD_DIM 64
#define P_DIM   128
#define B_SIZE  4
#define M_FULL  (B_SIZE * L_SEQ)   // 16384
#define M_KV    (B_SIZE * P_DIM)   // 512
#define BH      (B_SIZE * N_HEADS) // 64

// ---------------- scratch (static device arrays) ---------------------------
__device__ __nv_bfloat16 g_xh[(size_t)M_FULL * D_MODEL];
__device__ __nv_bfloat16 g_xl[(size_t)M_FULL * D_MODEL];
__device__ __nv_bfloat16 g_wh[4 * (size_t)D_MODEL * D_MODEL];
__device__ __nv_bfloat16 g_wl[4 * (size_t)D_MODEL * D_MODEL];
__device__ __nv_bfloat16 g_ah[(size_t)M_FULL * D_MODEL];   // attn out hi
__device__ __nv_bfloat16 g_al[(size_t)M_FULL * D_MODEL];   // attn out lo
__device__ __nv_bfloat16 g_qh[(size_t)M_FULL * D_MODEL];   // roped Q hi
__device__ __nv_bfloat16 g_ql[(size_t)M_FULL * D_MODEL];   // roped Q lo

__device__ float g_K[(size_t)M_KV * D_MODEL];
__device__ float g_V[(size_t)M_KV * D_MODEL];

__device__ __nv_bfloat16 g_kph[BH * P_DIM * HEAD_DIM];     // K_proj [bh][p][d] hi
__device__ __nv_bfloat16 g_kpl[BH * P_DIM * HEAD_DIM];
__device__ __nv_bfloat16 g_vth[BH * HEAD_DIM * P_DIM];     // V_proj^T [bh][d][p] hi
__device__ __nv_bfloat16 g_vtl[BH * HEAD_DIM * P_DIM];

// ---------------------------------------------------------------------------
// fp32 -> bf16 hi/lo split.
// ---------------------------------------------------------------------------
__global__ void __launch_bounds__(256)
convert_split(const float* __restrict__ src, int dsel, size_t off, size_t n4)
{
    __nv_bfloat16* hb = (dsel == 0) ? g_xh : g_wh;
    __nv_bfloat16* lb = (dsel == 0) ? g_xl : g_wl;
    hb += off; lb += off;
    const float4* s4 = (const float4*)src;
    for (size_t i = blockIdx.x * (size_t)blockDim.x + threadIdx.x; i < n4;
         i += (size_t)gridDim.x * blockDim.x) {
        float4 v = s4[i];
        union { __nv_bfloat16 b[4]; uint2 u; } H, L;
        float f[4] = {v.x, v.y, v.z, v.w};
#pragma unroll
        for (int j = 0; j < 4; j++) {
            __nv_bfloat16 h = __float2bfloat16_rn(f[j]);
            H.b[j] = h;
            L.b[j] = __float2bfloat16_rn(f[j] - __bfloat162float(h));
        }
        ((uint2*)hb)[i] = H.u;
        ((uint2*)lb)[i] = L.u;
    }
}

// ---------------------------------------------------------------------------
// mma.sync helpers
// ---------------------------------------------------------------------------
__device__ __forceinline__ uint32_t sptr(const void* p) {
    return (uint32_t)__cvta_generic_to_shared(p);
}
__device__ __forceinline__ void ldm4(uint32_t* r, uint32_t a) {
    asm volatile("ldmatrix.sync.aligned.m8n8.x4.shared.b16 {%0,%1,%2,%3}, [%4];"
                 : "=r"(r[0]), "=r"(r[1]), "=r"(r[2]), "=r"(r[3]) : "r"(a));
}
__device__ __forceinline__ void mma_bf16(float* c, const uint32_t* a, uint32_t b0, uint32_t b1) {
    asm volatile(
        "mma.sync.aligned.m16n8k16.row.col.f32.bf16.bf16.f32 "
        "{%0,%1,%2,%3}, {%4,%5,%6,%7}, {%8,%9}, {%0,%1,%2,%3};"
        : "+f"(c[0]), "+f"(c[1]), "+f"(c[2]), "+f"(c[3])
        : "r"(a[0]), "r"(a[1]), "r"(a[2]), "r"(a[3]), "r"(b0), "r"(b1));
}
__device__ __forceinline__ void cpa16(uint32_t s, const void* g) {
    asm volatile("cp.async.ca.shared.global [%0], [%1], 16;" :: "r"(s), "l"(g));
}
__device__ __forceinline__ void split2(float x, float y, uint32_t& h, uint32_t& l) {
    union { __nv_bfloat162 v; uint32_t u; } H, L;
    __nv_bfloat16 xh = __float2bfloat16_rn(x);
    __nv_bfloat16 yh = __float2bfloat16_rn(y);
    H.v = __nv_bfloat162(xh, yh);
    L.v = __nv_bfloat162(__float2bfloat16_rn(x - __bfloat162float(xh)),
                         __float2bfloat16_rn(y - __bfloat162float(yh)));
    h = H.u; l = L.u;
}

// ---------------------------------------------------------------------------
// bf16x3 NT GEMM, 128x256 tile, BK=32, 3-stage cp.async pipeline.
// 8 warps as 2(m) x 4(n), warp tile 64x64.
// Stage layout (bf16 elems): AH[128*SPAD] AL[128*SPAD] BH[256*SPAD] BL[256*SPAD]
// ---------------------------------------------------------------------------
#define SPAD     40
#define ST_AH    0
#define ST_AL    (128 * SPAD)            // 5120
#define ST_BH    (2 * 128 * SPAD)        // 10240
#define ST_BL    (ST_BH + 256 * SPAD)    // 20480
#define ST_ELEMS (ST_BL + 256 * SPAD)    // 30720 elems = 61440 B
#define SM_GEMM  (3 * ST_ELEMS * 2)      // 184320 B

template<int ROPE, int GATHER, int ASEL, int WOFF, int CSEL>
__global__ void __launch_bounds__(256, 1)
gemm_bf16x3(const float* __restrict__ fcos, const float* __restrict__ fsin,
            float* __restrict__ Cext, int posmask)
{
    extern __shared__ __nv_bfloat16 sbuf[];

    const __nv_bfloat16* Ah = (ASEL == 0) ? g_xh : g_ah;
    const __nv_bfloat16* Al = (ASEL == 0) ? g_xl : g_al;
    const __nv_bfloat16* Bh = g_wh + (size_t)WOFF * D_MODEL * D_MODEL;
    const __nv_bfloat16* Bl = g_wl + (size_t)WOFF * D_MODEL * D_MODEL;
    float* C = (CSEL == 1) ? g_K : (CSEL == 2) ? g_V : Cext;
    const __nv_bfloat16* mats[4] = {Ah, Al, Bh, Bl};

    const int tid  = threadIdx.x;
    const int warp = tid >> 5;
    const int lane = tid & 31;
    const int wm   = warp & 1;           // 2 m-slabs of 64
    const int wn   = warp >> 1;          // 4 n-slabs of 64
    const int m_tile = blockIdx.y * 128;
    const int n_tile = blockIdx.x * 256;
    const int lr = lane & 15;
    const int lh = lane >> 4;

    float acc[4][8][4];
#pragma unroll
    for (int i = 0; i < 4; i++)
#pragma unroll
        for (int j = 0; j < 8; j++)
#pragma unroll
            for (int q = 0; q < 4; q++) acc[i][j][q] = 0.f;

    // 3072 16B copies per chunk: A 1024 (hi+lo), B 2048 (hi+lo); 12/thread
    auto load_chunk = [&](int st, int k0) {
#pragma unroll
        for (int t = 0; t < 12; t++) {
            int idx = tid + t * 256;
            int mtx, row, c16;
            if (idx < 1024) {
                mtx = idx >> 9;                    // 0=AH 1=AL
                int rem = idx & 511;
                row = rem >> 2; c16 = rem & 3;
            } else {
                int j = idx - 1024;
                mtx = 2 + (j >> 10);               // 2=BH 3=BL
                int rem = j & 1023;
                row = rem >> 2; c16 = rem & 3;
            }
            int grow;
            if (mtx < 2) {
                int m = m_tile + row;
                grow = GATHER ? ((m >> 7) * L_SEQ + (m & 127)) : m;
            } else {
                grow = n_tile + row;
            }
            const int soff = (mtx == 0) ? ST_AH : (mtx == 1) ? ST_AL
                           : (mtx == 2) ? ST_BH : ST_BL;
            cpa16(sptr(sbuf + st * ST_ELEMS + soff + row * SPAD + c16 * 8),
                  mats[mtx] + (size_t)grow * 1024 + k0 + c16 * 8);
        }
    };

    load_chunk(0, 0);
    asm volatile("cp.async.commit_group;" ::: "memory");
    load_chunk(1, 32);
    asm volatile("cp.async.commit_group;" ::: "memory");

    for (int i = 0; i < 32; i++) {
        if (i + 2 < 32) {
            load_chunk((i + 2) % 3, (i + 2) * 32);
            asm volatile("cp.async.commit_group;" ::: "memory");
        }
        if (i < 30)      asm volatile("cp.async.wait_group 2;" ::: "memory");
        else if (i == 30) asm volatile("cp.async.wait_group 1;" ::: "memory");
        else              asm volatile("cp.async.wait_group 0;" ::: "memory");
        __syncthreads();

        const __nv_bfloat16* bAh = sbuf + (i % 3) * ST_ELEMS + ST_AH;
        const __nv_bfloat16* bAl = sbuf + (i % 3) * ST_ELEMS + ST_AL;
        const __nv_bfloat16* bBh = sbuf + (i % 3) * ST_ELEMS + ST_BH;
        const __nv_bfloat16* bBl = sbuf + (i % 3) * ST_ELEMS + ST_BL;

#pragma unroll
        for (int ks = 0; ks < 32; ks += 16) {
            uint32_t afh[4][4], afl[4][4];
#pragma unroll
            for (int mf = 0; mf < 4; mf++) {
                ldm4(afh[mf], sptr(bAh + (wm * 64 + mf * 16 + lr) * SPAD + ks + lh * 8));
                ldm4(afl[mf], sptr(bAl + (wm * 64 + mf * 16 + lr) * SPAD + ks + lh * 8));
            }
#pragma unroll
            for (int g = 0; g < 4; g++) {
                uint32_t bfh[4], bfl[4];
                ldm4(bfh, sptr(bBh + (wn * 64 + g * 16 + lr) * SPAD + ks + lh * 8));
                ldm4(bfl, sptr(bBl + (wn * 64 + g * 16 + lr) * SPAD + ks + lh * 8));
#pragma unroll
                for (int mf = 0; mf < 4; mf++) {
                    mma_bf16(acc[mf][2*g],   afh[mf], bfh[0], bfh[2]);
                    mma_bf16(acc[mf][2*g],   afh[mf], bfl[0], bfl[2]);
                    mma_bf16(acc[mf][2*g],   afl[mf], bfh[0], bfh[2]);
                    mma_bf16(acc[mf][2*g+1], afh[mf], bfh[1], bfh[3]);
                    mma_bf16(acc[mf][2*g+1], afh[mf], bfl[1], bfl[3]);
                    mma_bf16(acc[mf][2*g+1], afl[mf], bfh[1], bfh[3]);
                }
            }
        }
        __syncthreads();
    }

    // ---- epilogue: acc lane layout = rows {l/4, l/4+8}, cols (l%4)*2+{0,1}
    const int qrow = lane >> 2;
    const int qcol = (lane & 3) * 2;
#pragma unroll
    for (int mf = 0; mf < 4; mf++)
#pragma unroll
        for (int nf = 0; nf < 8; nf++) {
            int n = n_tile + wn * 64 + nf * 8 + qcol;
#pragma unroll
            for (int hhalf = 0; hhalf < 2; hhalf++) {
                int m = m_tile + wm * 64 + mf * 16 + qrow + hhalf * 8;
                float v0 = acc[mf][nf][hhalf * 2];
                float v1 = acc[mf][nf][hhalf * 2 + 1];
                float o0 = v0, o1 = v1;
                if (ROPE) {
                    int pos = m & posmask;
                    int j   = (n & 63) >> 1;
                    float c = __ldg(fcos + pos * 32 + j);
                    float s = __ldg(fsin + pos * 32 + j);
                    o0 = v0 * c - v1 * s;
                    o1 = v0 * s + v1 * c;
                }
                if (CSEL == 0) {
                    uint32_t h, l;
                    split2(o0, o1, h, l);
                    *(uint32_t*)(g_qh + (size_t)m * 1024 + n) = h;
                    *(uint32_t*)(g_ql + (size_t)m * 1024 + n) = l;
                } else {
                    *(float2*)(C + (size_t)m * 1024 + n) = make_float2(o0, o1);
                }
            }
        }
}

// ---------------------------------------------------------------------------
// K_proj / V_proj (tril): grid (BH, 8).  bf16 hi/lo outputs.
// ---------------------------------------------------------------------------
__global__ void __launch_bounds__(256)
proj_kernel(const float* __restrict__ kpm, const float* __restrict__ vpm)
{
    __shared__ float Ts[128][9];
    const int bh = blockIdx.x;
    const int b  = bh >> 4;
    const int hh = bh & 15;
    const int d0 = blockIdx.y * 8;
    const int tid = threadIdx.x;

    for (int idx = tid; idx < 128 * 8; idx += 256) {
        int l = idx >> 3, d = idx & 7;
        Ts[l][d] = g_K[(size_t)(b * 128 + l) * 1024 + hh * 64 + d0 + d];
    }
    __syncthreads();
#pragma unroll
    for (int t = 0; t < 4; t++) {
        int o = tid + t * 256;
        int p = o >> 3, d = o & 7;
        const float* pr = kpm + (size_t)p * 4096;
        float s = 0.f;
        for (int l = 0; l <= p; l++) s = fmaf(pr[l], Ts[l][d], s);
        __nv_bfloat16 h = __float2bfloat16_rn(s);
        size_t idx = (size_t)bh * 8192 + p * 64 + (d0 + d);
        g_kph[idx] = h;
        g_kpl[idx] = __float2bfloat16_rn(s - __bfloat162float(h));
    }
    __syncthreads();
    for (int idx = tid; idx < 128 * 8; idx += 256) {
        int l = idx >> 3, d = idx & 7;
        Ts[l][d] = g_V[(size_t)(b * 128 + l) * 1024 + hh * 64 + d0 + d];
    }
    __syncthreads();
#pragma unroll
    for (int t = 0; t < 4; t++) {
        int o = tid + t * 256;
        int p = o >> 3, d = o & 7;
        const float* pr = vpm + (size_t)p * 4096;
        float s = 0.f;
        for (int l = 0; l <= p; l++) s = fmaf(pr[l], Ts[l][d], s);
        __nv_bfloat16 h = __float2bfloat16_rn(s);
        size_t idx = (size_t)bh * 8192 + (d0 + d) * 128 + p;
        g_vth[idx] = h;
        g_vtl[idx] = __float2bfloat16_rn(s - __bfloat162float(h));
    }
}

// ---------------------------------------------------------------------------
// Flash-style mma attention (unchanged from R6, passing).
// ---------------------------------------------------------------------------
#define AT_QH 0
#define AT_QL 18432
#define AT_KH 36864
#define AT_KL 55296
#define AT_VH 73728
#define AT_VL 91136
#define ATTN_SMEM 108544

__global__ void __launch_bounds__(256)
attn_kernel()
{
    extern __shared__ char smem[];
    const int bh = blockIdx.y;
    const int b  = bh >> 4;
    const int hh = bh & 15;
    const int l0 = blockIdx.x * 128;
    const int tid  = threadIdx.x;
    const int wp   = tid >> 5;
    const int lane = tid & 31;
    const int lr   = lane & 15;
    const int lh   = lane >> 4;
    const int qrow = lane >> 2;
    const int qcol = (lane & 3) * 2;

    const size_t qbase = (size_t)(b * L_SEQ + l0) * 1024 + hh * 64;
#pragma unroll
    for (int t = 0; t < 4; t++) {
        int i = tid + t * 256;
        int r = i >> 3, c = i & 7;
        cpa16(sptr(smem + AT_QH + r * 144 + c * 16), g_qh + qbase + (size_t)r * 1024 + c * 8);
        cpa16(sptr(smem + AT_QL + r * 144 + c * 16), g_ql + qbase + (size_t)r * 1024 + c * 8);
        cpa16(sptr(smem + AT_KH + r * 144 + c * 16), g_kph + (size_t)bh * 8192 + r * 64 + c * 8);
        cpa16(sptr(smem + AT_KL + r * 144 + c * 16), g_kpl + (size_t)bh * 8192 + r * 64 + c * 8);
        int rv = i >> 4, cv = i & 15;
        cpa16(sptr(smem + AT_VH + rv * 272 + cv * 16), g_vth + (size_t)bh * 8192 + rv * 128 + cv * 8);
        cpa16(sptr(smem + AT_VL + rv * 272 + cv * 16), g_vtl + (size_t)bh * 8192 + rv * 128 + cv * 8);
    }
    asm volatile("cp.async.commit_group;" ::: "memory");
    asm volatile("cp.async.wait_group 0;" ::: "memory");
    __syncthreads();

    float acc[16][4];
#pragma unroll
    for (int i = 0; i < 16; i++)
#pragma unroll
        for (int q = 0; q < 4; q++) acc[i][q] = 0.f;

#pragma unroll
    for (int ks = 0; ks < 4; ks++) {
        uint32_t aqh[4], aql[4];
        ldm4(aqh, sptr(smem + AT_QH + (wp * 16 + lr) * 144 + ks * 32 + lh * 16));
        ldm4(aql, sptr(smem + AT_QL + (wp * 16 + lr) * 144 + ks * 32 + lh * 16));
#pragma unroll
        for (int g = 0; g < 8; g++) {
            uint32_t bkh[4], bkl[4];
            ldm4(bkh, sptr(smem + AT_KH + (g * 16 + lr) * 144 + ks * 32 + lh * 16));
            ldm4(bkl, sptr(smem + AT_KL + (g * 16 + lr) * 144 + ks * 32 + lh * 16));
            mma_bf16(acc[2*g],   aqh, bkh[0], bkh[2]);
            mma_bf16(acc[2*g],   aqh, bkl[0], bkl[2]);
            mma_bf16(acc[2*g],   aql, bkh[0], bkh[2]);
            mma_bf16(acc[2*g+1], aqh, bkh[1], bkh[3]);
            mma_bf16(acc[2*g+1], aqh, bkl[1], bkl[3]);
            mma_bf16(acc[2*g+1], aql, bkh[1], bkh[3]);
        }
    }

#pragma unroll
    for (int i = 0; i < 16; i++)
#pragma unroll
        for (int q = 0; q < 4; q++) acc[i][q] *= 0.125f;

    if (blockIdx.x == 0) {
        const int r0 = wp * 16 + qrow;
        const int r1 = r0 + 8;
#pragma unroll
        for (int nf = 0; nf < 16; nf++) {
            int p0 = nf * 8 + qcol;
            if (p0 > r0)     acc[nf][0] = -1e30f;
            if (p0 + 1 > r0) acc[nf][1] = -1e30f;
            if (p0 > r1)     acc[nf][2] = -1e30f;
            if (p0 + 1 > r1) acc[nf][3] = -1e30f;
        }
    }

    float mx0 = -1e30f, mx1 = -1e30f;
#pragma unroll
    for (int nf = 0; nf < 16; nf++) {
        mx0 = fmaxf(mx0, fmaxf(acc[nf][0], acc[nf][1]));
        mx1 = fmaxf(mx1, fmaxf(acc[nf][2], acc[nf][3]));
    }
    mx0 = fmaxf(mx0, __shfl_xor_sync(0xffffffffu, mx0, 1));
    mx0 = fmaxf(mx0, __shfl_xor_sync(0xffffffffu, mx0, 2));
    mx1 = fmaxf(mx1, __shfl_xor_sync(0xffffffffu, mx1, 1));
    mx1 = fmaxf(mx1, __shfl_xor_sync(0xffffffffu, mx1, 2));

    float s0 = 0.f, s1 = 0.f;
#pragma unroll
    for (int nf = 0; nf < 16; nf++) {
        acc[nf][0] = __expf(acc[nf][0] - mx0);
        acc[nf][1] = __expf(acc[nf][1] - mx0);
        acc[nf][2] = __expf(acc[nf][2] - mx1);
        acc[nf][3] = __expf(acc[nf][3] - mx1);
        s0 += acc[nf][0] + acc[nf][1];
        s1 += acc[nf][2] + acc[nf][3];
    }
    s0 += __shfl_xor_sync(0xffffffffu, s0, 1);
    s0 += __shfl_xor_sync(0xffffffffu, s0, 2);
    s1 += __shfl_xor_sync(0xffffffffu, s1, 1);
    s1 += __shfl_xor_sync(0xffffffffu, s1, 2);
    const float inv0 = 1.0f / s0;
    const float inv1 = 1.0f / s1;

    float o[8][4];
#pragma unroll
    for (int i = 0; i < 8; i++)
#pragma unroll
        for (int q = 0; q < 4; q++) o[i][q] = 0.f;

#pragma unroll
    for (int kc = 0; kc < 8; kc++) {
        uint32_t awh[4], awl[4];
        split2(acc[2*kc][0],   acc[2*kc][1],   awh[0], awl[0]);
        split2(acc[2*kc][2],   acc[2*kc][3],   awh[1], awl[1]);
        split2(acc[2*kc+1][0], acc[2*kc+1][1], awh[2], awl[2]);
        split2(acc[2*kc+1][2], acc[2*kc+1][3], awh[3], awl[3]);
#pragma unroll
        for (int g = 0; g < 4; g++) {
            uint32_t bvh[4], bvl[4];
            ldm4(bvh, sptr(smem + AT_VH + (g * 16 + lr) * 272 + kc * 32 + lh * 16));
            ldm4(bvl, sptr(smem + AT_VL + (g * 16 + lr) * 272 + kc * 32 + lh * 16));
            mma_bf16(o[2*g],   awh, bvh[0], bvh[2]);
            mma_bf16(o[2*g],   awh, bvl[0], bvl[2]);
            mma_bf16(o[2*g],   awl, bvh[0], bvh[2]);
            mma_bf16(o[2*g+1], awh, bvh[1], bvh[3]);
            mma_bf16(o[2*g+1], awh, bvl[1], bvl[3]);
            mma_bf16(o[2*g+1], awl, bvh[1], bvh[3]);
        }
    }

    const size_t row0 = (size_t)(b * L_SEQ + l0 + wp * 16 + qrow);
    const size_t row1 = row0 + 8;
#pragma unroll
    for (int nf = 0; nf < 8; nf++) {
        int col = hh * 64 + nf * 8 + qcol;
        uint32_t h01, l01, h23, l23;
        split2(o[nf][0] * inv0, o[nf][1] * inv0, h01, l01);
        split2(o[nf][2] * inv1, o[nf][3] * inv1, h23, l23);
        *(uint32_t*)(g_ah + row0 * 1024 + col) = h01;
        *(uint32_t*)(g_al + row0 * 1024 + col) = l01;
        *(uint32_t*)(g_ah + row1 * 1024 + col) = h23;
        *(uint32_t*)(g_al + row1 * 1024 + col) = l23;
    }
}

// ---------------------------------------------------------------------------
extern "C" void kernel_launch(void* const* d_in, const int* in_sizes, int n_in,
                              void* d_out, int out_size)
{
    const float* x    = (const float*)d_in[0];
    const float* fcos = (const float*)d_in[1];
    const float* fsin = (const float*)d_in[2];
    const float* Wq   = (const float*)d_in[3];
    const float* Wk   = (const float*)d_in[4];
    const float* Wv   = (const float*)d_in[5];
    const float* Wo   = (const float*)d_in[6];
    const float* kpm  = (const float*)d_in[7];
    const float* vpm  = (const float*)d_in[8];
    float* out = (float*)d_out;

    cudaFuncSetAttribute(attn_kernel,
                         cudaFuncAttributeMaxDynamicSharedMemorySize, ATTN_SMEM);
    cudaFuncSetAttribute(gemm_bf16x3<1,0,0,0,0>, cudaFuncAttributeMaxDynamicSharedMemorySize, SM_GEMM);
    cudaFuncSetAttribute(gemm_bf16x3<1,1,0,1,1>, cudaFuncAttributeMaxDynamicSharedMemorySize, SM_GEMM);
    cudaFuncSetAttribute(gemm_bf16x3<0,1,0,2,2>, cudaFuncAttributeMaxDynamicSharedMemorySize, SM_GEMM);
    cudaFuncSetAttribute(gemm_bf16x3<0,0,1,3,3>, cudaFuncAttributeMaxDynamicSharedMemorySize, SM_GEMM);

    const size_t DD4 = (size_t)D_MODEL * D_MODEL / 4;
    convert_split<<<2048, 256>>>(x,  0, 0,                  (size_t)M_FULL * D_MODEL / 4);
    convert_split<<<256,  256>>>(Wq, 1, 0,                  DD4);
    convert_split<<<256,  256>>>(Wk, 1, (size_t)D_MODEL*D_MODEL,   DD4);
    convert_split<<<256,  256>>>(Wv, 1, (size_t)2*D_MODEL*D_MODEL, DD4);
    convert_split<<<256,  256>>>(Wo, 1, (size_t)3*D_MODEL*D_MODEL, DD4);

    dim3 blk(256);
    // Q = rope(x @ Wq^T) -> bf16 hi/lo
    gemm_bf16x3<1,0,0,0,0><<<dim3(4, 128), blk, SM_GEMM>>>(fcos, fsin, nullptr, L_SEQ - 1);
    // K = rope(x[:,:128] @ Wk^T) fp32
    gemm_bf16x3<1,1,0,1,1><<<dim3(4, 4),   blk, SM_GEMM>>>(fcos, fsin, nullptr, P_DIM - 1);
    // V = x[:,:128] @ Wv^T fp32
    gemm_bf16x3<0,1,0,2,2><<<dim3(4, 4),   blk, SM_GEMM>>>(nullptr, nullptr, nullptr, 0);
    // Linformer tril projections -> bf16 hi/lo
    proj_kernel<<<dim3(BH, 8), blk>>>(kpm, vpm);
    // flash-style mma attention
    attn_kernel<<<dim3(L_SEQ / 128, BH), blk, ATTN_SMEM>>>();
    // out = attn @ Wo^T
    gemm_bf16x3<0,0,1,3,3><<<dim3(4, 128), blk, SM_GEMM>>>(nullptr, nullptr, out, 0);
}

// round 8
// speedup vs baseline: 1.3567x; 1.3567x over previous
#include <cuda_runtime.h>
#include <cuda_bf16.h>
#include <math.h>
#include <stdint.h>

#define L_SEQ   4096
#define D_MODEL 1024
#define N_HEADS 16
#define HEAD_DIM 64
#define P_DIM   128
#define B_SIZE  4
#define M_FULL  (B_SIZE * L_SEQ)   // 16384
#define M_KV    (B_SIZE * P_DIM)   // 512
#define BH      (B_SIZE * N_HEADS) // 64

// ---------------- scratch (static device arrays) ---------------------------
__device__ __nv_bfloat16 g_xh[(size_t)M_FULL * D_MODEL];
__device__ __nv_bfloat16 g_xl[(size_t)M_FULL * D_MODEL];
__device__ __nv_bfloat16 g_wh[4 * (size_t)D_MODEL * D_MODEL];
__device__ __nv_bfloat16 g_wl[4 * (size_t)D_MODEL * D_MODEL];
__device__ __nv_bfloat16 g_ah[(size_t)M_FULL * D_MODEL];   // attn out hi
__device__ __nv_bfloat16 g_al[(size_t)M_FULL * D_MODEL];   // attn out lo
__device__ __nv_bfloat16 g_qh[(size_t)M_FULL * D_MODEL];   // roped Q hi
__device__ __nv_bfloat16 g_ql[(size_t)M_FULL * D_MODEL];   // roped Q lo

__device__ float g_K[(size_t)M_KV * D_MODEL];
__device__ float g_V[(size_t)M_KV * D_MODEL];

__device__ __nv_bfloat16 g_kph[BH * P_DIM * HEAD_DIM];     // K_proj [bh][p][d] hi
__device__ __nv_bfloat16 g_kpl[BH * P_DIM * HEAD_DIM];
__device__ __nv_bfloat16 g_vth[BH * HEAD_DIM * P_DIM];     // V_proj^T [bh][d][p] hi
__device__ __nv_bfloat16 g_vtl[BH * HEAD_DIM * P_DIM];

// ---------------------------------------------------------------------------
// fp32 -> bf16 hi/lo split.
// ---------------------------------------------------------------------------
__global__ void __launch_bounds__(256)
convert_split(const float* __restrict__ src, int dsel, size_t off, size_t n4)
{
    __nv_bfloat16* hb = (dsel == 0) ? g_xh : g_wh;
    __nv_bfloat16* lb = (dsel == 0) ? g_xl : g_wl;
    hb += off; lb += off;
    const float4* s4 = (const float4*)src;
    for (size_t i = blockIdx.x * (size_t)blockDim.x + threadIdx.x; i < n4;
         i += (size_t)gridDim.x * blockDim.x) {
        float4 v = s4[i];
        union { __nv_bfloat16 b[4]; uint2 u; } H, L;
        float f[4] = {v.x, v.y, v.z, v.w};
#pragma unroll
        for (int j = 0; j < 4; j++) {
            __nv_bfloat16 h = __float2bfloat16_rn(f[j]);
            H.b[j] = h;
            L.b[j] = __float2bfloat16_rn(f[j] - __bfloat162float(h));
        }
        ((uint2*)hb)[i] = H.u;
        ((uint2*)lb)[i] = L.u;
    }
}

// ---------------------------------------------------------------------------
// mma.sync helpers
// ---------------------------------------------------------------------------
__device__ __forceinline__ uint32_t sptr(const void* p) {
    return (uint32_t)__cvta_generic_to_shared(p);
}
__device__ __forceinline__ void ldm4(uint32_t* r, uint32_t a) {
    asm volatile("ldmatrix.sync.aligned.m8n8.x4.shared.b16 {%0,%1,%2,%3}, [%4];"
                 : "=r"(r[0]), "=r"(r[1]), "=r"(r[2]), "=r"(r[3]) : "r"(a));
}
__device__ __forceinline__ void mma_bf16(float* c, const uint32_t* a, uint32_t b0, uint32_t b1) {
    asm volatile(
        "mma.sync.aligned.m16n8k16.row.col.f32.bf16.bf16.f32 "
        "{%0,%1,%2,%3}, {%4,%5,%6,%7}, {%8,%9}, {%0,%1,%2,%3};"
        : "+f"(c[0]), "+f"(c[1]), "+f"(c[2]), "+f"(c[3])
        : "r"(a[0]), "r"(a[1]), "r"(a[2]), "r"(a[3]), "r"(b0), "r"(b1));
}
__device__ __forceinline__ void cpa16(uint32_t s, const void* g) {
    asm volatile("cp.async.ca.shared.global [%0], [%1], 16;" :: "r"(s), "l"(g));
}
__device__ __forceinline__ void cpa16cg(uint32_t s, const void* g) {
    asm volatile("cp.async.cg.shared.global [%0], [%1], 16;" :: "r"(s), "l"(g));
}
__device__ __forceinline__ void split2(float x, float y, uint32_t& h, uint32_t& l) {
    union { __nv_bfloat162 v; uint32_t u; } H, L;
    __nv_bfloat16 xh = __float2bfloat16_rn(x);
    __nv_bfloat16 yh = __float2bfloat16_rn(y);
    H.v = __nv_bfloat162(xh, yh);
    L.v = __nv_bfloat162(__float2bfloat16_rn(x - __bfloat162float(xh)),
                         __float2bfloat16_rn(y - __bfloat162float(yh)));
    h = H.u; l = L.u;
}

// ---------------------------------------------------------------------------
// bf16x3 NT GEMM, 128x128 tile, BK=32, 3-stage cp.async pipeline.
// 8 warps 4(m)x2(n), warp tile 32x64 (R6 shape — 2 CTAs/SM).
// smem: unpadded 64B rows with XOR swizzle; stage = 4 mats * 8192 B = 32768 B.
// chunk (r, c16) stored at  r*64 + ((c16 ^ ((r>>1)&3)) << 4)  — conflict-free
// per 8-row ldmatrix phase.
// ---------------------------------------------------------------------------
#define STG_BYTES 32768
#define MAT_BYTES 8192
#define SM_GEMM   (3 * STG_BYTES)   // 98304 B -> 2 CTAs/SM

__device__ __forceinline__ uint32_t swzoff(int row, int c16) {
    return (uint32_t)(row * 64 + ((c16 ^ ((row >> 1) & 3)) << 4));
}

template<int ROPE, int GATHER, int ASEL, int WOFF, int CSEL>
__global__ void __launch_bounds__(256, 2)
gemm_bf16x3(const float* __restrict__ fcos, const float* __restrict__ fsin,
            float* __restrict__ Cext, int posmask)
{
    extern __shared__ char sbuf[];

    const __nv_bfloat16* Ah = (ASEL == 0) ? g_xh : g_ah;
    const __nv_bfloat16* Al = (ASEL == 0) ? g_xl : g_al;
    const __nv_bfloat16* Bh = g_wh + (size_t)WOFF * D_MODEL * D_MODEL;
    const __nv_bfloat16* Bl = g_wl + (size_t)WOFF * D_MODEL * D_MODEL;
    float* C = (CSEL == 1) ? g_K : (CSEL == 2) ? g_V : Cext;
    const __nv_bfloat16* mats[4] = {Ah, Al, Bh, Bl};

    const int tid  = threadIdx.x;
    const int warp = tid >> 5;
    const int lane = tid & 31;
    const int wm   = warp & 3;           // 4 m-slabs of 32
    const int wn   = warp >> 2;          // 2 n-slabs of 64
    const int m_tile = blockIdx.y * 128;
    const int n_tile = blockIdx.x * 128;
    const int lr = lane & 15;
    const int lh = lane >> 4;

    float acc[2][8][4];
#pragma unroll
    for (int i = 0; i < 2; i++)
#pragma unroll
        for (int j = 0; j < 8; j++)
#pragma unroll
            for (int q = 0; q < 4; q++) acc[i][j][q] = 0.f;

    // per chunk: 4 mats x 128 rows x 4 chunks = 2048 copies; 8/thread
    auto load_chunk = [&](int st, int k0) {
#pragma unroll
        for (int t = 0; t < 8; t++) {
            int idx = tid + t * 256;
            int mtx = idx >> 9;               // 0=AH 1=AL 2=BH 3=BL
            int rem = idx & 511;
            int row = rem >> 2;
            int c16 = rem & 3;
            int grow;
            if (mtx < 2) {
                int m = m_tile + row;
                grow = GATHER ? ((m >> 7) * L_SEQ + (m & 127)) : m;
            } else {
                grow = n_tile + row;
            }
            cpa16cg(sptr(sbuf + st * STG_BYTES + mtx * MAT_BYTES + swzoff(row, c16)),
                    mats[mtx] + (size_t)grow * 1024 + k0 + c16 * 8);
        }
    };

    load_chunk(0, 0);
    asm volatile("cp.async.commit_group;" ::: "memory");
    load_chunk(1, 32);
    asm volatile("cp.async.commit_group;" ::: "memory");

    for (int i = 0; i < 32; i++) {
        if (i + 2 < 32) {
            load_chunk((i + 2) % 3, (i + 2) * 32);
            asm volatile("cp.async.commit_group;" ::: "memory");
        }
        if (i < 30)       asm volatile("cp.async.wait_group 2;" ::: "memory");
        else if (i == 30) asm volatile("cp.async.wait_group 1;" ::: "memory");
        else              asm volatile("cp.async.wait_group 0;" ::: "memory");
        __syncthreads();

        const char* stg = sbuf + (i % 3) * STG_BYTES;

#pragma unroll
        for (int ks = 0; ks < 2; ks++) {          // k halves of 16
            const int cb = ks * 2 + lh;           // 16B chunk index
            uint32_t afh[2][4], afl[2][4];
#pragma unroll
            for (int mf = 0; mf < 2; mf++) {
                int row = wm * 32 + mf * 16 + lr;
                ldm4(afh[mf], sptr(stg + 0 * MAT_BYTES + swzoff(row, cb)));
                ldm4(afl[mf], sptr(stg + 1 * MAT_BYTES + swzoff(row, cb)));
            }
#pragma unroll
            for (int g = 0; g < 4; g++) {
                int row = wn * 64 + g * 16 + lr;
                uint32_t bfh[4], bfl[4];
                ldm4(bfh, sptr(stg + 2 * MAT_BYTES + swzoff(row, cb)));
                ldm4(bfl, sptr(stg + 3 * MAT_BYTES + swzoff(row, cb)));
#pragma unroll
                for (int mf = 0; mf < 2; mf++) {
                    mma_bf16(acc[mf][2*g],   afh[mf], bfh[0], bfh[2]);
                    mma_bf16(acc[mf][2*g],   afh[mf], bfl[0], bfl[2]);
                    mma_bf16(acc[mf][2*g],   afl[mf], bfh[0], bfh[2]);
                    mma_bf16(acc[mf][2*g+1], afh[mf], bfh[1], bfh[3]);
                    mma_bf16(acc[mf][2*g+1], afh[mf], bfl[1], bfl[3]);
                    mma_bf16(acc[mf][2*g+1], afl[mf], bfh[1], bfh[3]);
                }
            }
        }
        __syncthreads();
    }

    // ---- epilogue: acc lane layout = rows {l/4, l/4+8}, cols (l%4)*2+{0,1}
    const int qrow = lane >> 2;
    const int qcol = (lane & 3) * 2;
#pragma unroll
    for (int mf = 0; mf < 2; mf++)
#pragma unroll
        for (int nf = 0; nf < 8; nf++) {
            int n = n_tile + wn * 64 + nf * 8 + qcol;
#pragma unroll
            for (int hhalf = 0; hhalf < 2; hhalf++) {
                int m = m_tile + wm * 32 + mf * 16 + qrow + hhalf * 8;
                float v0 = acc[mf][nf][hhalf * 2];
                float v1 = acc[mf][nf][hhalf * 2 + 1];
                float o0 = v0, o1 = v1;
                if (ROPE) {
                    int pos = m & posmask;
                    int j   = (n & 63) >> 1;
                    float c = __ldg(fcos + pos * 32 + j);
                    float s = __ldg(fsin + pos * 32 + j);
                    o0 = v0 * c - v1 * s;
                    o1 = v0 * s + v1 * c;
                }
                if (CSEL == 0) {
                    uint32_t h, l;
                    split2(o0, o1, h, l);
                    *(uint32_t*)(g_qh + (size_t)m * 1024 + n) = h;
                    *(uint32_t*)(g_ql + (size_t)m * 1024 + n) = l;
                } else {
                    *(float2*)(C + (size_t)m * 1024 + n) = make_float2(o0, o1);
                }
            }
        }
}

// ---------------------------------------------------------------------------
// K_proj / V_proj (tril): grid (BH, 8).  bf16 hi/lo outputs.
// ---------------------------------------------------------------------------
__global__ void __launch_bounds__(256)
proj_kernel(const float* __restrict__ kpm, const float* __restrict__ vpm)
{
    __shared__ float Ts[128][9];
    const int bh = blockIdx.x;
    const int b  = bh >> 4;
    const int hh = bh & 15;
    const int d0 = blockIdx.y * 8;
    const int tid = threadIdx.x;

    for (int idx = tid; idx < 128 * 8; idx += 256) {
        int l = idx >> 3, d = idx & 7;
        Ts[l][d] = g_K[(size_t)(b * 128 + l) * 1024 + hh * 64 + d0 + d];
    }
    __syncthreads();
#pragma unroll
    for (int t = 0; t < 4; t++) {
        int o = tid + t * 256;
        int p = o >> 3, d = o & 7;
        const float* pr = kpm + (size_t)p * 4096;
        float s = 0.f;
        for (int l = 0; l <= p; l++) s = fmaf(pr[l], Ts[l][d], s);
        __nv_bfloat16 h = __float2bfloat16_rn(s);
        size_t idx = (size_t)bh * 8192 + p * 64 + (d0 + d);
        g_kph[idx] = h;
        g_kpl[idx] = __float2bfloat16_rn(s - __bfloat162float(h));
    }
    __syncthreads();
    for (int idx = tid; idx < 128 * 8; idx += 256) {
        int l = idx >> 3, d = idx & 7;
        Ts[l][d] = g_V[(size_t)(b * 128 + l) * 1024 + hh * 64 + d0 + d];
    }
    __syncthreads();
#pragma unroll
    for (int t = 0; t < 4; t++) {
        int o = tid + t * 256;
        int p = o >> 3, d = o & 7;
        const float* pr = vpm + (size_t)p * 4096;
        float s = 0.f;
        for (int l = 0; l <= p; l++) s = fmaf(pr[l], Ts[l][d], s);
        __nv_bfloat16 h = __float2bfloat16_rn(s);
        size_t idx = (size_t)bh * 8192 + (d0 + d) * 128 + p;
        g_vth[idx] = h;
        g_vtl[idx] = __float2bfloat16_rn(s - __bfloat162float(h));
    }
}

// ---------------------------------------------------------------------------
// Flash-style mma attention (unchanged from R6, passing).
// ---------------------------------------------------------------------------
#define AT_QH 0
#define AT_QL 18432
#define AT_KH 36864
#define AT_KL 55296
#define AT_VH 73728
#define AT_VL 91136
#define ATTN_SMEM 108544

__global__ void __launch_bounds__(256)
attn_kernel()
{
    extern __shared__ char smem[];
    const int bh = blockIdx.y;
    const int b  = bh >> 4;
    const int hh = bh & 15;
    const int l0 = blockIdx.x * 128;
    const int tid  = threadIdx.x;
    const int wp   = tid >> 5;
    const int lane = tid & 31;
    const int lr   = lane & 15;
    const int lh   = lane >> 4;
    const int qrow = lane >> 2;
    const int qcol = (lane & 3) * 2;

    const size_t qbase = (size_t)(b * L_SEQ + l0) * 1024 + hh * 64;
#pragma unroll
    for (int t = 0; t < 4; t++) {
        int i = tid + t * 256;
        int r = i >> 3, c = i & 7;
        cpa16(sptr(smem + AT_QH + r * 144 + c * 16), g_qh + qbase + (size_t)r * 1024 + c * 8);
        cpa16(sptr(smem + AT_QL + r * 144 + c * 16), g_ql + qbase + (size_t)r * 1024 + c * 8);
        cpa16(sptr(smem + AT_KH + r * 144 + c * 16), g_kph + (size_t)bh * 8192 + r * 64 + c * 8);
        cpa16(sptr(smem + AT_KL + r * 144 + c * 16), g_kpl + (size_t)bh * 8192 + r * 64 + c * 8);
        int rv = i >> 4, cv = i & 15;
        cpa16(sptr(smem + AT_VH + rv * 272 + cv * 16), g_vth + (size_t)bh * 8192 + rv * 128 + cv * 8);
        cpa16(sptr(smem + AT_VL + rv * 272 + cv * 16), g_vtl + (size_t)bh * 8192 + rv * 128 + cv * 8);
    }
    asm volatile("cp.async.commit_group;" ::: "memory");
    asm volatile("cp.async.wait_group 0;" ::: "memory");
    __syncthreads();

    float acc[16][4];
#pragma unroll
    for (int i = 0; i < 16; i++)
#pragma unroll
        for (int q = 0; q < 4; q++) acc[i][q] = 0.f;

#pragma unroll
    for (int ks = 0; ks < 4; ks++) {
        uint32_t aqh[4], aql[4];
        ldm4(aqh, sptr(smem + AT_QH + (wp * 16 + lr) * 144 + ks * 32 + lh * 16));
        ldm4(aql, sptr(smem + AT_QL + (wp * 16 + lr) * 144 + ks * 32 + lh * 16));
#pragma unroll
        for (int g = 0; g < 8; g++) {
            uint32_t bkh[4], bkl[4];
            ldm4(bkh, sptr(smem + AT_KH + (g * 16 + lr) * 144 + ks * 32 + lh * 16));
            ldm4(bkl, sptr(smem + AT_KL + (g * 16 + lr) * 144 + ks * 32 + lh * 16));
            mma_bf16(acc[2*g],   aqh, bkh[0], bkh[2]);
            mma_bf16(acc[2*g],   aqh, bkl[0], bkl[2]);
            mma_bf16(acc[2*g],   aql, bkh[0], bkh[2]);
            mma_bf16(acc[2*g+1], aqh, bkh[1], bkh[3]);
            mma_bf16(acc[2*g+1], aqh, bkl[1], bkl[3]);
            mma_bf16(acc[2*g+1], aql, bkh[1], bkh[3]);
        }
    }

#pragma unroll
    for (int i = 0; i < 16; i++)
#pragma unroll
        for (int q = 0; q < 4; q++) acc[i][q] *= 0.125f;

    if (blockIdx.x == 0) {
        const int r0 = wp * 16 + qrow;
        const int r1 = r0 + 8;
#pragma unroll
        for (int nf = 0; nf < 16; nf++) {
            int p0 = nf * 8 + qcol;
            if (p0 > r0)     acc[nf][0] = -1e30f;
            if (p0 + 1 > r0) acc[nf][1] = -1e30f;
            if (p0 > r1)     acc[nf][2] = -1e30f;
            if (p0 + 1 > r1) acc[nf][3] = -1e30f;
        }
    }

    float mx0 = -1e30f, mx1 = -1e30f;
#pragma unroll
    for (int nf = 0; nf < 16; nf++) {
        mx0 = fmaxf(mx0, fmaxf(acc[nf][0], acc[nf][1]));
        mx1 = fmaxf(mx1, fmaxf(acc[nf][2], acc[nf][3]));
    }
    mx0 = fmaxf(mx0, __shfl_xor_sync(0xffffffffu, mx0, 1));
    mx0 = fmaxf(mx0, __shfl_xor_sync(0xffffffffu, mx0, 2));
    mx1 = fmaxf(mx1, __shfl_xor_sync(0xffffffffu, mx1, 1));
    mx1 = fmaxf(mx1, __shfl_xor_sync(0xffffffffu, mx1, 2));

    float s0 = 0.f, s1 = 0.f;
#pragma unroll
    for (int nf = 0; nf < 16; nf++) {
        acc[nf][0] = __expf(acc[nf][0] - mx0);
        acc[nf][1] = __expf(acc[nf][1] - mx0);
        acc[nf][2] = __expf(acc[nf][2] - mx1);
        acc[nf][3] = __expf(acc[nf][3] - mx1);
        s0 += acc[nf][0] + acc[nf][1];
        s1 += acc[nf][2] + acc[nf][3];
    }
    s0 += __shfl_xor_sync(0xffffffffu, s0, 1);
    s0 += __shfl_xor_sync(0xffffffffu, s0, 2);
    s1 += __shfl_xor_sync(0xffffffffu, s1, 1);
    s1 += __shfl_xor_sync(0xffffffffu, s1, 2);
    const float inv0 = 1.0f / s0;
    const float inv1 = 1.0f / s1;

    float o[8][4];
#pragma unroll
    for (int i = 0; i < 8; i++)
#pragma unroll
        for (int q = 0; q < 4; q++) o[i][q] = 0.f;

#pragma unroll
    for (int kc = 0; kc < 8; kc++) {
        uint32_t awh[4], awl[4];
        split2(acc[2*kc][0],   acc[2*kc][1],   awh[0], awl[0]);
        split2(acc[2*kc][2],   acc[2*kc][3],   awh[1], awl[1]);
        split2(acc[2*kc+1][0], acc[2*kc+1][1], awh[2], awl[2]);
        split2(acc[2*kc+1][2], acc[2*kc+1][3], awh[3], awl[3]);
#pragma unroll
        for (int g = 0; g < 4; g++) {
            uint32_t bvh[4], bvl[4];
            ldm4(bvh, sptr(smem + AT_VH + (g * 16 + lr) * 272 + kc * 32 + lh * 16));
            ldm4(bvl, sptr(smem + AT_VL + (g * 16 + lr) * 272 + kc * 32 + lh * 16));
            mma_bf16(o[2*g],   awh, bvh[0], bvh[2]);
            mma_bf16(o[2*g],   awh, bvl[0], bvl[2]);
            mma_bf16(o[2*g],   awl, bvh[0], bvh[2]);
            mma_bf16(o[2*g+1], awh, bvh[1], bvh[3]);
            mma_bf16(o[2*g+1], awh, bvl[1], bvl[3]);
            mma_bf16(o[2*g+1], awl, bvh[1], bvh[3]);
        }
    }

    const size_t row0 = (size_t)(b * L_SEQ + l0 + wp * 16 + qrow);
    const size_t row1 = row0 + 8;
#pragma unroll
    for (int nf = 0; nf < 8; nf++) {
        int col = hh * 64 + nf * 8 + qcol;
        uint32_t h01, l01, h23, l23;
        split2(o[nf][0] * inv0, o[nf][1] * inv0, h01, l01);
        split2(o[nf][2] * inv1, o[nf][3] * inv1, h23, l23);
        *(uint32_t*)(g_ah + row0 * 1024 + col) = h01;
        *(uint32_t*)(g_al + row0 * 1024 + col) = l01;
        *(uint32_t*)(g_ah + row1 * 1024 + col) = h23;
        *(uint32_t*)(g_al + row1 * 1024 + col) = l23;
    }
}

// ---------------------------------------------------------------------------
extern "C" void kernel_launch(void* const* d_in, const int* in_sizes, int n_in,
                              void* d_out, int out_size)
{
    const float* x    = (const float*)d_in[0];
    const float* fcos = (const float*)d_in[1];
    const float* fsin = (const float*)d_in[2];
    const float* Wq   = (const float*)d_in[3];
    const float* Wk   = (const float*)d_in[4];
    const float* Wv   = (const float*)d_in[5];
    const float* Wo   = (const float*)d_in[6];
    const float* kpm  = (const float*)d_in[7];
    const float* vpm  = (const float*)d_in[8];
    float* out = (float*)d_out;

    cudaFuncSetAttribute(attn_kernel,
                         cudaFuncAttributeMaxDynamicSharedMemorySize, ATTN_SMEM);
    cudaFuncSetAttribute(gemm_bf16x3<1,0,0,0,0>, cudaFuncAttributeMaxDynamicSharedMemorySize, SM_GEMM);
    cudaFuncSetAttribute(gemm_bf16x3<1,1,0,1,1>, cudaFuncAttributeMaxDynamicSharedMemorySize, SM_GEMM);
    cudaFuncSetAttribute(gemm_bf16x3<0,1,0,2,2>, cudaFuncAttributeMaxDynamicSharedMemorySize, SM_GEMM);
    cudaFuncSetAttribute(gemm_bf16x3<0,0,1,3,3>, cudaFuncAttributeMaxDynamicSharedMemorySize, SM_GEMM);

    const size_t DD4 = (size_t)D_MODEL * D_MODEL / 4;
    convert_split<<<2048, 256>>>(x,  0, 0,                  (size_t)M_FULL * D_MODEL / 4);
    convert_split<<<256,  256>>>(Wq, 1, 0,                  DD4);
    convert_split<<<256,  256>>>(Wk, 1, (size_t)D_MODEL*D_MODEL,   DD4);
    convert_split<<<256,  256>>>(Wv, 1, (size_t)2*D_MODEL*D_MODEL, DD4);
    convert_split<<<256,  256>>>(Wo, 1, (size_t)3*D_MODEL*D_MODEL, DD4);

    dim3 blk(256);
    // Q = rope(x @ Wq^T) -> bf16 hi/lo
    gemm_bf16x3<1,0,0,0,0><<<dim3(8, 128), blk, SM_GEMM>>>(fcos, fsin, nullptr, L_SEQ - 1);
    // K = rope(x[:,:128] @ Wk^T) fp32
    gemm_bf16x3<1,1,0,1,1><<<dim3(8, 4),   blk, SM_GEMM>>>(fcos, fsin, nullptr, P_DIM - 1);
    // V = x[:,:128] @ Wv^T fp32
    gemm_bf16x3<0,1,0,2,2><<<dim3(8, 4),   blk, SM_GEMM>>>(nullptr, nullptr, nullptr, 0);
    // Linformer tril projections -> bf16 hi/lo
    proj_kernel<<<dim3(BH, 8), blk>>>(kpm, vpm);
    // flash-style mma attention
    attn_kernel<<<dim3(L_SEQ / 128, BH), blk, ATTN_SMEM>>>();
    // out = attn @ Wo^T
    gemm_bf16x3<0,0,1,3,3><<<dim3(8, 128), blk, SM_GEMM>>>(nullptr, nullptr, out, 0);
}

// round 9
// speedup vs baseline: 1.3713x; 1.0108x over previous
#include <cuda_runtime.h>
#include <cuda_bf16.h>
#include <math.h>
#include <stdint.h>

#define L_SEQ   4096
#define D_MODEL 1024
#define N_HEADS 16
#define HEAD_DIM 64
#define P_DIM   128
#define B_SIZE  4
#define M_FULL  (B_SIZE * L_SEQ)   // 16384
#define M_KV    (B_SIZE * P_DIM)   // 512
#define BH      (B_SIZE * N_HEADS) // 64

// ---------------- scratch (static device arrays) ---------------------------
__device__ __nv_bfloat16 g_xh[(size_t)M_FULL * D_MODEL];
__device__ __nv_bfloat16 g_xl[(size_t)M_FULL * D_MODEL];
__device__ __nv_bfloat16 g_wh[4 * (size_t)D_MODEL * D_MODEL];
__device__ __nv_bfloat16 g_wl[4 * (size_t)D_MODEL * D_MODEL];
__device__ __nv_bfloat16 g_ah[(size_t)M_FULL * D_MODEL];   // attn out hi
__device__ __nv_bfloat16 g_al[(size_t)M_FULL * D_MODEL];   // attn out lo
__device__ __nv_bfloat16 g_qh[(size_t)M_FULL * D_MODEL];   // roped Q hi
__device__ __nv_bfloat16 g_ql[(size_t)M_FULL * D_MODEL];   // roped Q lo

__device__ float g_K[(size_t)M_KV * D_MODEL];
__device__ float g_V[(size_t)M_KV * D_MODEL];

__device__ __nv_bfloat16 g_kph[BH * P_DIM * HEAD_DIM];     // K_proj [bh][p][d] hi
__device__ __nv_bfloat16 g_kpl[BH * P_DIM * HEAD_DIM];
__device__ __nv_bfloat16 g_vth[BH * HEAD_DIM * P_DIM];     // V_proj^T [bh][d][p] hi
__device__ __nv_bfloat16 g_vtl[BH * HEAD_DIM * P_DIM];

// ---------------------------------------------------------------------------
// fp32 -> bf16 hi/lo splits
// ---------------------------------------------------------------------------
__device__ __forceinline__ void split4(float4 v, uint2& H, uint2& L) {
    union { __nv_bfloat16 b[4]; uint2 u; } h, l;
    float f[4] = {v.x, v.y, v.z, v.w};
#pragma unroll
    for (int j = 0; j < 4; j++) {
        __nv_bfloat16 hv = __float2bfloat16_rn(f[j]);
        h.b[j] = hv;
        l.b[j] = __float2bfloat16_rn(f[j] - __bfloat162float(hv));
    }
    H = h.u; L = l.u;
}

__global__ void __launch_bounds__(256)
convert_x(const float* __restrict__ src, size_t n4)
{
    const float4* s4 = (const float4*)src;
    for (size_t i = blockIdx.x * (size_t)blockDim.x + threadIdx.x; i < n4;
         i += (size_t)gridDim.x * blockDim.x) {
        uint2 H, L;
        split4(s4[i], H, L);
        ((uint2*)g_xh)[i] = H;
        ((uint2*)g_xl)[i] = L;
    }
}

// all 4 weights in one launch: slot = i / 262144
__global__ void __launch_bounds__(256)
convert_w4(const float* __restrict__ w0, const float* __restrict__ w1,
           const float* __restrict__ w2, const float* __restrict__ w3)
{
    const size_t per = (size_t)D_MODEL * D_MODEL / 4;   // float4s per weight
    const float* ws[4] = {w0, w1, w2, w3};
    for (size_t i = blockIdx.x * (size_t)blockDim.x + threadIdx.x; i < 4 * per;
         i += (size_t)gridDim.x * blockDim.x) {
        int slot = (int)(i / per);
        size_t j = i - (size_t)slot * per;
        uint2 H, L;
        split4(((const float4*)ws[slot])[j], H, L);
        ((uint2*)g_wh)[i] = H;
        ((uint2*)g_wl)[i] = L;
    }
}

// ---------------------------------------------------------------------------
// mma.sync helpers
// ---------------------------------------------------------------------------
__device__ __forceinline__ uint32_t sptr(const void* p) {
    return (uint32_t)__cvta_generic_to_shared(p);
}
__device__ __forceinline__ void ldm4(uint32_t* r, uint32_t a) {
    asm volatile("ldmatrix.sync.aligned.m8n8.x4.shared.b16 {%0,%1,%2,%3}, [%4];"
                 : "=r"(r[0]), "=r"(r[1]), "=r"(r[2]), "=r"(r[3]) : "r"(a));
}
__device__ __forceinline__ void mma_bf16(float* c, const uint32_t* a, uint32_t b0, uint32_t b1) {
    asm volatile(
        "mma.sync.aligned.m16n8k16.row.col.f32.bf16.bf16.f32 "
        "{%0,%1,%2,%3}, {%4,%5,%6,%7}, {%8,%9}, {%0,%1,%2,%3};"
        : "+f"(c[0]), "+f"(c[1]), "+f"(c[2]), "+f"(c[3])
        : "r"(a[0]), "r"(a[1]), "r"(a[2]), "r"(a[3]), "r"(b0), "r"(b1));
}
__device__ __forceinline__ void cpa16(uint32_t s, const void* g) {
    asm volatile("cp.async.ca.shared.global [%0], [%1], 16;" :: "r"(s), "l"(g));
}
__device__ __forceinline__ void cpa16cg(uint32_t s, const void* g) {
    asm volatile("cp.async.cg.shared.global [%0], [%1], 16;" :: "r"(s), "l"(g));
}
__device__ __forceinline__ void split2(float x, float y, uint32_t& h, uint32_t& l) {
    union { __nv_bfloat162 v; uint32_t u; } H, L;
    __nv_bfloat16 xh = __float2bfloat16_rn(x);
    __nv_bfloat16 yh = __float2bfloat16_rn(y);
    H.v = __nv_bfloat162(xh, yh);
    L.v = __nv_bfloat162(__float2bfloat16_rn(x - __bfloat162float(xh)),
                         __float2bfloat16_rn(y - __bfloat162float(yh)));
    h = H.u; l = L.u;
}

// ---------------------------------------------------------------------------
// bf16x3 NT GEMM, 128x128 tile, BK=32, 3-stage cp.async pipeline,
// single __syncthreads per chunk.  8 warps 4(m)x2(n), 2 CTAs/SM.
// ---------------------------------------------------------------------------
#define STG_BYTES 32768
#define MAT_BYTES 8192
#define SM_GEMM   (3 * STG_BYTES)   // 98304 B

__device__ __forceinline__ uint32_t swzoff(int row, int c16) {
    return (uint32_t)(row * 64 + ((c16 ^ ((row >> 1) & 3)) << 4));
}

template<int ROPE, int GATHER, int ASEL, int WOFF, int CSEL>
__global__ void __launch_bounds__(256, 2)
gemm_bf16x3(const float* __restrict__ fcos, const float* __restrict__ fsin,
            float* __restrict__ Cext, int posmask)
{
    extern __shared__ char sbuf[];

    const __nv_bfloat16* Ah = (ASEL == 0) ? g_xh : g_ah;
    const __nv_bfloat16* Al = (ASEL == 0) ? g_xl : g_al;
    const __nv_bfloat16* Bh = g_wh + (size_t)WOFF * D_MODEL * D_MODEL;
    const __nv_bfloat16* Bl = g_wl + (size_t)WOFF * D_MODEL * D_MODEL;
    float* C = (CSEL == 1) ? g_K : (CSEL == 2) ? g_V : Cext;
    const __nv_bfloat16* mats[4] = {Ah, Al, Bh, Bl};

    const int tid  = threadIdx.x;
    const int warp = tid >> 5;
    const int lane = tid & 31;
    const int wm   = warp & 3;
    const int wn   = warp >> 2;
    const int m_tile = blockIdx.y * 128;
    const int n_tile = blockIdx.x * 128;
    const int lr = lane & 15;
    const int lh = lane >> 4;

    float acc[2][8][4];
#pragma unroll
    for (int i = 0; i < 2; i++)
#pragma unroll
        for (int j = 0; j < 8; j++)
#pragma unroll
            for (int q = 0; q < 4; q++) acc[i][j][q] = 0.f;

    auto load_chunk = [&](int st, int k0) {
#pragma unroll
        for (int t = 0; t < 8; t++) {
            int idx = tid + t * 256;
            int mtx = idx >> 9;
            int rem = idx & 511;
            int row = rem >> 2;
            int c16 = rem & 3;
            int grow;
            if (mtx < 2) {
                int m = m_tile + row;
                grow = GATHER ? ((m >> 7) * L_SEQ + (m & 127)) : m;
            } else {
                grow = n_tile + row;
            }
            cpa16cg(sptr(sbuf + st * STG_BYTES + mtx * MAT_BYTES + swzoff(row, c16)),
                    mats[mtx] + (size_t)grow * 1024 + k0 + c16 * 8);
        }
    };

    load_chunk(0, 0);
    asm volatile("cp.async.commit_group;" ::: "memory");
    load_chunk(1, 32);
    asm volatile("cp.async.commit_group;" ::: "memory");

    for (int i = 0; i < 32; i++) {
        if (i < 31) asm volatile("cp.async.wait_group 1;" ::: "memory");
        else        asm volatile("cp.async.wait_group 0;" ::: "memory");
        __syncthreads();
        // safe: this sync also proves all threads finished computing stage (i-1),
        // which is the buffer the following load overwrites.
        if (i + 2 < 32) {
            load_chunk((i + 2) % 3, (i + 2) * 32);
            asm volatile("cp.async.commit_group;" ::: "memory");
        }

        const char* stg = sbuf + (i % 3) * STG_BYTES;

#pragma unroll
        for (int ks = 0; ks < 2; ks++) {
            const int cb = ks * 2 + lh;
            uint32_t afh[2][4], afl[2][4];
#pragma unroll
            for (int mf = 0; mf < 2; mf++) {
                int row = wm * 32 + mf * 16 + lr;
                ldm4(afh[mf], sptr(stg + 0 * MAT_BYTES + swzoff(row, cb)));
                ldm4(afl[mf], sptr(stg + 1 * MAT_BYTES + swzoff(row, cb)));
            }
#pragma unroll
            for (int g = 0; g < 4; g++) {
                int row = wn * 64 + g * 16 + lr;
                uint32_t bfh[4], bfl[4];
                ldm4(bfh, sptr(stg + 2 * MAT_BYTES + swzoff(row, cb)));
                ldm4(bfl, sptr(stg + 3 * MAT_BYTES + swzoff(row, cb)));
#pragma unroll
                for (int mf = 0; mf < 2; mf++) {
                    mma_bf16(acc[mf][2*g],   afh[mf], bfh[0], bfh[2]);
                    mma_bf16(acc[mf][2*g],   afh[mf], bfl[0], bfl[2]);
                    mma_bf16(acc[mf][2*g],   afl[mf], bfh[0], bfh[2]);
                    mma_bf16(acc[mf][2*g+1], afh[mf], bfh[1], bfh[3]);
                    mma_bf16(acc[mf][2*g+1], afh[mf], bfl[1], bfl[3]);
                    mma_bf16(acc[mf][2*g+1], afl[mf], bfh[1], bfh[3]);
                }
            }
        }
    }

    // ---- epilogue ----
    const int qrow = lane >> 2;
    const int qcol = (lane & 3) * 2;
#pragma unroll
    for (int mf = 0; mf < 2; mf++)
#pragma unroll
        for (int nf = 0; nf < 8; nf++) {
            int n = n_tile + wn * 64 + nf * 8 + qcol;
#pragma unroll
            for (int hhalf = 0; hhalf < 2; hhalf++) {
                int m = m_tile + wm * 32 + mf * 16 + qrow + hhalf * 8;
                float v0 = acc[mf][nf][hhalf * 2];
                float v1 = acc[mf][nf][hhalf * 2 + 1];
                float o0 = v0, o1 = v1;
                if (ROPE) {
                    int pos = m & posmask;
                    int j   = (n & 63) >> 1;
                    float c = __ldg(fcos + pos * 32 + j);
                    float s = __ldg(fsin + pos * 32 + j);
                    o0 = v0 * c - v1 * s;
                    o1 = v0 * s + v1 * c;
                }
                if (CSEL == 0) {
                    uint32_t h, l;
                    split2(o0, o1, h, l);
                    *(uint32_t*)(g_qh + (size_t)m * 1024 + n) = h;
                    *(uint32_t*)(g_ql + (size_t)m * 1024 + n) = l;
                } else {
                    *(float2*)(C + (size_t)m * 1024 + n) = make_float2(o0, o1);
                }
            }
        }
}

// ---------------------------------------------------------------------------
// K_proj / V_proj (tril): grid (BH, 8).  bf16 hi/lo outputs.
// ---------------------------------------------------------------------------
__global__ void __launch_bounds__(256)
proj_kernel(const float* __restrict__ kpm, const float* __restrict__ vpm)
{
    __shared__ float Ts[128][9];
    const int bh = blockIdx.x;
    const int b  = bh >> 4;
    const int hh = bh & 15;
    const int d0 = blockIdx.y * 8;
    const int tid = threadIdx.x;

    for (int idx = tid; idx < 128 * 8; idx += 256) {
        int l = idx >> 3, d = idx & 7;
        Ts[l][d] = g_K[(size_t)(b * 128 + l) * 1024 + hh * 64 + d0 + d];
    }
    __syncthreads();
#pragma unroll
    for (int t = 0; t < 4; t++) {
        int o = tid + t * 256;
        int p = o >> 3, d = o & 7;
        const float* pr = kpm + (size_t)p * 4096;
        float s = 0.f;
        for (int l = 0; l <= p; l++) s = fmaf(pr[l], Ts[l][d], s);
        __nv_bfloat16 h = __float2bfloat16_rn(s);
        size_t idx = (size_t)bh * 8192 + p * 64 + (d0 + d);
        g_kph[idx] = h;
        g_kpl[idx] = __float2bfloat16_rn(s - __bfloat162float(h));
    }
    __syncthreads();
    for (int idx = tid; idx < 128 * 8; idx += 256) {
        int l = idx >> 3, d = idx & 7;
        Ts[l][d] = g_V[(size_t)(b * 128 + l) * 1024 + hh * 64 + d0 + d];
    }
    __syncthreads();
#pragma unroll
    for (int t = 0; t < 4; t++) {
        int o = tid + t * 256;
        int p = o >> 3, d = o & 7;
        const float* pr = vpm + (size_t)p * 4096;
        float s = 0.f;
        for (int l = 0; l <= p; l++) s = fmaf(pr[l], Ts[l][d], s);
        __nv_bfloat16 h = __float2bfloat16_rn(s);
        size_t idx = (size_t)bh * 8192 + (d0 + d) * 128 + p;
        g_vth[idx] = h;
        g_vtl[idx] = __float2bfloat16_rn(s - __bfloat162float(h));
    }
}

// ---------------------------------------------------------------------------
// Flash-style mma attention (unchanged, passing since R6).
// ---------------------------------------------------------------------------
#define AT_QH 0
#define AT_QL 18432
#define AT_KH 36864
#define AT_KL 55296
#define AT_VH 73728
#define AT_VL 91136
#define ATTN_SMEM 108544

__global__ void __launch_bounds__(256)
attn_kernel()
{
    extern __shared__ char smem[];
    const int bh = blockIdx.y;
    const int b  = bh >> 4;
    const int hh = bh & 15;
    const int l0 = blockIdx.x * 128;
    const int tid  = threadIdx.x;
    const int wp   = tid >> 5;
    const int lane = tid & 31;
    const int lr   = lane & 15;
    const int lh   = lane >> 4;
    const int qrow = lane >> 2;
    const int qcol = (lane & 3) * 2;

    const size_t qbase = (size_t)(b * L_SEQ + l0) * 1024 + hh * 64;
#pragma unroll
    for (int t = 0; t < 4; t++) {
        int i = tid + t * 256;
        int r = i >> 3, c = i & 7;
        cpa16(sptr(smem + AT_QH + r * 144 + c * 16), g_qh + qbase + (size_t)r * 1024 + c * 8);
        cpa16(sptr(smem + AT_QL + r * 144 + c * 16), g_ql + qbase + (size_t)r * 1024 + c * 8);
        cpa16(sptr(smem + AT_KH + r * 144 + c * 16), g_kph + (size_t)bh * 8192 + r * 64 + c * 8);
        cpa16(sptr(smem + AT_KL + r * 144 + c * 16), g_kpl + (size_t)bh * 8192 + r * 64 + c * 8);
        int rv = i >> 4, cv = i & 15;
        cpa16(sptr(smem + AT_VH + rv * 272 + cv * 16), g_vth + (size_t)bh * 8192 + rv * 128 + cv * 8);
        cpa16(sptr(smem + AT_VL + rv * 272 + cv * 16), g_vtl + (size_t)bh * 8192 + rv * 128 + cv * 8);
    }
    asm volatile("cp.async.commit_group;" ::: "memory");
    asm volatile("cp.async.wait_group 0;" ::: "memory");
    __syncthreads();

    float acc[16][4];
#pragma unroll
    for (int i = 0; i < 16; i++)
#pragma unroll
        for (int q = 0; q < 4; q++) acc[i][q] = 0.f;

#pragma unroll
    for (int ks = 0; ks < 4; ks++) {
        uint32_t aqh[4], aql[4];
        ldm4(aqh, sptr(smem + AT_QH + (wp * 16 + lr) * 144 + ks * 32 + lh * 16));
        ldm4(aql, sptr(smem + AT_QL + (wp * 16 + lr) * 144 + ks * 32 + lh * 16));
#pragma unroll
        for (int g = 0; g < 8; g++) {
            uint32_t bkh[4], bkl[4];
            ldm4(bkh, sptr(smem + AT_KH + (g * 16 + lr) * 144 + ks * 32 + lh * 16));
            ldm4(bkl, sptr(smem + AT_KL + (g * 16 + lr) * 144 + ks * 32 + lh * 16));
            mma_bf16(acc[2*g],   aqh, bkh[0], bkh[2]);
            mma_bf16(acc[2*g],   aqh, bkl[0], bkl[2]);
            mma_bf16(acc[2*g],   aql, bkh[0], bkh[2]);
            mma_bf16(acc[2*g+1], aqh, bkh[1], bkh[3]);
            mma_bf16(acc[2*g+1], aqh, bkl[1], bkl[3]);
            mma_bf16(acc[2*g+1], aql, bkh[1], bkh[3]);
        }
    }

#pragma unroll
    for (int i = 0; i < 16; i++)
#pragma unroll
        for (int q = 0; q < 4; q++) acc[i][q] *= 0.125f;

    if (blockIdx.x == 0) {
        const int r0 = wp * 16 + qrow;
        const int r1 = r0 + 8;
#pragma unroll
        for (int nf = 0; nf < 16; nf++) {
            int p0 = nf * 8 + qcol;
            if (p0 > r0)     acc[nf][0] = -1e30f;
            if (p0 + 1 > r0) acc[nf][1] = -1e30f;
            if (p0 > r1)     acc[nf][2] = -1e30f;
            if (p0 + 1 > r1) acc[nf][3] = -1e30f;
        }
    }

    float mx0 = -1e30f, mx1 = -1e30f;
#pragma unroll
    for (int nf = 0; nf < 16; nf++) {
        mx0 = fmaxf(mx0, fmaxf(acc[nf][0], acc[nf][1]));
        mx1 = fmaxf(mx1, fmaxf(acc[nf][2], acc[nf][3]));
    }
    mx0 = fmaxf(mx0, __shfl_xor_sync(0xffffffffu, mx0, 1));
    mx0 = fmaxf(mx0, __shfl_xor_sync(0xffffffffu, mx0, 2));
    mx1 = fmaxf(mx1, __shfl_xor_sync(0xffffffffu, mx1, 1));
    mx1 = fmaxf(mx1, __shfl_xor_sync(0xffffffffu, mx1, 2));

    float s0 = 0.f, s1 = 0.f;
#pragma unroll
    for (int nf = 0; nf < 16; nf++) {
        acc[nf][0] = __expf(acc[nf][0] - mx0);
        acc[nf][1] = __expf(acc[nf][1] - mx0);
        acc[nf][2] = __expf(acc[nf][2] - mx1);
        acc[nf][3] = __expf(acc[nf][3] - mx1);
        s0 += acc[nf][0] + acc[nf][1];
        s1 += acc[nf][2] + acc[nf][3];
    }
    s0 += __shfl_xor_sync(0xffffffffu, s0, 1);
    s0 += __shfl_xor_sync(0xffffffffu, s0, 2);
    s1 += __shfl_xor_sync(0xffffffffu, s1, 1);
    s1 += __shfl_xor_sync(0xffffffffu, s1, 2);
    const float inv0 = 1.0f / s0;
    const float inv1 = 1.0f / s1;

    float o[8][4];
#pragma unroll
    for (int i = 0; i < 8; i++)
#pragma unroll
        for (int q = 0; q < 4; q++) o[i][q] = 0.f;

#pragma unroll
    for (int kc = 0; kc < 8; kc++) {
        uint32_t awh[4], awl[4];
        split2(acc[2*kc][0],   acc[2*kc][1],   awh[0], awl[0]);
        split2(acc[2*kc][2],   acc[2*kc][3],   awh[1], awl[1]);
        split2(acc[2*kc+1][0], acc[2*kc+1][1], awh[2], awl[2]);
        split2(acc[2*kc+1][2], acc[2*kc+1][3], awh[3], awl[3]);
#pragma unroll
        for (int g = 0; g < 4; g++) {
            uint32_t bvh[4], bvl[4];
            ldm4(bvh, sptr(smem + AT_VH + (g * 16 + lr) * 272 + kc * 32 + lh * 16));
            ldm4(bvl, sptr(smem + AT_VL + (g * 16 + lr) * 272 + kc * 32 + lh * 16));
            mma_bf16(o[2*g],   awh, bvh[0], bvh[2]);
            mma_bf16(o[2*g],   awh, bvl[0], bvl[2]);
            mma_bf16(o[2*g],   awl, bvh[0], bvh[2]);
            mma_bf16(o[2*g+1], awh, bvh[1], bvh[3]);
            mma_bf16(o[2*g+1], awh, bvl[1], bvl[3]);
            mma_bf16(o[2*g+1], awl, bvh[1], bvh[3]);
        }
    }

    const size_t row0 = (size_t)(b * L_SEQ + l0 + wp * 16 + qrow);
    const size_t row1 = row0 + 8;
#pragma unroll
    for (int nf = 0; nf < 8; nf++) {
        int col = hh * 64 + nf * 8 + qcol;
        uint32_t h01, l01, h23, l23;
        split2(o[nf][0] * inv0, o[nf][1] * inv0, h01, l01);
        split2(o[nf][2] * inv1, o[nf][3] * inv1, h23, l23);
        *(uint32_t*)(g_ah + row0 * 1024 + col) = h01;
        *(uint32_t*)(g_al + row0 * 1024 + col) = l01;
        *(uint32_t*)(g_ah + row1 * 1024 + col) = h23;
        *(uint32_t*)(g_al + row1 * 1024 + col) = l23;
    }
}

// ---------------------------------------------------------------------------
extern "C" void kernel_launch(void* const* d_in, const int* in_sizes, int n_in,
                              void* d_out, int out_size)
{
    const float* x    = (const float*)d_in[0];
    const float* fcos = (const float*)d_in[1];
    const float* fsin = (const float*)d_in[2];
    const float* Wq   = (const float*)d_in[3];
    const float* Wk   = (const float*)d_in[4];
    const float* Wv   = (const float*)d_in[5];
    const float* Wo   = (const float*)d_in[6];
    const float* kpm  = (const float*)d_in[7];
    const float* vpm  = (const float*)d_in[8];
    float* out = (float*)d_out;

    cudaFuncSetAttribute(attn_kernel,
                         cudaFuncAttributeMaxDynamicSharedMemorySize, ATTN_SMEM);
    cudaFuncSetAttribute(gemm_bf16x3<1,0,0,0,0>, cudaFuncAttributeMaxDynamicSharedMemorySize, SM_GEMM);
    cudaFuncSetAttribute(gemm_bf16x3<1,1,0,1,1>, cudaFuncAttributeMaxDynamicSharedMemorySize, SM_GEMM);
    cudaFuncSetAttribute(gemm_bf16x3<0,1,0,2,2>, cudaFuncAttributeMaxDynamicSharedMemorySize, SM_GEMM);
    cudaFuncSetAttribute(gemm_bf16x3<0,0,1,3,3>, cudaFuncAttributeMaxDynamicSharedMemorySize, SM_GEMM);

    dim3 blk(256);
    // fp32 -> bf16 hi/lo splits (wide grids: these were latency-bound)
    convert_x <<<4096, blk>>>(x, (size_t)M_FULL * D_MODEL / 4);
    convert_w4<<<2048, blk>>>(Wq, Wk, Wv, Wo);

    // Q = rope(x @ Wq^T) -> bf16 hi/lo
    gemm_bf16x3<1,0,0,0,0><<<dim3(8, 128), blk, SM_GEMM>>>(fcos, fsin, nullptr, L_SEQ - 1);
    // K = rope(x[:,:128] @ Wk^T) fp32
    gemm_bf16x3<1,1,0,1,1><<<dim3(8, 4),   blk, SM_GEMM>>>(fcos, fsin, nullptr, P_DIM - 1);
    // V = x[:,:128] @ Wv^T fp32
    gemm_bf16x3<0,1,0,2,2><<<dim3(8, 4),   blk, SM_GEMM>>>(nullptr, nullptr, nullptr, 0);
    // Linformer tril projections -> bf16 hi/lo
    proj_kernel<<<dim3(BH, 8), blk>>>(kpm, vpm);
    // flash-style mma attention
    attn_kernel<<<dim3(L_SEQ / 128, BH), blk, ATTN_SMEM>>>();
    // out = attn @ Wo^T
    gemm_bf16x3<0,0,1,3,3><<<dim3(8, 128), blk, SM_GEMM>>>(nullptr, nullptr, out, 0);
}

// round 11
// speedup vs baseline: 1.4815x; 1.0804x over previous
#include <cuda_runtime.h>
#include <cuda_bf16.h>
#include <math.h>
#include <stdint.h>

#define L_SEQ   4096
#define D_MODEL 1024
#define N_HEADS 16
#define HEAD_DIM 64
#define P_DIM   128
#define B_SIZE  4
#define M_FULL  (B_SIZE * L_SEQ)   // 16384
#define M_KV    (B_SIZE * P_DIM)   // 512
#define BH      (B_SIZE * N_HEADS) // 64

// ---------------- scratch (static device arrays) ---------------------------
__device__ __nv_bfloat16 g_xh[(size_t)M_FULL * D_MODEL];
__device__ __nv_bfloat16 g_xl[(size_t)M_FULL * D_MODEL];
__device__ __nv_bfloat16 g_wh[4 * (size_t)D_MODEL * D_MODEL];
__device__ __nv_bfloat16 g_wl[4 * (size_t)D_MODEL * D_MODEL];
__device__ __nv_bfloat16 g_ah[(size_t)M_FULL * D_MODEL];   // attn out hi
__device__ __nv_bfloat16 g_al[(size_t)M_FULL * D_MODEL];   // attn out lo
__device__ __nv_bfloat16 g_qh[(size_t)M_FULL * D_MODEL];   // roped Q hi
__device__ __nv_bfloat16 g_ql[(size_t)M_FULL * D_MODEL];   // roped Q lo

__device__ float g_K[(size_t)M_KV * D_MODEL];
__device__ float g_V[(size_t)M_KV * D_MODEL];
__device__ float g_kvpart[8 * (size_t)M_KV * D_MODEL];     // [kv*4+ks][m][n]

__device__ __nv_bfloat16 g_kph[BH * P_DIM * HEAD_DIM];     // K_proj [bh][p][d] hi
__device__ __nv_bfloat16 g_kpl[BH * P_DIM * HEAD_DIM];
__device__ __nv_bfloat16 g_vth[BH * HEAD_DIM * P_DIM];     // V_proj^T [bh][d][p] hi
__device__ __nv_bfloat16 g_vtl[BH * HEAD_DIM * P_DIM];

// ---------------------------------------------------------------------------
// fp32 -> bf16 hi/lo splits
// ---------------------------------------------------------------------------
__device__ __forceinline__ void split4(float4 v, uint2& H, uint2& L) {
    union { __nv_bfloat16 b[4]; uint2 u; } h, l;
    float f[4] = {v.x, v.y, v.z, v.w};
#pragma unroll
    for (int j = 0; j < 4; j++) {
        __nv_bfloat16 hv = __float2bfloat16_rn(f[j]);
        h.b[j] = hv;
        l.b[j] = __float2bfloat16_rn(f[j] - __bfloat162float(hv));
    }
    H = h.u; L = l.u;
}

__global__ void __launch_bounds__(256)
convert_x(const float* __restrict__ src, size_t n4)
{
    const float4* s4 = (const float4*)src;
    for (size_t i = blockIdx.x * (size_t)blockDim.x + threadIdx.x; i < n4;
         i += (size_t)gridDim.x * blockDim.x) {
        uint2 H, L;
        split4(s4[i], H, L);
        ((uint2*)g_xh)[i] = H;
        ((uint2*)g_xl)[i] = L;
    }
}

__global__ void __launch_bounds__(256)
convert_w4(const float* __restrict__ w0, const float* __restrict__ w1,
           const float* __restrict__ w2, const float* __restrict__ w3)
{
    const size_t per = (size_t)D_MODEL * D_MODEL / 4;
    const float* ws[4] = {w0, w1, w2, w3};
    for (size_t i = blockIdx.x * (size_t)blockDim.x + threadIdx.x; i < 4 * per;
         i += (size_t)gridDim.x * blockDim.x) {
        int slot = (int)(i / per);
        size_t j = i - (size_t)slot * per;
        uint2 H, L;
        split4(((const float4*)ws[slot])[j], H, L);
        ((uint2*)g_wh)[i] = H;
        ((uint2*)g_wl)[i] = L;
    }
}

// ---------------------------------------------------------------------------
// mma.sync helpers
// ---------------------------------------------------------------------------
__device__ __forceinline__ uint32_t sptr(const void* p) {
    return (uint32_t)__cvta_generic_to_shared(p);
}
__device__ __forceinline__ void ldm4(uint32_t* r, uint32_t a) {
    asm volatile("ldmatrix.sync.aligned.m8n8.x4.shared.b16 {%0,%1,%2,%3}, [%4];"
                 : "=r"(r[0]), "=r"(r[1]), "=r"(r[2]), "=r"(r[3]) : "r"(a));
}
__device__ __forceinline__ void mma_bf16(float* c, const uint32_t* a, uint32_t b0, uint32_t b1) {
    asm volatile(
        "mma.sync.aligned.m16n8k16.row.col.f32.bf16.bf16.f32 "
        "{%0,%1,%2,%3}, {%4,%5,%6,%7}, {%8,%9}, {%0,%1,%2,%3};"
        : "+f"(c[0]), "+f"(c[1]), "+f"(c[2]), "+f"(c[3])
        : "r"(a[0]), "r"(a[1]), "r"(a[2]), "r"(a[3]), "r"(b0), "r"(b1));
}
__device__ __forceinline__ void cpa16(uint32_t s, const void* g) {
    asm volatile("cp.async.ca.shared.global [%0], [%1], 16;" :: "r"(s), "l"(g));
}
__device__ __forceinline__ void cpa16cg(uint32_t s, const void* g) {
    asm volatile("cp.async.cg.shared.global [%0], [%1], 16;" :: "r"(s), "l"(g));
}
__device__ __forceinline__ void split2(float x, float y, uint32_t& h, uint32_t& l) {
    union { __nv_bfloat162 v; uint32_t u; } H, L;
    __nv_bfloat16 xh = __float2bfloat16_rn(x);
    __nv_bfloat16 yh = __float2bfloat16_rn(y);
    H.v = __nv_bfloat162(xh, yh);
    L.v = __nv_bfloat162(__float2bfloat16_rn(x - __bfloat162float(xh)),
                         __float2bfloat16_rn(y - __bfloat162float(yh)));
    h = H.u; l = L.u;
}

// ---------------------------------------------------------------------------
// smem swizzle + shared tile constants
// ---------------------------------------------------------------------------
#define STG_BYTES 32768
#define MAT_BYTES 8192
#define SM_GEMM   (3 * STG_BYTES)   // 98304 B

__device__ __forceinline__ uint32_t swzoff(int row, int c16) {
    return (uint32_t)(row * 64 + ((c16 ^ ((row >> 1) & 3)) << 4));
}

// ---------------------------------------------------------------------------
// bf16x3 NT GEMM, 128x128 tile, BK=32, 3-stage pipeline (R9, passing).
// ---------------------------------------------------------------------------
template<int ROPE, int GATHER, int ASEL, int WOFF, int CSEL>
__global__ void __launch_bounds__(256, 2)
gemm_bf16x3(const float* __restrict__ fcos, const float* __restrict__ fsin,
            float* __restrict__ Cext, int posmask)
{
    extern __shared__ char sbuf[];

    const __nv_bfloat16* Ah = (ASEL == 0) ? g_xh : g_ah;
    const __nv_bfloat16* Al = (ASEL == 0) ? g_xl : g_al;
    const __nv_bfloat16* Bh = g_wh + (size_t)WOFF * D_MODEL * D_MODEL;
    const __nv_bfloat16* Bl = g_wl + (size_t)WOFF * D_MODEL * D_MODEL;
    float* C = Cext;
    const __nv_bfloat16* mats[4] = {Ah, Al, Bh, Bl};

    const int tid  = threadIdx.x;
    const int warp = tid >> 5;
    const int lane = tid & 31;
    const int wm   = warp & 3;
    const int wn   = warp >> 2;
    const int m_tile = blockIdx.y * 128;
    const int n_tile = blockIdx.x * 128;
    const int lr = lane & 15;
    const int lh = lane >> 4;

    float acc[2][8][4];
#pragma unroll
    for (int i = 0; i < 2; i++)
#pragma unroll
        for (int j = 0; j < 8; j++)
#pragma unroll
            for (int q = 0; q < 4; q++) acc[i][j][q] = 0.f;

    auto load_chunk = [&](int st, int k0) {
#pragma unroll
        for (int t = 0; t < 8; t++) {
            int idx = tid + t * 256;
            int mtx = idx >> 9;
            int rem = idx & 511;
            int row = rem >> 2;
            int c16 = rem & 3;
            int grow;
            if (mtx < 2) {
                int m = m_tile + row;
                grow = GATHER ? ((m >> 7) * L_SEQ + (m & 127)) : m;
            } else {
                grow = n_tile + row;
            }
            cpa16cg(sptr(sbuf + st * STG_BYTES + mtx * MAT_BYTES + swzoff(row, c16)),
                    mats[mtx] + (size_t)grow * 1024 + k0 + c16 * 8);
        }
    };

    load_chunk(0, 0);
    asm volatile("cp.async.commit_group;" ::: "memory");
    load_chunk(1, 32);
    asm volatile("cp.async.commit_group;" ::: "memory");

    for (int i = 0; i < 32; i++) {
        if (i < 31) asm volatile("cp.async.wait_group 1;" ::: "memory");
        else        asm volatile("cp.async.wait_group 0;" ::: "memory");
        __syncthreads();
        if (i + 2 < 32) {
            load_chunk((i + 2) % 3, (i + 2) * 32);
            asm volatile("cp.async.commit_group;" ::: "memory");
        }

        const char* stg = sbuf + (i % 3) * STG_BYTES;

#pragma unroll
        for (int ks = 0; ks < 2; ks++) {
            const int cb = ks * 2 + lh;
            uint32_t afh[2][4], afl[2][4];
#pragma unroll
            for (int mf = 0; mf < 2; mf++) {
                int row = wm * 32 + mf * 16 + lr;
                ldm4(afh[mf], sptr(stg + 0 * MAT_BYTES + swzoff(row, cb)));
                ldm4(afl[mf], sptr(stg + 1 * MAT_BYTES + swzoff(row, cb)));
            }
#pragma unroll
            for (int g = 0; g < 4; g++) {
                int row = wn * 64 + g * 16 + lr;
                uint32_t bfh[4], bfl[4];
                ldm4(bfh, sptr(stg + 2 * MAT_BYTES + swzoff(row, cb)));
                ldm4(bfl, sptr(stg + 3 * MAT_BYTES + swzoff(row, cb)));
#pragma unroll
                for (int mf = 0; mf < 2; mf++) {
                    mma_bf16(acc[mf][2*g],   afh[mf], bfh[0], bfh[2]);
                    mma_bf16(acc[mf][2*g],   afh[mf], bfl[0], bfl[2]);
                    mma_bf16(acc[mf][2*g],   afl[mf], bfh[0], bfh[2]);
                    mma_bf16(acc[mf][2*g+1], afh[mf], bfh[1], bfh[3]);
                    mma_bf16(acc[mf][2*g+1], afh[mf], bfl[1], bfl[3]);
                    mma_bf16(acc[mf][2*g+1], afl[mf], bfh[1], bfh[3]);
                }
            }
        }
    }

    const int qrow = lane >> 2;
    const int qcol = (lane & 3) * 2;
#pragma unroll
    for (int mf = 0; mf < 2; mf++)
#pragma unroll
        for (int nf = 0; nf < 8; nf++) {
            int n = n_tile + wn * 64 + nf * 8 + qcol;
#pragma unroll
            for (int hhalf = 0; hhalf < 2; hhalf++) {
                int m = m_tile + wm * 32 + mf * 16 + qrow + hhalf * 8;
                float v0 = acc[mf][nf][hhalf * 2];
                float v1 = acc[mf][nf][hhalf * 2 + 1];
                float o0 = v0, o1 = v1;
                if (ROPE) {
                    int pos = m & posmask;
                    int j   = (n & 63) >> 1;
                    float c = __ldg(fcos + pos * 32 + j);
                    float s = __ldg(fsin + pos * 32 + j);
                    o0 = v0 * c - v1 * s;
                    o1 = v0 * s + v1 * c;
                }
                if (CSEL == 0) {
                    uint32_t h, l;
                    split2(o0, o1, h, l);
                    *(uint32_t*)(g_qh + (size_t)m * 1024 + n) = h;
                    *(uint32_t*)(g_ql + (size_t)m * 1024 + n) = l;
                } else {
                    *(float2*)(C + (size_t)m * 1024 + n) = make_float2(o0, o1);
                }
            }
        }
}

// ---------------------------------------------------------------------------
// Split-K partial GEMM for K and V projections.
// Grid (8, 4, 8): z = kv*4 + ksplit.  Each CTA: 128x128 tile, k in
// [ksplit*256, +256) (8 chunks of 32).  Writes fp32 partials (no rope).
// ---------------------------------------------------------------------------
__global__ void __launch_bounds__(256, 2)
gemm_kv_part()
{
    extern __shared__ char sbuf[];

    const int kv = blockIdx.z >> 2;          // 0=K(Wk), 1=V(Wv)
    const int ks = blockIdx.z & 3;
    const int kbase = ks * 256;

    const __nv_bfloat16* Bh = g_wh + (size_t)(1 + kv) * D_MODEL * D_MODEL;
    const __nv_bfloat16* Bl = g_wl + (size_t)(1 + kv) * D_MODEL * D_MODEL;
    const __nv_bfloat16* mats[4] = {g_xh, g_xl, Bh, Bl};
    float* P = g_kvpart + (size_t)blockIdx.z * M_KV * D_MODEL;

    const int tid  = threadIdx.x;
    const int warp = tid >> 5;
    const int lane = tid & 31;
    const int wm   = warp & 3;
    const int wn   = warp >> 2;
    const int m_tile = blockIdx.y * 128;
    const int n_tile = blockIdx.x * 128;
    const int lr = lane & 15;
    const int lh = lane >> 4;

    float acc[2][8][4];
#pragma unroll
    for (int i = 0; i < 2; i++)
#pragma unroll
        for (int j = 0; j < 8; j++)
#pragma unroll
            for (int q = 0; q < 4; q++) acc[i][j][q] = 0.f;

    auto load_chunk = [&](int st, int k0) {
#pragma unroll
        for (int t = 0; t < 8; t++) {
            int idx = tid + t * 256;
            int mtx = idx >> 9;
            int rem = idx & 511;
            int row = rem >> 2;
            int c16 = rem & 3;
            int grow;
            if (mtx < 2) {
                int m = m_tile + row;
                grow = (m >> 7) * L_SEQ + (m & 127);   // gather first-128 rows/batch
            } else {
                grow = n_tile + row;
            }
            cpa16cg(sptr(sbuf + st * STG_BYTES + mtx * MAT_BYTES + swzoff(row, c16)),
                    mats[mtx] + (size_t)grow * 1024 + k0 + c16 * 8);
        }
    };

    load_chunk(0, kbase);
    asm volatile("cp.async.commit_group;" ::: "memory");
    load_chunk(1, kbase + 32);
    asm volatile("cp.async.commit_group;" ::: "memory");

    for (int i = 0; i < 8; i++) {
        if (i < 7) asm volatile("cp.async.wait_group 1;" ::: "memory");
        else       asm volatile("cp.async.wait_group 0;" ::: "memory");
        __syncthreads();
        if (i + 2 < 8) {
            load_chunk((i + 2) % 3, kbase + (i + 2) * 32);
            asm volatile("cp.async.commit_group;" ::: "memory");
        }

        const char* stg = sbuf + (i % 3) * STG_BYTES;

#pragma unroll
        for (int kk = 0; kk < 2; kk++) {
            const int cb = kk * 2 + lh;
            uint32_t afh[2][4], afl[2][4];
#pragma unroll
            for (int mf = 0; mf < 2; mf++) {
                int row = wm * 32 + mf * 16 + lr;
                ldm4(afh[mf], sptr(stg + 0 * MAT_BYTES + swzoff(row, cb)));
                ldm4(afl[mf], sptr(stg + 1 * MAT_BYTES + swzoff(row, cb)));
            }
#pragma unroll
            for (int g = 0; g < 4; g++) {
                int row = wn * 64 + g * 16 + lr;
                uint32_t bfh[4], bfl[4];
                ldm4(bfh, sptr(stg + 2 * MAT_BYTES + swzoff(row, cb)));
                ldm4(bfl, sptr(stg + 3 * MAT_BYTES + swzoff(row, cb)));
#pragma unroll
                for (int mf = 0; mf < 2; mf++) {
                    mma_bf16(acc[mf][2*g],   afh[mf], bfh[0], bfh[2]);
                    mma_bf16(acc[mf][2*g],   afh[mf], bfl[0], bfl[2]);
                    mma_bf16(acc[mf][2*g],   afl[mf], bfh[0], bfh[2]);
                    mma_bf16(acc[mf][2*g+1], afh[mf], bfh[1], bfh[3]);
                    mma_bf16(acc[mf][2*g+1], afh[mf], bfl[1], bfl[3]);
                    mma_bf16(acc[mf][2*g+1], afl[mf], bfh[1], bfh[3]);
                }
            }
        }
    }

    const int qrow = lane >> 2;
    const int qcol = (lane & 3) * 2;
#pragma unroll
    for (int mf = 0; mf < 2; mf++)
#pragma unroll
        for (int nf = 0; nf < 8; nf++) {
            int n = n_tile + wn * 64 + nf * 8 + qcol;
#pragma unroll
            for (int hhalf = 0; hhalf < 2; hhalf++) {
                int m = m_tile + wm * 32 + mf * 16 + qrow + hhalf * 8;
                *(float2*)(P + (size_t)m * 1024 + n) =
                    make_float2(acc[mf][nf][hhalf * 2], acc[mf][nf][hhalf * 2 + 1]);
            }
        }
}

// ---------------------------------------------------------------------------
// Reduce 4 k-split partials; apply RoPE to K; write g_K / g_V fp32.
// ---------------------------------------------------------------------------
__global__ void __launch_bounds__(256)
reduce_kv(const float* __restrict__ fcos, const float* __restrict__ fsin)
{
    const size_t total = (size_t)2 * M_KV * 256;     // float4 units
    for (size_t i = blockIdx.x * (size_t)blockDim.x + threadIdx.x; i < total;
         i += (size_t)gridDim.x * blockDim.x) {
        int kv  = (int)(i / ((size_t)M_KV * 256));
        size_t rem = i - (size_t)kv * M_KV * 256;
        int m   = (int)(rem >> 8);
        int c4  = (int)(rem & 255);
        int n   = c4 * 4;

        const float4* base = (const float4*)(g_kvpart) + (size_t)kv * 4 * M_KV * 256 + rem;
        float4 s = base[0];
        float4 p1 = base[(size_t)M_KV * 256];
        float4 p2 = base[(size_t)2 * M_KV * 256];
        float4 p3 = base[(size_t)3 * M_KV * 256];
        s.x += p1.x; s.y += p1.y; s.z += p1.z; s.w += p1.w;
        s.x += p2.x; s.y += p2.y; s.z += p2.z; s.w += p2.w;
        s.x += p3.x; s.y += p3.y; s.z += p3.z; s.w += p3.w;

        if (kv == 0) {
            int pos = m & (P_DIM - 1);
            int j   = (n & 63) >> 1;
            float c0 = __ldg(fcos + pos * 32 + j);
            float s0 = __ldg(fsin + pos * 32 + j);
            float c1 = __ldg(fcos + pos * 32 + j + 1);
            float s1 = __ldg(fsin + pos * 32 + j + 1);
            float4 r;
            r.x = s.x * c0 - s.y * s0;
            r.y = s.x * s0 + s.y * c0;
            r.z = s.z * c1 - s.w * s1;
            r.w = s.z * s1 + s.w * c1;
            ((float4*)g_K)[rem] = r;
        } else {
            ((float4*)g_V)[rem] = s;
        }
    }
}

// ---------------------------------------------------------------------------
// K_proj / V_proj (tril): grid (BH, 8).  bf16 hi/lo outputs.
// ---------------------------------------------------------------------------
__global__ void __launch_bounds__(256)
proj_kernel(const float* __restrict__ kpm, const float* __restrict__ vpm)
{
    __shared__ float Ts[128][9];
    const int bh = blockIdx.x;
    const int b  = bh >> 4;
    const int hh = bh & 15;
    const int d0 = blockIdx.y * 8;
    const int tid = threadIdx.x;

    for (int idx = tid; idx < 128 * 8; idx += 256) {
        int l = idx >> 3, d = idx & 7;
        Ts[l][d] = g_K[(size_t)(b * 128 + l) * 1024 + hh * 64 + d0 + d];
    }
    __syncthreads();
#pragma unroll
    for (int t = 0; t < 4; t++) {
        int o = tid + t * 256;
        int p = o >> 3, d = o & 7;
        const float* pr = kpm + (size_t)p * 4096;
        float s = 0.f;
        for (int l = 0; l <= p; l++) s = fmaf(pr[l], Ts[l][d], s);
        __nv_bfloat16 h = __float2bfloat16_rn(s);
        size_t idx = (size_t)bh * 8192 + p * 64 + (d0 + d);
        g_kph[idx] = h;
        g_kpl[idx] = __float2bfloat16_rn(s - __bfloat162float(h));
    }
    __syncthreads();
    for (int idx = tid; idx < 128 * 8; idx += 256) {
        int l = idx >> 3, d = idx & 7;
        Ts[l][d] = g_V[(size_t)(b * 128 + l) * 1024 + hh * 64 + d0 + d];
    }
    __syncthreads();
#pragma unroll
    for (int t = 0; t < 4; t++) {
        int o = tid + t * 256;
        int p = o >> 3, d = o & 7;
        const float* pr = vpm + (size_t)p * 4096;
        float s = 0.f;
        for (int l = 0; l <= p; l++) s = fmaf(pr[l], Ts[l][d], s);
        __nv_bfloat16 h = __float2bfloat16_rn(s);
        size_t idx = (size_t)bh * 8192 + (d0 + d) * 128 + p;
        g_vth[idx] = h;
        g_vtl[idx] = __float2bfloat16_rn(s - __bfloat162float(h));
    }
}

// ---------------------------------------------------------------------------
// Flash-style mma attention (unchanged, passing since R6).
// ---------------------------------------------------------------------------
#define AT_QH 0
#define AT_QL 18432
#define AT_KH 36864
#define AT_KL 55296
#define AT_VH 73728
#define AT_VL 91136
#define ATTN_SMEM 108544

__global__ void __launch_bounds__(256)
attn_kernel()
{
    extern __shared__ char smem[];
    const int bh = blockIdx.y;
    const int b  = bh >> 4;
    const int hh = bh & 15;
    const int l0 = blockIdx.x * 128;
    const int tid  = threadIdx.x;
    const int wp   = tid >> 5;
    const int lane = tid & 31;
    const int lr   = lane & 15;
    const int lh   = lane >> 4;
    const int qrow = lane >> 2;
    const int qcol = (lane & 3) * 2;

    const size_t qbase = (size_t)(b * L_SEQ + l0) * 1024 + hh * 64;
#pragma unroll
    for (int t = 0; t < 4; t++) {
        int i = tid + t * 256;
        int r = i >> 3, c = i & 7;
        cpa16(sptr(smem + AT_QH + r * 144 + c * 16), g_qh + qbase + (size_t)r * 1024 + c * 8);
        cpa16(sptr(smem + AT_QL + r * 144 + c * 16), g_ql + qbase + (size_t)r * 1024 + c * 8);
        cpa16(sptr(smem + AT_KH + r * 144 + c * 16), g_kph + (size_t)bh * 8192 + r * 64 + c * 8);
        cpa16(sptr(smem + AT_KL + r * 144 + c * 16), g_kpl + (size_t)bh * 8192 + r * 64 + c * 8);
        int rv = i >> 4, cv = i & 15;
        cpa16(sptr(smem + AT_VH + rv * 272 + cv * 16), g_vth + (size_t)bh * 8192 + rv * 128 + cv * 8);
        cpa16(sptr(smem + AT_VL + rv * 272 + cv * 16), g_vtl + (size_t)bh * 8192 + rv * 128 + cv * 8);
    }
    asm volatile("cp.async.commit_group;" ::: "memory");
    asm volatile("cp.async.wait_group 0;" ::: "memory");
    __syncthreads();

    float acc[16][4];
#pragma unroll
    for (int i = 0; i < 16; i++)
#pragma unroll
        for (int q = 0; q < 4; q++) acc[i][q] = 0.f;

#pragma unroll
    for (int ks = 0; ks < 4; ks++) {
        uint32_t aqh[4], aql[4];
        ldm4(aqh, sptr(smem + AT_QH + (wp * 16 + lr) * 144 + ks * 32 + lh * 16));
        ldm4(aql, sptr(smem + AT_QL + (wp * 16 + lr) * 144 + ks * 32 + lh * 16));
#pragma unroll
        for (int g = 0; g < 8; g++) {
            uint32_t bkh[4], bkl[4];
            ldm4(bkh, sptr(smem + AT_KH + (g * 16 + lr) * 144 + ks * 32 + lh * 16));
            ldm4(bkl, sptr(smem + AT_KL + (g * 16 + lr) * 144 + ks * 32 + lh * 16));
            mma_bf16(acc[2*g],   aqh, bkh[0], bkh[2]);
            mma_bf16(acc[2*g],   aqh, bkl[0], bkl[2]);
            mma_bf16(acc[2*g],   aql, bkh[0], bkh[2]);
            mma_bf16(acc[2*g+1], aqh, bkh[1], bkh[3]);
            mma_bf16(acc[2*g+1], aqh, bkl[1], bkl[3]);
            mma_bf16(acc[2*g+1], aql, bkh[1], bkh[3]);
        }
    }

#pragma unroll
    for (int i = 0; i < 16; i++)
#pragma unroll
        for (int q = 0; q < 4; q++) acc[i][q] *= 0.125f;

    if (blockIdx.x == 0) {
        const int r0 = wp * 16 + qrow;
        const int r1 = r0 + 8;
#pragma unroll
        for (int nf = 0; nf < 16; nf++) {
            int p0 = nf * 8 + qcol;
            if (p0 > r0)     acc[nf][0] = -1e30f;
            if (p0 + 1 > r0) acc[nf][1] = -1e30f;
            if (p0 > r1)     acc[nf][2] = -1e30f;
            if (p0 + 1 > r1) acc[nf][3] = -1e30f;
        }
    }

    float mx0 = -1e30f, mx1 = -1e30f;
#pragma unroll
    for (int nf = 0; nf < 16; nf++) {
        mx0 = fmaxf(mx0, fmaxf(acc[nf][0], acc[nf][1]));
        mx1 = fmaxf(mx1, fmaxf(acc[nf][2], acc[nf][3]));
    }
    mx0 = fmaxf(mx0, __shfl_xor_sync(0xffffffffu, mx0, 1));
    mx0 = fmaxf(mx0, __shfl_xor_sync(0xffffffffu, mx0, 2));
    mx1 = fmaxf(mx1, __shfl_xor_sync(0xffffffffu, mx1, 1));
    mx1 = fmaxf(mx1, __shfl_xor_sync(0xffffffffu, mx1, 2));

    float s0 = 0.f, s1 = 0.f;
#pragma unroll
    for (int nf = 0; nf < 16; nf++) {
        acc[nf][0] = __expf(acc[nf][0] - mx0);
        acc[nf][1] = __expf(acc[nf][1] - mx0);
        acc[nf][2] = __expf(acc[nf][2] - mx1);
        acc[nf][3] = __expf(acc[nf][3] - mx1);
        s0 += acc[nf][0] + acc[nf][1];
        s1 += acc[nf][2] + acc[nf][3];
    }
    s0 += __shfl_xor_sync(0xffffffffu, s0, 1);
    s0 += __shfl_xor_sync(0xffffffffu, s0, 2);
    s1 += __shfl_xor_sync(0xffffffffu, s1, 1);
    s1 += __shfl_xor_sync(0xffffffffu, s1, 2);
    const float inv0 = 1.0f / s0;
    const float inv1 = 1.0f / s1;

    float o[8][4];
#pragma unroll
    for (int i = 0; i < 8; i++)
#pragma unroll
        for (int q = 0; q < 4; q++) o[i][q] = 0.f;

#pragma unroll
    for (int kc = 0; kc < 8; kc++) {
        uint32_t awh[4], awl[4];
        split2(acc[2*kc][0],   acc[2*kc][1],   awh[0], awl[0]);
        split2(acc[2*kc][2],   acc[2*kc][3],   awh[1], awl[1]);
        split2(acc[2*kc+1][0], acc[2*kc+1][1], awh[2], awl[2]);
        split2(acc[2*kc+1][2], acc[2*kc+1][3], awh[3], awl[3]);
#pragma unroll
        for (int g = 0; g < 4; g++) {
            uint32_t bvh[4], bvl[4];
            ldm4(bvh, sptr(smem + AT_VH + (g * 16 + lr) * 272 + kc * 32 + lh * 16));
            ldm4(bvl, sptr(smem + AT_VL + (g * 16 + lr) * 272 + kc * 32 + lh * 16));
            mma_bf16(o[2*g],   awh, bvh[0], bvh[2]);
            mma_bf16(o[2*g],   awh, bvl[0], bvl[2]);
            mma_bf16(o[2*g],   awl, bvh[0], bvh[2]);
            mma_bf16(o[2*g+1], awh, bvh[1], bvh[3]);
            mma_bf16(o[2*g+1], awh, bvl[1], bvl[3]);
            mma_bf16(o[2*g+1], awl, bvh[1], bvh[3]);
        }
    }

    const size_t row0 = (size_t)(b * L_SEQ + l0 + wp * 16 + qrow);
    const size_t row1 = row0 + 8;
#pragma unroll
    for (int nf = 0; nf < 8; nf++) {
        int col = hh * 64 + nf * 8 + qcol;
        uint32_t h01, l01, h23, l23;
        split2(o[nf][0] * inv0, o[nf][1] * inv0, h01, l01);
        split2(o[nf][2] * inv1, o[nf][3] * inv1, h23, l23);
        *(uint32_t*)(g_ah + row0 * 1024 + col) = h01;
        *(uint32_t*)(g_al + row0 * 1024 + col) = l01;
        *(uint32_t*)(g_ah + row1 * 1024 + col) = h23;
        *(uint32_t*)(g_al + row1 * 1024 + col) = l23;
    }
}

// ---------------------------------------------------------------------------
extern "C" void kernel_launch(void* const* d_in, const int* in_sizes, int n_in,
                              void* d_out, int out_size)
{
    const float* x    = (const float*)d_in[0];
    const float* fcos = (const float*)d_in[1];
    const float* fsin = (const float*)d_in[2];
    const float* Wq   = (const float*)d_in[3];
    const float* Wk   = (const float*)d_in[4];
    const float* Wv   = (const float*)d_in[5];
    const float* Wo   = (const float*)d_in[6];
    const float* kpm  = (const float*)d_in[7];
    const float* vpm  = (const float*)d_in[8];
    float* out = (float*)d_out;

    cudaFuncSetAttribute(attn_kernel,
                         cudaFuncAttributeMaxDynamicSharedMemorySize, ATTN_SMEM);
    cudaFuncSetAttribute(gemm_bf16x3<1,0,0,0,0>, cudaFuncAttributeMaxDynamicSharedMemorySize, SM_GEMM);
    cudaFuncSetAttribute(gemm_kv_part,           cudaFuncAttributeMaxDynamicSharedMemorySize, SM_GEMM);
    cudaFuncSetAttribute(gemm_bf16x3<0,0,1,3,3>, cudaFuncAttributeMaxDynamicSharedMemorySize, SM_GEMM);

    dim3 blk(256);
    // fp32 -> bf16 hi/lo splits
    convert_x <<<4096, blk>>>(x, (size_t)M_FULL * D_MODEL / 4);
    convert_w4<<<2048, blk>>>(Wq, Wk, Wv, Wo);

    // K/V split-K partial GEMMs (256 CTAs, ~1 wave) + reduce w/ RoPE(K)
    gemm_kv_part<<<dim3(8, 4, 8), blk, SM_GEMM>>>();
    reduce_kv<<<512, blk>>>(fcos, fsin);

    // Q = rope(x @ Wq^T) -> bf16 hi/lo
    gemm_bf16x3<1,0,0,0,0><<<dim3(8, 128), blk, SM_GEMM>>>(fcos, fsin, nullptr, L_SEQ - 1);

    // Linformer tril projections -> bf16 hi/lo
    proj_kernel<<<dim3(BH, 8), blk>>>(kpm, vpm);
    // flash-style mma attention
    attn_kernel<<<dim3(L_SEQ / 128, BH), blk, ATTN_SMEM>>>();
    // out = attn @ Wo^T
    gemm_bf16x3<0,0,1,3,3><<<dim3(8, 128), blk, SM_GEMM>>>(nullptr, nullptr, out, 0);
}

// round 12
// speedup vs baseline: 1.4887x; 1.0049x over previous
#include <cuda_runtime.h>
#include <cuda_bf16.h>
#include <math.h>
#include <stdint.h>

#define L_SEQ   4096
#define D_MODEL 1024
#define N_HEADS 16
#define HEAD_DIM 64
#define P_DIM   128
#define B_SIZE  4
#define M_FULL  (B_SIZE * L_SEQ)   // 16384
#define M_KV    (B_SIZE * P_DIM)   // 512
#define BH      (B_SIZE * N_HEADS) // 64

// ---------------- scratch (static device arrays) ---------------------------
__device__ __nv_bfloat16 g_xh[(size_t)M_FULL * D_MODEL];
__device__ __nv_bfloat16 g_xl[(size_t)M_FULL * D_MODEL];
__device__ __nv_bfloat16 g_wh[4 * (size_t)D_MODEL * D_MODEL];
__device__ __nv_bfloat16 g_wl[4 * (size_t)D_MODEL * D_MODEL];
__device__ __nv_bfloat16 g_ah[(size_t)M_FULL * D_MODEL];   // attn out hi
__device__ __nv_bfloat16 g_al[(size_t)M_FULL * D_MODEL];   // attn out lo
__device__ __nv_bfloat16 g_qh[(size_t)M_FULL * D_MODEL];   // roped Q hi
__device__ __nv_bfloat16 g_ql[(size_t)M_FULL * D_MODEL];   // roped Q lo

__device__ float g_K[(size_t)M_KV * D_MODEL];
__device__ float g_V[(size_t)M_KV * D_MODEL];
__device__ float g_kvpart[8 * (size_t)M_KV * D_MODEL];     // [kv*4+ks][m][n]

__device__ __nv_bfloat16 g_kph[BH * P_DIM * HEAD_DIM];     // K_proj [bh][p][d] hi
__device__ __nv_bfloat16 g_kpl[BH * P_DIM * HEAD_DIM];
__device__ __nv_bfloat16 g_vth[BH * HEAD_DIM * P_DIM];     // V_proj^T [bh][d][p] hi
__device__ __nv_bfloat16 g_vtl[BH * HEAD_DIM * P_DIM];

// ---------------------------------------------------------------------------
// fp32 -> bf16 hi/lo splits
// ---------------------------------------------------------------------------
__device__ __forceinline__ void split4(float4 v, uint2& H, uint2& L) {
    union { __nv_bfloat16 b[4]; uint2 u; } h, l;
    float f[4] = {v.x, v.y, v.z, v.w};
#pragma unroll
    for (int j = 0; j < 4; j++) {
        __nv_bfloat16 hv = __float2bfloat16_rn(f[j]);
        h.b[j] = hv;
        l.b[j] = __float2bfloat16_rn(f[j] - __bfloat162float(hv));
    }
    H = h.u; L = l.u;
}

__global__ void __launch_bounds__(256)
convert_x(const float* __restrict__ src, size_t n4)
{
    const float4* s4 = (const float4*)src;
    for (size_t i = blockIdx.x * (size_t)blockDim.x + threadIdx.x; i < n4;
         i += (size_t)gridDim.x * blockDim.x) {
        uint2 H, L;
        split4(s4[i], H, L);
        ((uint2*)g_xh)[i] = H;
        ((uint2*)g_xl)[i] = L;
    }
}

__global__ void __launch_bounds__(256)
convert_w4(const float* __restrict__ w0, const float* __restrict__ w1,
           const float* __restrict__ w2, const float* __restrict__ w3)
{
    const size_t per = (size_t)D_MODEL * D_MODEL / 4;
    const float* ws[4] = {w0, w1, w2, w3};
    for (size_t i = blockIdx.x * (size_t)blockDim.x + threadIdx.x; i < 4 * per;
         i += (size_t)gridDim.x * blockDim.x) {
        int slot = (int)(i / per);
        size_t j = i - (size_t)slot * per;
        uint2 H, L;
        split4(((const float4*)ws[slot])[j], H, L);
        ((uint2*)g_wh)[i] = H;
        ((uint2*)g_wl)[i] = L;
    }
}

// ---------------------------------------------------------------------------
// mma.sync helpers
// ---------------------------------------------------------------------------
__device__ __forceinline__ uint32_t sptr(const void* p) {
    return (uint32_t)__cvta_generic_to_shared(p);
}
__device__ __forceinline__ void ldm4(uint32_t* r, uint32_t a) {
    asm volatile("ldmatrix.sync.aligned.m8n8.x4.shared.b16 {%0,%1,%2,%3}, [%4];"
                 : "=r"(r[0]), "=r"(r[1]), "=r"(r[2]), "=r"(r[3]) : "r"(a));
}
__device__ __forceinline__ void mma_bf16(float* c, const uint32_t* a, uint32_t b0, uint32_t b1) {
    asm volatile(
        "mma.sync.aligned.m16n8k16.row.col.f32.bf16.bf16.f32 "
        "{%0,%1,%2,%3}, {%4,%5,%6,%7}, {%8,%9}, {%0,%1,%2,%3};"
        : "+f"(c[0]), "+f"(c[1]), "+f"(c[2]), "+f"(c[3])
        : "r"(a[0]), "r"(a[1]), "r"(a[2]), "r"(a[3]), "r"(b0), "r"(b1));
}
__device__ __forceinline__ void cpa16(uint32_t s, const void* g) {
    asm volatile("cp.async.ca.shared.global [%0], [%1], 16;" :: "r"(s), "l"(g));
}
__device__ __forceinline__ void cpa16cg(uint32_t s, const void* g) {
    asm volatile("cp.async.cg.shared.global [%0], [%1], 16;" :: "r"(s), "l"(g));
}
__device__ __forceinline__ void split2(float x, float y, uint32_t& h, uint32_t& l) {
    union { __nv_bfloat162 v; uint32_t u; } H, L;
    __nv_bfloat16 xh = __float2bfloat16_rn(x);
    __nv_bfloat16 yh = __float2bfloat16_rn(y);
    H.v = __nv_bfloat162(xh, yh);
    L.v = __nv_bfloat162(__float2bfloat16_rn(x - __bfloat162float(xh)),
                         __float2bfloat16_rn(y - __bfloat162float(yh)));
    h = H.u; l = L.u;
}

// ---------------------------------------------------------------------------
// smem swizzle + shared tile constants
// ---------------------------------------------------------------------------
#define STG_BYTES 32768
#define MAT_BYTES 8192
#define SM_GEMM   (3 * STG_BYTES)   // 98304 B

__device__ __forceinline__ uint32_t swzoff(int row, int c16) {
    return (uint32_t)(row * 64 + ((c16 ^ ((row >> 1) & 3)) << 4));
}

// One product pass over the whole 128x128 warp-tile: 16 independent mma
// before any accumulator is reused (kills the per-acc RAW chain).
// Per-acc accumulation ORDER across the 3 passes is unchanged (hh, hl, lh)
// so results are bit-identical to the previous schedule.
__device__ __forceinline__ void mma_pass(
    float acc[2][8][4], uint32_t A[2][4], uint32_t B[4][4])
{
#pragma unroll
    for (int g = 0; g < 4; g++)
#pragma unroll
        for (int mf = 0; mf < 2; mf++) {
            mma_bf16(acc[mf][2*g],   A[mf], B[g][0], B[g][2]);
            mma_bf16(acc[mf][2*g+1], A[mf], B[g][1], B[g][3]);
        }
}

// ---------------------------------------------------------------------------
// bf16x3 NT GEMM, 128x128 tile, BK=32, 3-stage pipeline, pass-reordered mma.
// ---------------------------------------------------------------------------
template<int ROPE, int GATHER, int ASEL, int WOFF, int CSEL>
__global__ void __launch_bounds__(256, 2)
gemm_bf16x3(const float* __restrict__ fcos, const float* __restrict__ fsin,
            float* __restrict__ Cext, int posmask)
{
    extern __shared__ char sbuf[];

    const __nv_bfloat16* Ah = (ASEL == 0) ? g_xh : g_ah;
    const __nv_bfloat16* Al = (ASEL == 0) ? g_xl : g_al;
    const __nv_bfloat16* Bh = g_wh + (size_t)WOFF * D_MODEL * D_MODEL;
    const __nv_bfloat16* Bl = g_wl + (size_t)WOFF * D_MODEL * D_MODEL;
    float* C = Cext;
    const __nv_bfloat16* mats[4] = {Ah, Al, Bh, Bl};

    const int tid  = threadIdx.x;
    const int warp = tid >> 5;
    const int lane = tid & 31;
    const int wm   = warp & 3;
    const int wn   = warp >> 2;
    const int m_tile = blockIdx.y * 128;
    const int n_tile = blockIdx.x * 128;
    const int lr = lane & 15;
    const int lh = lane >> 4;

    float acc[2][8][4];
#pragma unroll
    for (int i = 0; i < 2; i++)
#pragma unroll
        for (int j = 0; j < 8; j++)
#pragma unroll
            for (int q = 0; q < 4; q++) acc[i][j][q] = 0.f;

    auto load_chunk = [&](int st, int k0) {
#pragma unroll
        for (int t = 0; t < 8; t++) {
            int idx = tid + t * 256;
            int mtx = idx >> 9;
            int rem = idx & 511;
            int row = rem >> 2;
            int c16 = rem & 3;
            int grow;
            if (mtx < 2) {
                int m = m_tile + row;
                grow = GATHER ? ((m >> 7) * L_SEQ + (m & 127)) : m;
            } else {
                grow = n_tile + row;
            }
            cpa16cg(sptr(sbuf + st * STG_BYTES + mtx * MAT_BYTES + swzoff(row, c16)),
                    mats[mtx] + (size_t)grow * 1024 + k0 + c16 * 8);
        }
    };

    load_chunk(0, 0);
    asm volatile("cp.async.commit_group;" ::: "memory");
    load_chunk(1, 32);
    asm volatile("cp.async.commit_group;" ::: "memory");

    for (int i = 0; i < 32; i++) {
        if (i < 31) asm volatile("cp.async.wait_group 1;" ::: "memory");
        else        asm volatile("cp.async.wait_group 0;" ::: "memory");
        __syncthreads();
        if (i + 2 < 32) {
            load_chunk((i + 2) % 3, (i + 2) * 32);
            asm volatile("cp.async.commit_group;" ::: "memory");
        }

        const char* stg = sbuf + (i % 3) * STG_BYTES;

#pragma unroll
        for (int ks = 0; ks < 2; ks++) {
            const int cb = ks * 2 + lh;
            uint32_t afh[2][4], afl[2][4];
#pragma unroll
            for (int mf = 0; mf < 2; mf++) {
                int row = wm * 32 + mf * 16 + lr;
                ldm4(afh[mf], sptr(stg + 0 * MAT_BYTES + swzoff(row, cb)));
                ldm4(afl[mf], sptr(stg + 1 * MAT_BYTES + swzoff(row, cb)));
            }
            uint32_t bfh[4][4], bfl[4][4];
#pragma unroll
            for (int g = 0; g < 4; g++) {
                int row = wn * 64 + g * 16 + lr;
                ldm4(bfh[g], sptr(stg + 2 * MAT_BYTES + swzoff(row, cb)));
                ldm4(bfl[g], sptr(stg + 3 * MAT_BYTES + swzoff(row, cb)));
            }
            mma_pass(acc, afh, bfh);   // hh
            mma_pass(acc, afh, bfl);   // hl
            mma_pass(acc, afl, bfh);   // lh
        }
    }

    const int qrow = lane >> 2;
    const int qcol = (lane & 3) * 2;
#pragma unroll
    for (int mf = 0; mf < 2; mf++)
#pragma unroll
        for (int nf = 0; nf < 8; nf++) {
            int n = n_tile + wn * 64 + nf * 8 + qcol;
#pragma unroll
            for (int hhalf = 0; hhalf < 2; hhalf++) {
                int m = m_tile + wm * 32 + mf * 16 + qrow + hhalf * 8;
                float v0 = acc[mf][nf][hhalf * 2];
                float v1 = acc[mf][nf][hhalf * 2 + 1];
                float o0 = v0, o1 = v1;
                if (ROPE) {
                    int pos = m & posmask;
                    int j   = (n & 63) >> 1;
                    float c = __ldg(fcos + pos * 32 + j);
                    float s = __ldg(fsin + pos * 32 + j);
                    o0 = v0 * c - v1 * s;
                    o1 = v0 * s + v1 * c;
                }
                if (CSEL == 0) {
                    uint32_t h, l;
                    split2(o0, o1, h, l);
                    *(uint32_t*)(g_qh + (size_t)m * 1024 + n) = h;
                    *(uint32_t*)(g_ql + (size_t)m * 1024 + n) = l;
                } else {
                    *(float2*)(C + (size_t)m * 1024 + n) = make_float2(o0, o1);
                }
            }
        }
}

// ---------------------------------------------------------------------------
// Split-K partial GEMM for K and V (pass-reordered mma).
// ---------------------------------------------------------------------------
__global__ void __launch_bounds__(256, 2)
gemm_kv_part()
{
    extern __shared__ char sbuf[];

    const int kv = blockIdx.z >> 2;
    const int ks = blockIdx.z & 3;
    const int kbase = ks * 256;

    const __nv_bfloat16* Bh = g_wh + (size_t)(1 + kv) * D_MODEL * D_MODEL;
    const __nv_bfloat16* Bl = g_wl + (size_t)(1 + kv) * D_MODEL * D_MODEL;
    const __nv_bfloat16* mats[4] = {g_xh, g_xl, Bh, Bl};
    float* P = g_kvpart + (size_t)blockIdx.z * M_KV * D_MODEL;

    const int tid  = threadIdx.x;
    const int warp = tid >> 5;
    const int lane = tid & 31;
    const int wm   = warp & 3;
    const int wn   = warp >> 2;
    const int m_tile = blockIdx.y * 128;
    const int n_tile = blockIdx.x * 128;
    const int lr = lane & 15;
    const int lh = lane >> 4;

    float acc[2][8][4];
#pragma unroll
    for (int i = 0; i < 2; i++)
#pragma unroll
        for (int j = 0; j < 8; j++)
#pragma unroll
            for (int q = 0; q < 4; q++) acc[i][j][q] = 0.f;

    auto load_chunk = [&](int st, int k0) {
#pragma unroll
        for (int t = 0; t < 8; t++) {
            int idx = tid + t * 256;
            int mtx = idx >> 9;
            int rem = idx & 511;
            int row = rem >> 2;
            int c16 = rem & 3;
            int grow;
            if (mtx < 2) {
                int m = m_tile + row;
                grow = (m >> 7) * L_SEQ + (m & 127);
            } else {
                grow = n_tile + row;
            }
            cpa16cg(sptr(sbuf + st * STG_BYTES + mtx * MAT_BYTES + swzoff(row, c16)),
                    mats[mtx] + (size_t)grow * 1024 + k0 + c16 * 8);
        }
    };

    load_chunk(0, kbase);
    asm volatile("cp.async.commit_group;" ::: "memory");
    load_chunk(1, kbase + 32);
    asm volatile("cp.async.commit_group;" ::: "memory");

    for (int i = 0; i < 8; i++) {
        if (i < 7) asm volatile("cp.async.wait_group 1;" ::: "memory");
        else       asm volatile("cp.async.wait_group 0;" ::: "memory");
        __syncthreads();
        if (i + 2 < 8) {
            load_chunk((i + 2) % 3, kbase + (i + 2) * 32);
            asm volatile("cp.async.commit_group;" ::: "memory");
        }

        const char* stg = sbuf + (i % 3) * STG_BYTES;

#pragma unroll
        for (int kk = 0; kk < 2; kk++) {
            const int cb = kk * 2 + lh;
            uint32_t afh[2][4], afl[2][4];
#pragma unroll
            for (int mf = 0; mf < 2; mf++) {
                int row = wm * 32 + mf * 16 + lr;
                ldm4(afh[mf], sptr(stg + 0 * MAT_BYTES + swzoff(row, cb)));
                ldm4(afl[mf], sptr(stg + 1 * MAT_BYTES + swzoff(row, cb)));
            }
            uint32_t bfh[4][4], bfl[4][4];
#pragma unroll
            for (int g = 0; g < 4; g++) {
                int row = wn * 64 + g * 16 + lr;
                ldm4(bfh[g], sptr(stg + 2 * MAT_BYTES + swzoff(row, cb)));
                ldm4(bfl[g], sptr(stg + 3 * MAT_BYTES + swzoff(row, cb)));
            }
            mma_pass(acc, afh, bfh);
            mma_pass(acc, afh, bfl);
            mma_pass(acc, afl, bfh);
        }
    }

    const int qrow = lane >> 2;
    const int qcol = (lane & 3) * 2;
#pragma unroll
    for (int mf = 0; mf < 2; mf++)
#pragma unroll
        for (int nf = 0; nf < 8; nf++) {
            int n = n_tile + wn * 64 + nf * 8 + qcol;
#pragma unroll
            for (int hhalf = 0; hhalf < 2; hhalf++) {
                int m = m_tile + wm * 32 + mf * 16 + qrow + hhalf * 8;
                *(float2*)(P + (size_t)m * 1024 + n) =
                    make_float2(acc[mf][nf][hhalf * 2], acc[mf][nf][hhalf * 2 + 1]);
            }
        }
}

// ---------------------------------------------------------------------------
// Reduce 4 k-split partials; apply RoPE to K; write g_K / g_V fp32.
// ---------------------------------------------------------------------------
__global__ void __launch_bounds__(256)
reduce_kv(const float* __restrict__ fcos, const float* __restrict__ fsin)
{
    const size_t total = (size_t)2 * M_KV * 256;
    for (size_t i = blockIdx.x * (size_t)blockDim.x + threadIdx.x; i < total;
         i += (size_t)gridDim.x * blockDim.x) {
        int kv  = (int)(i / ((size_t)M_KV * 256));
        size_t rem = i - (size_t)kv * M_KV * 256;
        int m   = (int)(rem >> 8);
        int c4  = (int)(rem & 255);
        int n   = c4 * 4;

        const float4* base = (const float4*)(g_kvpart) + (size_t)kv * 4 * M_KV * 256 + rem;
        float4 s = base[0];
        float4 p1 = base[(size_t)M_KV * 256];
        float4 p2 = base[(size_t)2 * M_KV * 256];
        float4 p3 = base[(size_t)3 * M_KV * 256];
        s.x += p1.x; s.y += p1.y; s.z += p1.z; s.w += p1.w;
        s.x += p2.x; s.y += p2.y; s.z += p2.z; s.w += p2.w;
        s.x += p3.x; s.y += p3.y; s.z += p3.z; s.w += p3.w;

        if (kv == 0) {
            int pos = m & (P_DIM - 1);
            int j   = (n & 63) >> 1;
            float c0 = __ldg(fcos + pos * 32 + j);
            float s0 = __ldg(fsin + pos * 32 + j);
            float c1 = __ldg(fcos + pos * 32 + j + 1);
            float s1 = __ldg(fsin + pos * 32 + j + 1);
            float4 r;
            r.x = s.x * c0 - s.y * s0;
            r.y = s.x * s0 + s.y * c0;
            r.z = s.z * c1 - s.w * s1;
            r.w = s.z * s1 + s.w * c1;
            ((float4*)g_K)[rem] = r;
        } else {
            ((float4*)g_V)[rem] = s;
        }
    }
}

// ---------------------------------------------------------------------------
// K_proj / V_proj (tril): grid (BH, 8).  bf16 hi/lo outputs.
// ---------------------------------------------------------------------------
__global__ void __launch_bounds__(256)
proj_kernel(const float* __restrict__ kpm, const float* __restrict__ vpm)
{
    __shared__ float Ts[128][9];
    const int bh = blockIdx.x;
    const int b  = bh >> 4;
    const int hh = bh & 15;
    const int d0 = blockIdx.y * 8;
    const int tid = threadIdx.x;

    for (int idx = tid; idx < 128 * 8; idx += 256) {
        int l = idx >> 3, d = idx & 7;
        Ts[l][d] = g_K[(size_t)(b * 128 + l) * 1024 + hh * 64 + d0 + d];
    }
    __syncthreads();
#pragma unroll
    for (int t = 0; t < 4; t++) {
        int o = tid + t * 256;
        int p = o >> 3, d = o & 7;
        const float* pr = kpm + (size_t)p * 4096;
        float s = 0.f;
        for (int l = 0; l <= p; l++) s = fmaf(pr[l], Ts[l][d], s);
        __nv_bfloat16 h = __float2bfloat16_rn(s);
        size_t idx = (size_t)bh * 8192 + p * 64 + (d0 + d);
        g_kph[idx] = h;
        g_kpl[idx] = __float2bfloat16_rn(s - __bfloat162float(h));
    }
    __syncthreads();
    for (int idx = tid; idx < 128 * 8; idx += 256) {
        int l = idx >> 3, d = idx & 7;
        Ts[l][d] = g_V[(size_t)(b * 128 + l) * 1024 + hh * 64 + d0 + d];
    }
    __syncthreads();
#pragma unroll
    for (int t = 0; t < 4; t++) {
        int o = tid + t * 256;
        int p = o >> 3, d = o & 7;
        const float* pr = vpm + (size_t)p * 4096;
        float s = 0.f;
        for (int l = 0; l <= p; l++) s = fmaf(pr[l], Ts[l][d], s);
        __nv_bfloat16 h = __float2bfloat16_rn(s);
        size_t idx = (size_t)bh * 8192 + (d0 + d) * 128 + p;
        g_vth[idx] = h;
        g_vtl[idx] = __float2bfloat16_rn(s - __bfloat162float(h));
    }
}

// ---------------------------------------------------------------------------
// Flash-style mma attention (acc pairs interleaved; per-acc order unchanged).
// ---------------------------------------------------------------------------
#define AT_QH 0
#define AT_QL 18432
#define AT_KH 36864
#define AT_KL 55296
#define AT_VH 73728
#define AT_VL 91136
#define ATTN_SMEM 108544

__global__ void __launch_bounds__(256)
attn_kernel()
{
    extern __shared__ char smem[];
    const int bh = blockIdx.y;
    const int b  = bh >> 4;
    const int hh = bh & 15;
    const int l0 = blockIdx.x * 128;
    const int tid  = threadIdx.x;
    const int wp   = tid >> 5;
    const int lane = tid & 31;
    const int lr   = lane & 15;
    const int lh   = lane >> 4;
    const int qrow = lane >> 2;
    const int qcol = (lane & 3) * 2;

    const size_t qbase = (size_t)(b * L_SEQ + l0) * 1024 + hh * 64;
#pragma unroll
    for (int t = 0; t < 4; t++) {
        int i = tid + t * 256;
        int r = i >> 3, c = i & 7;
        cpa16(sptr(smem + AT_QH + r * 144 + c * 16), g_qh + qbase + (size_t)r * 1024 + c * 8);
        cpa16(sptr(smem + AT_QL + r * 144 + c * 16), g_ql + qbase + (size_t)r * 1024 + c * 8);
        cpa16(sptr(smem + AT_KH + r * 144 + c * 16), g_kph + (size_t)bh * 8192 + r * 64 + c * 8);
        cpa16(sptr(smem + AT_KL + r * 144 + c * 16), g_kpl + (size_t)bh * 8192 + r * 64 + c * 8);
        int rv = i >> 4, cv = i & 15;
        cpa16(sptr(smem + AT_VH + rv * 272 + cv * 16), g_vth + (size_t)bh * 8192 + rv * 128 + cv * 8);
        cpa16(sptr(smem + AT_VL + rv * 272 + cv * 16), g_vtl + (size_t)bh * 8192 + rv * 128 + cv * 8);
    }
    asm volatile("cp.async.commit_group;" ::: "memory");
    asm volatile("cp.async.wait_group 0;" ::: "memory");
    __syncthreads();

    float acc[16][4];
#pragma unroll
    for (int i = 0; i < 16; i++)
#pragma unroll
        for (int q = 0; q < 4; q++) acc[i][q] = 0.f;

#pragma unroll
    for (int ks = 0; ks < 4; ks++) {
        uint32_t aqh[4], aql[4];
        ldm4(aqh, sptr(smem + AT_QH + (wp * 16 + lr) * 144 + ks * 32 + lh * 16));
        ldm4(aql, sptr(smem + AT_QL + (wp * 16 + lr) * 144 + ks * 32 + lh * 16));
#pragma unroll
        for (int g = 0; g < 8; g++) {
            uint32_t bkh[4], bkl[4];
            ldm4(bkh, sptr(smem + AT_KH + (g * 16 + lr) * 144 + ks * 32 + lh * 16));
            ldm4(bkl, sptr(smem + AT_KL + (g * 16 + lr) * 144 + ks * 32 + lh * 16));
            // interleave across the acc pair; per-acc order stays hh, hl, lh
            mma_bf16(acc[2*g],   aqh, bkh[0], bkh[2]);
            mma_bf16(acc[2*g+1], aqh, bkh[1], bkh[3]);
            mma_bf16(acc[2*g],   aqh, bkl[0], bkl[2]);
            mma_bf16(acc[2*g+1], aqh, bkl[1], bkl[3]);
            mma_bf16(acc[2*g],   aql, bkh[0], bkh[2]);
            mma_bf16(acc[2*g+1], aql, bkh[1], bkh[3]);
        }
    }

#pragma unroll
    for (int i = 0; i < 16; i++)
#pragma unroll
        for (int q = 0; q < 4; q++) acc[i][q] *= 0.125f;

    if (blockIdx.x == 0) {
        const int r0 = wp * 16 + qrow;
        const int r1 = r0 + 8;
#pragma unroll
        for (int nf = 0; nf < 16; nf++) {
            int p0 = nf * 8 + qcol;
            if (p0 > r0)     acc[nf][0] = -1e30f;
            if (p0 + 1 > r0) acc[nf][1] = -1e30f;
            if (p0 > r1)     acc[nf][2] = -1e30f;
            if (p0 + 1 > r1) acc[nf][3] = -1e30f;
        }
    }

    float mx0 = -1e30f, mx1 = -1e30f;
#pragma unroll
    for (int nf = 0; nf < 16; nf++) {
        mx0 = fmaxf(mx0, fmaxf(acc[nf][0], acc[nf][1]));
        mx1 = fmaxf(mx1, fmaxf(acc[nf][2], acc[nf][3]));
    }
    mx0 = fmaxf(mx0, __shfl_xor_sync(0xffffffffu, mx0, 1));
    mx0 = fmaxf(mx0, __shfl_xor_sync(0xffffffffu, mx0, 2));
    mx1 = fmaxf(mx1, __shfl_xor_sync(0xffffffffu, mx1, 1));
    mx1 = fmaxf(mx1, __shfl_xor_sync(0xffffffffu, mx1, 2));

    float s0 = 0.f, s1 = 0.f;
#pragma unroll
    for (int nf = 0; nf < 16; nf++) {
        acc[nf][0] = __expf(acc[nf][0] - mx0);
        acc[nf][1] = __expf(acc[nf][1] - mx0);
        acc[nf][2] = __expf(acc[nf][2] - mx1);
        acc[nf][3] = __expf(acc[nf][3] - mx1);
        s0 += acc[nf][0] + acc[nf][1];
        s1 += acc[nf][2] + acc[nf][3];
    }
    s0 += __shfl_xor_sync(0xffffffffu, s0, 1);
    s0 += __shfl_xor_sync(0xffffffffu, s0, 2);
    s1 += __shfl_xor_sync(0xffffffffu, s1, 1);
    s1 += __shfl_xor_sync(0xffffffffu, s1, 2);
    const float inv0 = 1.0f / s0;
    const float inv1 = 1.0f / s1;

    float o[8][4];
#pragma unroll
    for (int i = 0; i < 8; i++)
#pragma unroll
        for (int q = 0; q < 4; q++) o[i][q] = 0.f;

#pragma unroll
    for (int kc = 0; kc < 8; kc++) {
        uint32_t awh[4], awl[4];
        split2(acc[2*kc][0],   acc[2*kc][1],   awh[0], awl[0]);
        split2(acc[2*kc][2],   acc[2*kc][3],   awh[1], awl[1]);
        split2(acc[2*kc+1][0], acc[2*kc+1][1], awh[2], awl[2]);
        split2(acc[2*kc+1][2], acc[2*kc+1][3], awh[3], awl[3]);
#pragma unroll
        for (int g = 0; g < 4; g++) {
            uint32_t bvh[4], bvl[4];
            ldm4(bvh, sptr(smem + AT_VH + (g * 16 + lr) * 272 + kc * 32 + lh * 16));
            ldm4(bvl, sptr(smem + AT_VL + (g * 16 + lr) * 272 + kc * 32 + lh * 16));
            mma_bf16(o[2*g],   awh, bvh[0], bvh[2]);
            mma_bf16(o[2*g+1], awh, bvh[1], bvh[3]);
            mma_bf16(o[2*g],   awh, bvl[0], bvl[2]);
            mma_bf16(o[2*g+1], awh, bvl[1], bvl[3]);
            mma_bf16(o[2*g],   awl, bvh[0], bvh[2]);
            mma_bf16(o[2*g+1], awl, bvh[1], bvh[3]);
        }
    }

    const size_t row0 = (size_t)(b * L_SEQ + l0 + wp * 16 + qrow);
    const size_t row1 = row0 + 8;
#pragma unroll
    for (int nf = 0; nf < 8; nf++) {
        int col = hh * 64 + nf * 8 + qcol;
        uint32_t h01, l01, h23, l23;
        split2(o[nf][0] * inv0, o[nf][1] * inv0, h01, l01);
        split2(o[nf][2] * inv1, o[nf][3] * inv1, h23, l23);
        *(uint32_t*)(g_ah + row0 * 1024 + col) = h01;
        *(uint32_t*)(g_al + row0 * 1024 + col) = l01;
        *(uint32_t*)(g_ah + row1 * 1024 + col) = h23;
        *(uint32_t*)(g_al + row1 * 1024 + col) = l23;
    }
}

// ---------------------------------------------------------------------------
extern "C" void kernel_launch(void* const* d_in, const int* in_sizes, int n_in,
                              void* d_out, int out_size)
{
    const float* x    = (const float*)d_in[0];
    const float* fcos = (const float*)d_in[1];
    const float* fsin = (const float*)d_in[2];
    const float* Wq   = (const float*)d_in[3];
    const float* Wk   = (const float*)d_in[4];
    const float* Wv   = (const float*)d_in[5];
    const float* Wo   = (const float*)d_in[6];
    const float* kpm  = (const float*)d_in[7];
    const float* vpm  = (const float*)d_in[8];
    float* out = (float*)d_out;

    cudaFuncSetAttribute(attn_kernel,
                         cudaFuncAttributeMaxDynamicSharedMemorySize, ATTN_SMEM);
    cudaFuncSetAttribute(gemm_bf16x3<1,0,0,0,0>, cudaFuncAttributeMaxDynamicSharedMemorySize, SM_GEMM);
    cudaFuncSetAttribute(gemm_kv_part,           cudaFuncAttributeMaxDynamicSharedMemorySize, SM_GEMM);
    cudaFuncSetAttribute(gemm_bf16x3<0,0,1,3,3>, cudaFuncAttributeMaxDynamicSharedMemorySize, SM_GEMM);

    dim3 blk(256);
    // fp32 -> bf16 hi/lo splits
    convert_x <<<4096, blk>>>(x, (size_t)M_FULL * D_MODEL / 4);
    convert_w4<<<2048, blk>>>(Wq, Wk, Wv, Wo);

    // K/V split-K partial GEMMs + reduce w/ RoPE(K)
    gemm_kv_part<<<dim3(8, 4, 8), blk, SM_GEMM>>>();
    reduce_kv<<<512, blk>>>(fcos, fsin);

    // Q = rope(x @ Wq^T) -> bf16 hi/lo
    gemm_bf16x3<1,0,0,0,0><<<dim3(8, 128), blk, SM_GEMM>>>(fcos, fsin, nullptr, L_SEQ - 1);

    // Linformer tril projections -> bf16 hi/lo
    proj_kernel<<<dim3(BH, 8), blk>>>(kpm, vpm);
    // flash-style mma attention
    attn_kernel<<<dim3(L_SEQ / 128, BH), blk, ATTN_SMEM>>>();
    // out = attn @ Wo^T
    gemm_bf16x3<0,0,1,3,3><<<dim3(8, 128), blk, SM_GEMM>>>(nullptr, nullptr, out, 0);
}

// round 13
// speedup vs baseline: 1.9882x; 1.3355x over previous
#include <cuda_runtime.h>
#include <cuda_fp16.h>
#include <math.h>
#include <stdint.h>

#define L_SEQ   4096
#define D_MODEL 1024
#define N_HEADS 16
#define HEAD_DIM 64
#define P_DIM   128
#define B_SIZE  4
#define M_FULL  (B_SIZE * L_SEQ)   // 16384
#define M_KV    (B_SIZE * P_DIM)   // 512
#define BH      (B_SIZE * N_HEADS) // 64

// ---------------- scratch (static device arrays) ---------------------------
__device__ __half g_xh[(size_t)M_FULL * D_MODEL];          // x split hi (fp16)
__device__ __half g_xl[(size_t)M_FULL * D_MODEL];          // x split lo
__device__ __half g_w [4 * (size_t)D_MODEL * D_MODEL];     // weights single fp16
__device__ __half g_ah[(size_t)M_FULL * D_MODEL];          // attn out hi
__device__ __half g_al[(size_t)M_FULL * D_MODEL];          // attn out lo
__device__ __half g_qh[(size_t)M_FULL * D_MODEL];          // roped Q hi
__device__ __half g_ql[(size_t)M_FULL * D_MODEL];          // roped Q lo

__device__ float g_K[(size_t)M_KV * D_MODEL];
__device__ float g_V[(size_t)M_KV * D_MODEL];
__device__ float g_kvpart[8 * (size_t)M_KV * D_MODEL];

__device__ __half g_kp[BH * P_DIM * HEAD_DIM];             // K_proj [bh][p][d]
__device__ __half g_vt[BH * HEAD_DIM * P_DIM];             // V_proj^T [bh][d][p]

// ---------------------------------------------------------------------------
// fp32 -> fp16 converts
// ---------------------------------------------------------------------------
__device__ __forceinline__ void split4h(float4 v, uint2& H, uint2& L) {
    union { __half b[4]; uint2 u; } h, l;
    float f[4] = {v.x, v.y, v.z, v.w};
#pragma unroll
    for (int j = 0; j < 4; j++) {
        __half hv = __float2half_rn(f[j]);
        h.b[j] = hv;
        l.b[j] = __float2half_rn(f[j] - __half2float(hv));
    }
    H = h.u; L = l.u;
}

__global__ void __launch_bounds__(256)
convert_x(const float* __restrict__ src, size_t n4)
{
    const float4* s4 = (const float4*)src;
    for (size_t i = blockIdx.x * (size_t)blockDim.x + threadIdx.x; i < n4;
         i += (size_t)gridDim.x * blockDim.x) {
        uint2 H, L;
        split4h(s4[i], H, L);
        ((uint2*)g_xh)[i] = H;
        ((uint2*)g_xl)[i] = L;
    }
}

// all 4 weights -> single fp16
__global__ void __launch_bounds__(256)
convert_w4(const float* __restrict__ w0, const float* __restrict__ w1,
           const float* __restrict__ w2, const float* __restrict__ w3)
{
    const size_t per = (size_t)D_MODEL * D_MODEL / 4;
    const float* ws[4] = {w0, w1, w2, w3};
    for (size_t i = blockIdx.x * (size_t)blockDim.x + threadIdx.x; i < 4 * per;
         i += (size_t)gridDim.x * blockDim.x) {
        int slot = (int)(i / per);
        size_t j = i - (size_t)slot * per;
        float4 v = ((const float4*)ws[slot])[j];
        union { __half b[4]; uint2 u; } h;
        h.b[0] = __float2half_rn(v.x); h.b[1] = __float2half_rn(v.y);
        h.b[2] = __float2half_rn(v.z); h.b[3] = __float2half_rn(v.w);
        ((uint2*)g_w)[i] = h.u;
    }
}

// ---------------------------------------------------------------------------
// mma.sync helpers (fp16 operands, fp32 accum)
// ---------------------------------------------------------------------------
__device__ __forceinline__ uint32_t sptr(const void* p) {
    return (uint32_t)__cvta_generic_to_shared(p);
}
__device__ __forceinline__ void ldm4(uint32_t* r, uint32_t a) {
    asm volatile("ldmatrix.sync.aligned.m8n8.x4.shared.b16 {%0,%1,%2,%3}, [%4];"
                 : "=r"(r[0]), "=r"(r[1]), "=r"(r[2]), "=r"(r[3]) : "r"(a));
}
__device__ __forceinline__ void mma_f16(float* c, const uint32_t* a, uint32_t b0, uint32_t b1) {
    asm volatile(
        "mma.sync.aligned.m16n8k16.row.col.f32.f16.f16.f32 "
        "{%0,%1,%2,%3}, {%4,%5,%6,%7}, {%8,%9}, {%0,%1,%2,%3};"
        : "+f"(c[0]), "+f"(c[1]), "+f"(c[2]), "+f"(c[3])
        : "r"(a[0]), "r"(a[1]), "r"(a[2]), "r"(a[3]), "r"(b0), "r"(b1));
}
__device__ __forceinline__ void cpa16(uint32_t s, const void* g) {
    asm volatile("cp.async.ca.shared.global [%0], [%1], 16;" :: "r"(s), "l"(g));
}
__device__ __forceinline__ void cpa16cg(uint32_t s, const void* g) {
    asm volatile("cp.async.cg.shared.global [%0], [%1], 16;" :: "r"(s), "l"(g));
}
__device__ __forceinline__ void split2h(float x, float y, uint32_t& h, uint32_t& l) {
    __half xh = __float2half_rn(x);
    __half yh = __float2half_rn(y);
    union { __half2 v; uint32_t u; } H, L;
    H.v = __halves2half2(xh, yh);
    L.v = __halves2half2(__float2half_rn(x - __half2float(xh)),
                         __float2half_rn(y - __half2float(yh)));
    h = H.u; l = L.u;
}

// ---------------------------------------------------------------------------
// smem swizzle + tile constants: stage = {Ah, Al, B} x 8192 B = 24576 B
// ---------------------------------------------------------------------------
#define MAT_BYTES 8192
#define STG_BYTES (3 * MAT_BYTES)
#define SM_GEMM   (3 * STG_BYTES)   // 73728 B -> 2 CTAs/SM

__device__ __forceinline__ uint32_t swzoff(int row, int c16) {
    return (uint32_t)(row * 64 + ((c16 ^ ((row >> 1) & 3)) << 4));
}

// one product pass over the full warp tile (16 independent mma)
__device__ __forceinline__ void mma_pass2(
    float acc[2][8][4], uint32_t A[2][4], uint32_t B[4][4])
{
#pragma unroll
    for (int g = 0; g < 4; g++)
#pragma unroll
        for (int mf = 0; mf < 2; mf++) {
            mma_f16(acc[mf][2*g],   A[mf], B[g][0], B[g][2]);
            mma_f16(acc[mf][2*g+1], A[mf], B[g][1], B[g][3]);
        }
}

// ---------------------------------------------------------------------------
// fp16 A-split x2 NT GEMM, 128x128 tile, BK=32, 3-stage pipeline.
// C = (Ah + Al) . B^T ;  B single fp16.
// ---------------------------------------------------------------------------
template<int ROPE, int GATHER, int ASEL, int WOFF, int CSEL>
__global__ void __launch_bounds__(256, 2)
gemm_f16x2(const float* __restrict__ fcos, const float* __restrict__ fsin,
           float* __restrict__ Cext, int posmask)
{
    extern __shared__ char sbuf[];

    const __half* Ah = (ASEL == 0) ? g_xh : g_ah;
    const __half* Al = (ASEL == 0) ? g_xl : g_al;
    const __half* Bw = g_w + (size_t)WOFF * D_MODEL * D_MODEL;
    float* C = Cext;
    const __half* mats[3] = {Ah, Al, Bw};

    const int tid  = threadIdx.x;
    const int warp = tid >> 5;
    const int lane = tid & 31;
    const int wm   = warp & 3;
    const int wn   = warp >> 2;
    const int m_tile = blockIdx.y * 128;
    const int n_tile = blockIdx.x * 128;
    const int lr = lane & 15;
    const int lh = lane >> 4;

    float acc[2][8][4];
#pragma unroll
    for (int i = 0; i < 2; i++)
#pragma unroll
        for (int j = 0; j < 8; j++)
#pragma unroll
            for (int q = 0; q < 4; q++) acc[i][j][q] = 0.f;

    // per chunk: 3 mats x 128 rows x 4 c16 = 1536 copies; 6/thread
    auto load_chunk = [&](int st, int k0) {
#pragma unroll
        for (int t = 0; t < 6; t++) {
            int idx = tid + t * 256;
            int mtx = idx >> 9;               // 0=Ah 1=Al 2=B
            int rem = idx & 511;
            int row = rem >> 2;
            int c16 = rem & 3;
            int grow;
            if (mtx < 2) {
                int m = m_tile + row;
                grow = GATHER ? ((m >> 7) * L_SEQ + (m & 127)) : m;
            } else {
                grow = n_tile + row;
            }
            cpa16cg(sptr(sbuf + st * STG_BYTES + mtx * MAT_BYTES + swzoff(row, c16)),
                    mats[mtx] + (size_t)grow * 1024 + k0 + c16 * 8);
        }
    };

    load_chunk(0, 0);
    asm volatile("cp.async.commit_group;" ::: "memory");
    load_chunk(1, 32);
    asm volatile("cp.async.commit_group;" ::: "memory");

    for (int i = 0; i < 32; i++) {
        if (i < 31) asm volatile("cp.async.wait_group 1;" ::: "memory");
        else        asm volatile("cp.async.wait_group 0;" ::: "memory");
        __syncthreads();
        if (i + 2 < 32) {
            load_chunk((i + 2) % 3, (i + 2) * 32);
            asm volatile("cp.async.commit_group;" ::: "memory");
        }

        const char* stg = sbuf + (i % 3) * STG_BYTES;

#pragma unroll
        for (int ks = 0; ks < 2; ks++) {
            const int cb = ks * 2 + lh;
            uint32_t afh[2][4], afl[2][4];
#pragma unroll
            for (int mf = 0; mf < 2; mf++) {
                int row = wm * 32 + mf * 16 + lr;
                ldm4(afh[mf], sptr(stg + 0 * MAT_BYTES + swzoff(row, cb)));
                ldm4(afl[mf], sptr(stg + 1 * MAT_BYTES + swzoff(row, cb)));
            }
            uint32_t bf[4][4];
#pragma unroll
            for (int g = 0; g < 4; g++) {
                int row = wn * 64 + g * 16 + lr;
                ldm4(bf[g], sptr(stg + 2 * MAT_BYTES + swzoff(row, cb)));
            }
            mma_pass2(acc, afh, bf);   // hi
            mma_pass2(acc, afl, bf);   // lo
        }
    }

    const int qrow = lane >> 2;
    const int qcol = (lane & 3) * 2;
#pragma unroll
    for (int mf = 0; mf < 2; mf++)
#pragma unroll
        for (int nf = 0; nf < 8; nf++) {
            int n = n_tile + wn * 64 + nf * 8 + qcol;
#pragma unroll
            for (int hhalf = 0; hhalf < 2; hhalf++) {
                int m = m_tile + wm * 32 + mf * 16 + qrow + hhalf * 8;
                float v0 = acc[mf][nf][hhalf * 2];
                float v1 = acc[mf][nf][hhalf * 2 + 1];
                float o0 = v0, o1 = v1;
                if (ROPE) {
                    int pos = m & posmask;
                    int j   = (n & 63) >> 1;
                    float c = __ldg(fcos + pos * 32 + j);
                    float s = __ldg(fsin + pos * 32 + j);
                    o0 = v0 * c - v1 * s;
                    o1 = v0 * s + v1 * c;
                }
                if (CSEL == 0) {
                    uint32_t h, l;
                    split2h(o0, o1, h, l);
                    *(uint32_t*)(g_qh + (size_t)m * 1024 + n) = h;
                    *(uint32_t*)(g_ql + (size_t)m * 1024 + n) = l;
                } else {
                    *(float2*)(C + (size_t)m * 1024 + n) = make_float2(o0, o1);
                }
            }
        }
}

// ---------------------------------------------------------------------------
// Split-K partial GEMM for K and V (fp16 x2).
// ---------------------------------------------------------------------------
__global__ void __launch_bounds__(256, 2)
gemm_kv_part()
{
    extern __shared__ char sbuf[];

    const int kv = blockIdx.z >> 2;
    const int ks = blockIdx.z & 3;
    const int kbase = ks * 256;

    const __half* Bw = g_w + (size_t)(1 + kv) * D_MODEL * D_MODEL;
    const __half* mats[3] = {g_xh, g_xl, Bw};
    float* P = g_kvpart + (size_t)blockIdx.z * M_KV * D_MODEL;

    const int tid  = threadIdx.x;
    const int warp = tid >> 5;
    const int lane = tid & 31;
    const int wm   = warp & 3;
    const int wn   = warp >> 2;
    const int m_tile = blockIdx.y * 128;
    const int n_tile = blockIdx.x * 128;
    const int lr = lane & 15;
    const int lh = lane >> 4;

    float acc[2][8][4];
#pragma unroll
    for (int i = 0; i < 2; i++)
#pragma unroll
        for (int j = 0; j < 8; j++)
#pragma unroll
            for (int q = 0; q < 4; q++) acc[i][j][q] = 0.f;

    auto load_chunk = [&](int st, int k0) {
#pragma unroll
        for (int t = 0; t < 6; t++) {
            int idx = tid + t * 256;
            int mtx = idx >> 9;
            int rem = idx & 511;
            int row = rem >> 2;
            int c16 = rem & 3;
            int grow;
            if (mtx < 2) {
                int m = m_tile + row;
                grow = (m >> 7) * L_SEQ + (m & 127);
            } else {
                grow = n_tile + row;
            }
            cpa16cg(sptr(sbuf + st * STG_BYTES + mtx * MAT_BYTES + swzoff(row, c16)),
                    mats[mtx] + (size_t)grow * 1024 + k0 + c16 * 8);
        }
    };

    load_chunk(0, kbase);
    asm volatile("cp.async.commit_group;" ::: "memory");
    load_chunk(1, kbase + 32);
    asm volatile("cp.async.commit_group;" ::: "memory");

    for (int i = 0; i < 8; i++) {
        if (i < 7) asm volatile("cp.async.wait_group 1;" ::: "memory");
        else       asm volatile("cp.async.wait_group 0;" ::: "memory");
        __syncthreads();
        if (i + 2 < 8) {
            load_chunk((i + 2) % 3, kbase + (i + 2) * 32);
            asm volatile("cp.async.commit_group;" ::: "memory");
        }

        const char* stg = sbuf + (i % 3) * STG_BYTES;

#pragma unroll
        for (int kk = 0; kk < 2; kk++) {
            const int cb = kk * 2 + lh;
            uint32_t afh[2][4], afl[2][4];
#pragma unroll
            for (int mf = 0; mf < 2; mf++) {
                int row = wm * 32 + mf * 16 + lr;
                ldm4(afh[mf], sptr(stg + 0 * MAT_BYTES + swzoff(row, cb)));
                ldm4(afl[mf], sptr(stg + 1 * MAT_BYTES + swzoff(row, cb)));
            }
            uint32_t bf[4][4];
#pragma unroll
            for (int g = 0; g < 4; g++) {
                int row = wn * 64 + g * 16 + lr;
                ldm4(bf[g], sptr(stg + 2 * MAT_BYTES + swzoff(row, cb)));
            }
            mma_pass2(acc, afh, bf);
            mma_pass2(acc, afl, bf);
        }
    }

    const int qrow = lane >> 2;
    const int qcol = (lane & 3) * 2;
#pragma unroll
    for (int mf = 0; mf < 2; mf++)
#pragma unroll
        for (int nf = 0; nf < 8; nf++) {
            int n = n_tile + wn * 64 + nf * 8 + qcol;
#pragma unroll
            for (int hhalf = 0; hhalf < 2; hhalf++) {
                int m = m_tile + wm * 32 + mf * 16 + qrow + hhalf * 8;
                *(float2*)(P + (size_t)m * 1024 + n) =
                    make_float2(acc[mf][nf][hhalf * 2], acc[mf][nf][hhalf * 2 + 1]);
            }
        }
}

// ---------------------------------------------------------------------------
// Reduce 4 k-split partials; RoPE on K; write g_K / g_V fp32.
// ---------------------------------------------------------------------------
__global__ void __launch_bounds__(256)
reduce_kv(const float* __restrict__ fcos, const float* __restrict__ fsin)
{
    const size_t total = (size_t)2 * M_KV * 256;
    for (size_t i = blockIdx.x * (size_t)blockDim.x + threadIdx.x; i < total;
         i += (size_t)gridDim.x * blockDim.x) {
        int kv  = (int)(i / ((size_t)M_KV * 256));
        size_t rem = i - (size_t)kv * M_KV * 256;
        int m   = (int)(rem >> 8);
        int c4  = (int)(rem & 255);
        int n   = c4 * 4;

        const float4* base = (const float4*)(g_kvpart) + (size_t)kv * 4 * M_KV * 256 + rem;
        float4 s = base[0];
        float4 p1 = base[(size_t)M_KV * 256];
        float4 p2 = base[(size_t)2 * M_KV * 256];
        float4 p3 = base[(size_t)3 * M_KV * 256];
        s.x += p1.x; s.y += p1.y; s.z += p1.z; s.w += p1.w;
        s.x += p2.x; s.y += p2.y; s.z += p2.z; s.w += p2.w;
        s.x += p3.x; s.y += p3.y; s.z += p3.z; s.w += p3.w;

        if (kv == 0) {
            int pos = m & (P_DIM - 1);
            int j   = (n & 63) >> 1;
            float c0 = __ldg(fcos + pos * 32 + j);
            float s0 = __ldg(fsin + pos * 32 + j);
            float c1 = __ldg(fcos + pos * 32 + j + 1);
            float s1 = __ldg(fsin + pos * 32 + j + 1);
            float4 r;
            r.x = s.x * c0 - s.y * s0;
            r.y = s.x * s0 + s.y * c0;
            r.z = s.z * c1 - s.w * s1;
            r.w = s.z * s1 + s.w * c1;
            ((float4*)g_K)[rem] = r;
        } else {
            ((float4*)g_V)[rem] = s;
        }
    }
}

// ---------------------------------------------------------------------------
// K_proj / V_proj (tril): grid (BH, 8).  single fp16 outputs.
// ---------------------------------------------------------------------------
__global__ void __launch_bounds__(256)
proj_kernel(const float* __restrict__ kpm, const float* __restrict__ vpm)
{
    __shared__ float Ts[128][9];
    const int bh = blockIdx.x;
    const int b  = bh >> 4;
    const int hh = bh & 15;
    const int d0 = blockIdx.y * 8;
    const int tid = threadIdx.x;

    for (int idx = tid; idx < 128 * 8; idx += 256) {
        int l = idx >> 3, d = idx & 7;
        Ts[l][d] = g_K[(size_t)(b * 128 + l) * 1024 + hh * 64 + d0 + d];
    }
    __syncthreads();
#pragma unroll
    for (int t = 0; t < 4; t++) {
        int o = tid + t * 256;
        int p = o >> 3, d = o & 7;
        const float* pr = kpm + (size_t)p * 4096;
        float s = 0.f;
        for (int l = 0; l <= p; l++) s = fmaf(pr[l], Ts[l][d], s);
        g_kp[(size_t)bh * 8192 + p * 64 + (d0 + d)] = __float2half_rn(s);
    }
    __syncthreads();
    for (int idx = tid; idx < 128 * 8; idx += 256) {
        int l = idx >> 3, d = idx & 7;
        Ts[l][d] = g_V[(size_t)(b * 128 + l) * 1024 + hh * 64 + d0 + d];
    }
    __syncthreads();
#pragma unroll
    for (int t = 0; t < 4; t++) {
        int o = tid + t * 256;
        int p = o >> 3, d = o & 7;
        const float* pr = vpm + (size_t)p * 4096;
        float s = 0.f;
        for (int l = 0; l <= p; l++) s = fmaf(pr[l], Ts[l][d], s);
        g_vt[(size_t)bh * 8192 + (d0 + d) * 128 + p] = __float2half_rn(s);
    }
}

// ---------------------------------------------------------------------------
// Flash-style mma attention, fp16.
// smem: QH/QL/K [128][144B], VT [64][272B] = 72704 B
// ---------------------------------------------------------------------------
#define AT_QH 0
#define AT_QL 18432
#define AT_K  36864
#define AT_VT 55296
#define ATTN_SMEM 72704

__global__ void __launch_bounds__(256)
attn_kernel()
{
    extern __shared__ char smem[];
    const int bh = blockIdx.y;
    const int b  = bh >> 4;
    const int hh = bh & 15;
    const int l0 = blockIdx.x * 128;
    const int tid  = threadIdx.x;
    const int wp   = tid >> 5;
    const int lane = tid & 31;
    const int lr   = lane & 15;
    const int lh   = lane >> 4;
    const int qrow = lane >> 2;
    const int qcol = (lane & 3) * 2;

    const size_t qbase = (size_t)(b * L_SEQ + l0) * 1024 + hh * 64;
#pragma unroll
    for (int t = 0; t < 4; t++) {
        int i = tid + t * 256;
        int r = i >> 3, c = i & 7;
        cpa16(sptr(smem + AT_QH + r * 144 + c * 16), g_qh + qbase + (size_t)r * 1024 + c * 8);
        cpa16(sptr(smem + AT_QL + r * 144 + c * 16), g_ql + qbase + (size_t)r * 1024 + c * 8);
        cpa16(sptr(smem + AT_K  + r * 144 + c * 16), g_kp + (size_t)bh * 8192 + r * 64 + c * 8);
        int rv = i >> 4, cv = i & 15;
        cpa16(sptr(smem + AT_VT + rv * 272 + cv * 16), g_vt + (size_t)bh * 8192 + rv * 128 + cv * 8);
    }
    asm volatile("cp.async.commit_group;" ::: "memory");
    asm volatile("cp.async.wait_group 0;" ::: "memory");
    __syncthreads();

    float acc[16][4];
#pragma unroll
    for (int i = 0; i < 16; i++)
#pragma unroll
        for (int q = 0; q < 4; q++) acc[i][q] = 0.f;

#pragma unroll
    for (int ks = 0; ks < 4; ks++) {
        uint32_t aqh[4], aql[4];
        ldm4(aqh, sptr(smem + AT_QH + (wp * 16 + lr) * 144 + ks * 32 + lh * 16));
        ldm4(aql, sptr(smem + AT_QL + (wp * 16 + lr) * 144 + ks * 32 + lh * 16));
#pragma unroll
        for (int g = 0; g < 8; g++) {
            uint32_t bk[4];
            ldm4(bk, sptr(smem + AT_K + (g * 16 + lr) * 144 + ks * 32 + lh * 16));
            mma_f16(acc[2*g],   aqh, bk[0], bk[2]);
            mma_f16(acc[2*g+1], aqh, bk[1], bk[3]);
            mma_f16(acc[2*g],   aql, bk[0], bk[2]);
            mma_f16(acc[2*g+1], aql, bk[1], bk[3]);
        }
    }

#pragma unroll
    for (int i = 0; i < 16; i++)
#pragma unroll
        for (int q = 0; q < 4; q++) acc[i][q] *= 0.125f;

    if (blockIdx.x == 0) {
        const int r0 = wp * 16 + qrow;
        const int r1 = r0 + 8;
#pragma unroll
        for (int nf = 0; nf < 16; nf++) {
            int p0 = nf * 8 + qcol;
            if (p0 > r0)     acc[nf][0] = -1e30f;
            if (p0 + 1 > r0) acc[nf][1] = -1e30f;
            if (p0 > r1)     acc[nf][2] = -1e30f;
            if (p0 + 1 > r1) acc[nf][3] = -1e30f;
        }
    }

    float mx0 = -1e30f, mx1 = -1e30f;
#pragma unroll
    for (int nf = 0; nf < 16; nf++) {
        mx0 = fmaxf(mx0, fmaxf(acc[nf][0], acc[nf][1]));
        mx1 = fmaxf(mx1, fmaxf(acc[nf][2], acc[nf][3]));
    }
    mx0 = fmaxf(mx0, __shfl_xor_sync(0xffffffffu, mx0, 1));
    mx0 = fmaxf(mx0, __shfl_xor_sync(0xffffffffu, mx0, 2));
    mx1 = fmaxf(mx1, __shfl_xor_sync(0xffffffffu, mx1, 1));
    mx1 = fmaxf(mx1, __shfl_xor_sync(0xffffffffu, mx1, 2));

    float s0 = 0.f, s1 = 0.f;
#pragma unroll
    for (int nf = 0; nf < 16; nf++) {
        acc[nf][0] = __expf(acc[nf][0] - mx0);
        acc[nf][1] = __expf(acc[nf][1] - mx0);
        acc[nf][2] = __expf(acc[nf][2] - mx1);
        acc[nf][3] = __expf(acc[nf][3] - mx1);
        s0 += acc[nf][0] + acc[nf][1];
        s1 += acc[nf][2] + acc[nf][3];
    }
    s0 += __shfl_xor_sync(0xffffffffu, s0, 1);
    s0 += __shfl_xor_sync(0xffffffffu, s0, 2);
    s1 += __shfl_xor_sync(0xffffffffu, s1, 1);
    s1 += __shfl_xor_sync(0xffffffffu, s1, 2);
    const float inv0 = 1.0f / s0;
    const float inv1 = 1.0f / s1;

    float o[8][4];
#pragma unroll
    for (int i = 0; i < 8; i++)
#pragma unroll
        for (int q = 0; q < 4; q++) o[i][q] = 0.f;

#pragma unroll
    for (int kc = 0; kc < 8; kc++) {
        // repack softmax weights hi/lo fp16 (C-layout == A-layout)
        uint32_t awh[4], awl[4];
        split2h(acc[2*kc][0],   acc[2*kc][1],   awh[0], awl[0]);
        split2h(acc[2*kc][2],   acc[2*kc][3],   awh[1], awl[1]);
        split2h(acc[2*kc+1][0], acc[2*kc+1][1], awh[2], awl[2]);
        split2h(acc[2*kc+1][2], acc[2*kc+1][3], awh[3], awl[3]);
#pragma unroll
        for (int g = 0; g < 4; g++) {
            uint32_t bv[4];
            ldm4(bv, sptr(smem + AT_VT + (g * 16 + lr) * 272 + kc * 32 + lh * 16));
            mma_f16(o[2*g],   awh, bv[0], bv[2]);
            mma_f16(o[2*g+1], awh, bv[1], bv[3]);
            mma_f16(o[2*g],   awl, bv[0], bv[2]);
            mma_f16(o[2*g+1], awl, bv[1], bv[3]);
        }
    }

    const size_t row0 = (size_t)(b * L_SEQ + l0 + wp * 16 + qrow);
    const size_t row1 = row0 + 8;
#pragma unroll
    for (int nf = 0; nf < 8; nf++) {
        int col = hh * 64 + nf * 8 + qcol;
        uint32_t h01, l01, h23, l23;
        split2h(o[nf][0] * inv0, o[nf][1] * inv0, h01, l01);
        split2h(o[nf][2] * inv1, o[nf][3] * inv1, h23, l23);
        *(uint32_t*)(g_ah + row0 * 1024 + col) = h01;
        *(uint32_t*)(g_al + row0 * 1024 + col) = l01;
        *(uint32_t*)(g_ah + row1 * 1024 + col) = h23;
        *(uint32_t*)(g_al + row1 * 1024 + col) = l23;
    }
}

// ---------------------------------------------------------------------------
extern "C" void kernel_launch(void* const* d_in, const int* in_sizes, int n_in,
                              void* d_out, int out_size)
{
    const float* x    = (const float*)d_in[0];
    const float* fcos = (const float*)d_in[1];
    const float* fsin = (const float*)d_in[2];
    const float* Wq   = (const float*)d_in[3];
    const float* Wk   = (const float*)d_in[4];
    const float* Wv   = (const float*)d_in[5];
    const float* Wo   = (const float*)d_in[6];
    const float* kpm  = (const float*)d_in[7];
    const float* vpm  = (const float*)d_in[8];
    float* out = (float*)d_out;

    cudaFuncSetAttribute(attn_kernel,
                         cudaFuncAttributeMaxDynamicSharedMemorySize, ATTN_SMEM);
    cudaFuncSetAttribute(gemm_f16x2<1,0,0,0,0>, cudaFuncAttributeMaxDynamicSharedMemorySize, SM_GEMM);
    cudaFuncSetAttribute(gemm_kv_part,          cudaFuncAttributeMaxDynamicSharedMemorySize, SM_GEMM);
    cudaFuncSetAttribute(gemm_f16x2<0,0,1,3,3>, cudaFuncAttributeMaxDynamicSharedMemorySize, SM_GEMM);

    dim3 blk(256);
    // fp32 -> fp16 converts
    convert_x <<<4096, blk>>>(x, (size_t)M_FULL * D_MODEL / 4);
    convert_w4<<<2048, blk>>>(Wq, Wk, Wv, Wo);

    // K/V split-K partial GEMMs + reduce w/ RoPE(K)
    gemm_kv_part<<<dim3(8, 4, 8), blk, SM_GEMM>>>();
    reduce_kv<<<512, blk>>>(fcos, fsin);

    // Q = rope(x @ Wq^T) -> fp16 hi/lo
    gemm_f16x2<1,0,0,0,0><<<dim3(8, 128), blk, SM_GEMM>>>(fcos, fsin, nullptr, L_SEQ - 1);

    // Linformer tril projections -> fp16
    proj_kernel<<<dim3(BH, 8), blk>>>(kpm, vpm);
    // flash-style mma attention
    attn_kernel<<<dim3(L_SEQ / 128, BH), blk, ATTN_SMEM>>>();
    // out = attn @ Wo^T
    gemm_f16x2<0,0,1,3,3><<<dim3(8, 128), blk, SM_GEMM>>>(nullptr, nullptr, out, 0);
}

// round 14
// speedup vs baseline: 3.2388x; 1.6290x over previous
#include <cuda_runtime.h>
#include <cuda_fp16.h>
#include <math.h>
#include <stdint.h>

#define L_SEQ   4096
#define D_MODEL 1024
#define N_HEADS 16
#define HEAD_DIM 64
#define P_DIM   128
#define B_SIZE  4
#define M_FULL  (B_SIZE * L_SEQ)   // 16384
#define M_KV    (B_SIZE * P_DIM)   // 512
#define BH      (B_SIZE * N_HEADS) // 64

// ---------------- scratch (static device arrays) ---------------------------
__device__ __half g_x [(size_t)M_FULL * D_MODEL];          // x fp16
__device__ __half g_w [4 * (size_t)D_MODEL * D_MODEL];     // weights fp16
__device__ __half g_a [(size_t)M_FULL * D_MODEL];          // attn out fp16
__device__ __half g_q [(size_t)M_FULL * D_MODEL];          // roped Q fp16

__device__ float g_K[(size_t)M_KV * D_MODEL];
__device__ float g_V[(size_t)M_KV * D_MODEL];
__device__ float g_kvpart[8 * (size_t)M_KV * D_MODEL];

__device__ __half g_kp[BH * P_DIM * HEAD_DIM];             // K_proj [bh][p][d]
__device__ __half g_vt[BH * HEAD_DIM * P_DIM];             // V_proj^T [bh][d][p]

// ---------------------------------------------------------------------------
// fp32 -> fp16 converts
// ---------------------------------------------------------------------------
__global__ void __launch_bounds__(256)
convert_x(const float* __restrict__ src, size_t n4)
{
    const float4* s4 = (const float4*)src;
    for (size_t i = blockIdx.x * (size_t)blockDim.x + threadIdx.x; i < n4;
         i += (size_t)gridDim.x * blockDim.x) {
        float4 v = s4[i];
        union { __half b[4]; uint2 u; } h;
        h.b[0] = __float2half_rn(v.x); h.b[1] = __float2half_rn(v.y);
        h.b[2] = __float2half_rn(v.z); h.b[3] = __float2half_rn(v.w);
        ((uint2*)g_x)[i] = h.u;
    }
}

__global__ void __launch_bounds__(256)
convert_w4(const float* __restrict__ w0, const float* __restrict__ w1,
           const float* __restrict__ w2, const float* __restrict__ w3)
{
    const size_t per = (size_t)D_MODEL * D_MODEL / 4;
    const float* ws[4] = {w0, w1, w2, w3};
    for (size_t i = blockIdx.x * (size_t)blockDim.x + threadIdx.x; i < 4 * per;
         i += (size_t)gridDim.x * blockDim.x) {
        int slot = (int)(i / per);
        size_t j = i - (size_t)slot * per;
        float4 v = ((const float4*)ws[slot])[j];
        union { __half b[4]; uint2 u; } h;
        h.b[0] = __float2half_rn(v.x); h.b[1] = __float2half_rn(v.y);
        h.b[2] = __float2half_rn(v.z); h.b[3] = __float2half_rn(v.w);
        ((uint2*)g_w)[i] = h.u;
    }
}

// ---------------------------------------------------------------------------
// mma.sync helpers (fp16 operands, fp32 accum)
// ---------------------------------------------------------------------------
__device__ __forceinline__ uint32_t sptr(const void* p) {
    return (uint32_t)__cvta_generic_to_shared(p);
}
__device__ __forceinline__ void ldm4(uint32_t* r, uint32_t a) {
    asm volatile("ldmatrix.sync.aligned.m8n8.x4.shared.b16 {%0,%1,%2,%3}, [%4];"
                 : "=r"(r[0]), "=r"(r[1]), "=r"(r[2]), "=r"(r[3]) : "r"(a));
}
__device__ __forceinline__ void mma_f16(float* c, const uint32_t* a, uint32_t b0, uint32_t b1) {
    asm volatile(
        "mma.sync.aligned.m16n8k16.row.col.f32.f16.f16.f32 "
        "{%0,%1,%2,%3}, {%4,%5,%6,%7}, {%8,%9}, {%0,%1,%2,%3};"
        : "+f"(c[0]), "+f"(c[1]), "+f"(c[2]), "+f"(c[3])
        : "r"(a[0]), "r"(a[1]), "r"(a[2]), "r"(a[3]), "r"(b0), "r"(b1));
}
__device__ __forceinline__ void cpa16(uint32_t s, const void* g) {
    asm volatile("cp.async.ca.shared.global [%0], [%1], 16;" :: "r"(s), "l"(g));
}
__device__ __forceinline__ void cpa16cg(uint32_t s, const void* g) {
    asm volatile("cp.async.cg.shared.global [%0], [%1], 16;" :: "r"(s), "l"(g));
}
__device__ __forceinline__ uint32_t pack2h(float x, float y) {
    union { __half2 v; uint32_t u; } H;
    H.v = __halves2half2(__float2half_rn(x), __float2half_rn(y));
    return H.u;
}

// ---------------------------------------------------------------------------
// smem swizzle + tile constants: stage = {A, B} x 8192 B = 16384 B
// ---------------------------------------------------------------------------
#define MAT_BYTES 8192
#define STG_BYTES (2 * MAT_BYTES)
#define SM_GEMM   (3 * STG_BYTES)   // 49152 B -> 2 CTAs/SM

__device__ __forceinline__ uint32_t swzoff(int row, int c16) {
    return (uint32_t)(row * 64 + ((c16 ^ ((row >> 1) & 3)) << 4));
}

// one pass over the full 128x128 warp tile (16 independent mma)
__device__ __forceinline__ void mma_pass1(
    float acc[2][8][4], uint32_t A[2][4], uint32_t B[4][4])
{
#pragma unroll
    for (int g = 0; g < 4; g++)
#pragma unroll
        for (int mf = 0; mf < 2; mf++) {
            mma_f16(acc[mf][2*g],   A[mf], B[g][0], B[g][2]);
            mma_f16(acc[mf][2*g+1], A[mf], B[g][1], B[g][3]);
        }
}

// ---------------------------------------------------------------------------
// fp16 NT GEMM, 128x128 tile, BK=32, 3-stage pipeline.
// ---------------------------------------------------------------------------
template<int ROPE, int GATHER, int ASEL, int WOFF, int CSEL>
__global__ void __launch_bounds__(256, 2)
gemm_f16(const float* __restrict__ fcos, const float* __restrict__ fsin,
         float* __restrict__ Cext, int posmask)
{
    extern __shared__ char sbuf[];

    const __half* A  = (ASEL == 0) ? g_x : g_a;
    const __half* Bw = g_w + (size_t)WOFF * D_MODEL * D_MODEL;
    float* C = Cext;
    const __half* mats[2] = {A, Bw};

    const int tid  = threadIdx.x;
    const int warp = tid >> 5;
    const int lane = tid & 31;
    const int wm   = warp & 3;
    const int wn   = warp >> 2;
    const int m_tile = blockIdx.y * 128;
    const int n_tile = blockIdx.x * 128;
    const int lr = lane & 15;
    const int lh = lane >> 4;

    float acc[2][8][4];
#pragma unroll
    for (int i = 0; i < 2; i++)
#pragma unroll
        for (int j = 0; j < 8; j++)
#pragma unroll
            for (int q = 0; q < 4; q++) acc[i][j][q] = 0.f;

    // per chunk: 2 mats x 512 copies = 1024; 4 per thread
    auto load_chunk = [&](int st, int k0) {
#pragma unroll
        for (int t = 0; t < 4; t++) {
            int idx = tid + t * 256;
            int mtx = idx >> 9;               // 0=A 1=B
            int rem = idx & 511;
            int row = rem >> 2;
            int c16 = rem & 3;
            int grow;
            if (mtx == 0) {
                int m = m_tile + row;
                grow = GATHER ? ((m >> 7) * L_SEQ + (m & 127)) : m;
            } else {
                grow = n_tile + row;
            }
            cpa16cg(sptr(sbuf + st * STG_BYTES + mtx * MAT_BYTES + swzoff(row, c16)),
                    mats[mtx] + (size_t)grow * 1024 + k0 + c16 * 8);
        }
    };

    load_chunk(0, 0);
    asm volatile("cp.async.commit_group;" ::: "memory");
    load_chunk(1, 32);
    asm volatile("cp.async.commit_group;" ::: "memory");

    for (int i = 0; i < 32; i++) {
        if (i < 31) asm volatile("cp.async.wait_group 1;" ::: "memory");
        else        asm volatile("cp.async.wait_group 0;" ::: "memory");
        __syncthreads();
        if (i + 2 < 32) {
            load_chunk((i + 2) % 3, (i + 2) * 32);
            asm volatile("cp.async.commit_group;" ::: "memory");
        }

        const char* stg = sbuf + (i % 3) * STG_BYTES;

#pragma unroll
        for (int ks = 0; ks < 2; ks++) {
            const int cb = ks * 2 + lh;
            uint32_t af[2][4];
#pragma unroll
            for (int mf = 0; mf < 2; mf++) {
                int row = wm * 32 + mf * 16 + lr;
                ldm4(af[mf], sptr(stg + 0 * MAT_BYTES + swzoff(row, cb)));
            }
            uint32_t bf[4][4];
#pragma unroll
            for (int g = 0; g < 4; g++) {
                int row = wn * 64 + g * 16 + lr;
                ldm4(bf[g], sptr(stg + 1 * MAT_BYTES + swzoff(row, cb)));
            }
            mma_pass1(acc, af, bf);
        }
    }

    const int qrow = lane >> 2;
    const int qcol = (lane & 3) * 2;
#pragma unroll
    for (int mf = 0; mf < 2; mf++)
#pragma unroll
        for (int nf = 0; nf < 8; nf++) {
            int n = n_tile + wn * 64 + nf * 8 + qcol;
#pragma unroll
            for (int hhalf = 0; hhalf < 2; hhalf++) {
                int m = m_tile + wm * 32 + mf * 16 + qrow + hhalf * 8;
                float v0 = acc[mf][nf][hhalf * 2];
                float v1 = acc[mf][nf][hhalf * 2 + 1];
                float o0 = v0, o1 = v1;
                if (ROPE) {
                    int pos = m & posmask;
                    int j   = (n & 63) >> 1;
                    float c = __ldg(fcos + pos * 32 + j);
                    float s = __ldg(fsin + pos * 32 + j);
                    o0 = v0 * c - v1 * s;
                    o1 = v0 * s + v1 * c;
                }
                if (CSEL == 0) {
                    *(uint32_t*)(g_q + (size_t)m * 1024 + n) = pack2h(o0, o1);
                } else {
                    *(float2*)(C + (size_t)m * 1024 + n) = make_float2(o0, o1);
                }
            }
        }
}

// ---------------------------------------------------------------------------
// Split-K partial GEMM for K and V (fp16 x1).
// ---------------------------------------------------------------------------
__global__ void __launch_bounds__(256, 2)
gemm_kv_part()
{
    extern __shared__ char sbuf[];

    const int kv = blockIdx.z >> 2;
    const int ks = blockIdx.z & 3;
    const int kbase = ks * 256;

    const __half* Bw = g_w + (size_t)(1 + kv) * D_MODEL * D_MODEL;
    const __half* mats[2] = {g_x, Bw};
    float* P = g_kvpart + (size_t)blockIdx.z * M_KV * D_MODEL;

    const int tid  = threadIdx.x;
    const int warp = tid >> 5;
    const int lane = tid & 31;
    const int wm   = warp & 3;
    const int wn   = warp >> 2;
    const int m_tile = blockIdx.y * 128;
    const int n_tile = blockIdx.x * 128;
    const int lr = lane & 15;
    const int lh = lane >> 4;

    float acc[2][8][4];
#pragma unroll
    for (int i = 0; i < 2; i++)
#pragma unroll
        for (int j = 0; j < 8; j++)
#pragma unroll
            for (int q = 0; q < 4; q++) acc[i][j][q] = 0.f;

    auto load_chunk = [&](int st, int k0) {
#pragma unroll
        for (int t = 0; t < 4; t++) {
            int idx = tid + t * 256;
            int mtx = idx >> 9;
            int rem = idx & 511;
            int row = rem >> 2;
            int c16 = rem & 3;
            int grow;
            if (mtx == 0) {
                int m = m_tile + row;
                grow = (m >> 7) * L_SEQ + (m & 127);
            } else {
                grow = n_tile + row;
            }
            cpa16cg(sptr(sbuf + st * STG_BYTES + mtx * MAT_BYTES + swzoff(row, c16)),
                    mats[mtx] + (size_t)grow * 1024 + k0 + c16 * 8);
        }
    };

    load_chunk(0, kbase);
    asm volatile("cp.async.commit_group;" ::: "memory");
    load_chunk(1, kbase + 32);
    asm volatile("cp.async.commit_group;" ::: "memory");

    for (int i = 0; i < 8; i++) {
        if (i < 7) asm volatile("cp.async.wait_group 1;" ::: "memory");
        else       asm volatile("cp.async.wait_group 0;" ::: "memory");
        __syncthreads();
        if (i + 2 < 8) {
            load_chunk((i + 2) % 3, kbase + (i + 2) * 32);
            asm volatile("cp.async.commit_group;" ::: "memory");
        }

        const char* stg = sbuf + (i % 3) * STG_BYTES;

#pragma unroll
        for (int kk = 0; kk < 2; kk++) {
            const int cb = kk * 2 + lh;
            uint32_t af[2][4];
#pragma unroll
            for (int mf = 0; mf < 2; mf++) {
                int row = wm * 32 + mf * 16 + lr;
                ldm4(af[mf], sptr(stg + 0 * MAT_BYTES + swzoff(row, cb)));
            }
            uint32_t bf[4][4];
#pragma unroll
            for (int g = 0; g < 4; g++) {
                int row = wn * 64 + g * 16 + lr;
                ldm4(bf[g], sptr(stg + 1 * MAT_BYTES + swzoff(row, cb)));
            }
            mma_pass1(acc, af, bf);
        }
    }

    const int qrow = lane >> 2;
    const int qcol = (lane & 3) * 2;
#pragma unroll
    for (int mf = 0; mf < 2; mf++)
#pragma unroll
        for (int nf = 0; nf < 8; nf++) {
            int n = n_tile + wn * 64 + nf * 8 + qcol;
#pragma unroll
            for (int hhalf = 0; hhalf < 2; hhalf++) {
                int m = m_tile + wm * 32 + mf * 16 + qrow + hhalf * 8;
                *(float2*)(P + (size_t)m * 1024 + n) =
                    make_float2(acc[mf][nf][hhalf * 2], acc[mf][nf][hhalf * 2 + 1]);
            }
        }
}

// ---------------------------------------------------------------------------
// Reduce 4 k-split partials; RoPE on K; write g_K / g_V fp32.
// ---------------------------------------------------------------------------
__global__ void __launch_bounds__(256)
reduce_kv(const float* __restrict__ fcos, const float* __restrict__ fsin)
{
    const size_t total = (size_t)2 * M_KV * 256;
    for (size_t i = blockIdx.x * (size_t)blockDim.x + threadIdx.x; i < total;
         i += (size_t)gridDim.x * blockDim.x) {
        int kv  = (int)(i / ((size_t)M_KV * 256));
        size_t rem = i - (size_t)kv * M_KV * 256;
        int m   = (int)(rem >> 8);
        int c4  = (int)(rem & 255);
        int n   = c4 * 4;

        const float4* base = (const float4*)(g_kvpart) + (size_t)kv * 4 * M_KV * 256 + rem;
        float4 s = base[0];
        float4 p1 = base[(size_t)M_KV * 256];
        float4 p2 = base[(size_t)2 * M_KV * 256];
        float4 p3 = base[(size_t)3 * M_KV * 256];
        s.x += p1.x; s.y += p1.y; s.z += p1.z; s.w += p1.w;
        s.x += p2.x; s.y += p2.y; s.z += p2.z; s.w += p2.w;
        s.x += p3.x; s.y += p3.y; s.z += p3.z; s.w += p3.w;

        if (kv == 0) {
            int pos = m & (P_DIM - 1);
            int j   = (n & 63) >> 1;
            float c0 = __ldg(fcos + pos * 32 + j);
            float s0 = __ldg(fsin + pos * 32 + j);
            float c1 = __ldg(fcos + pos * 32 + j + 1);
            float s1 = __ldg(fsin + pos * 32 + j + 1);
            float4 r;
            r.x = s.x * c0 - s.y * s0;
            r.y = s.x * s0 + s.y * c0;
            r.z = s.z * c1 - s.w * s1;
            r.w = s.z * s1 + s.w * c1;
            ((float4*)g_K)[rem] = r;
        } else {
            ((float4*)g_V)[rem] = s;
        }
    }
}

// ---------------------------------------------------------------------------
// K_proj / V_proj (tril): grid (BH, 8).  fp16 outputs.
// ---------------------------------------------------------------------------
__global__ void __launch_bounds__(256)
proj_kernel(const float* __restrict__ kpm, const float* __restrict__ vpm)
{
    __shared__ float Ts[128][9];
    const int bh = blockIdx.x;
    const int b  = bh >> 4;
    const int hh = bh & 15;
    const int d0 = blockIdx.y * 8;
    const int tid = threadIdx.x;

    for (int idx = tid; idx < 128 * 8; idx += 256) {
        int l = idx >> 3, d = idx & 7;
        Ts[l][d] = g_K[(size_t)(b * 128 + l) * 1024 + hh * 64 + d0 + d];
    }
    __syncthreads();
#pragma unroll
    for (int t = 0; t < 4; t++) {
        int o = tid + t * 256;
        int p = o >> 3, d = o & 7;
        const float* pr = kpm + (size_t)p * 4096;
        float s = 0.f;
        for (int l = 0; l <= p; l++) s = fmaf(pr[l], Ts[l][d], s);
        g_kp[(size_t)bh * 8192 + p * 64 + (d0 + d)] = __float2half_rn(s);
    }
    __syncthreads();
    for (int idx = tid; idx < 128 * 8; idx += 256) {
        int l = idx >> 3, d = idx & 7;
        Ts[l][d] = g_V[(size_t)(b * 128 + l) * 1024 + hh * 64 + d0 + d];
    }
    __syncthreads();
#pragma unroll
    for (int t = 0; t < 4; t++) {
        int o = tid + t * 256;
        int p = o >> 3, d = o & 7;
        const float* pr = vpm + (size_t)p * 4096;
        float s = 0.f;
        for (int l = 0; l <= p; l++) s = fmaf(pr[l], Ts[l][d], s);
        g_vt[(size_t)bh * 8192 + (d0 + d) * 128 + p] = __float2half_rn(s);
    }
}

// ---------------------------------------------------------------------------
// Flash-style mma attention, single fp16 everywhere.
// smem: Q[128][144B], K[128][144B], VT[64][272B] = 54272 B
// ---------------------------------------------------------------------------
#define AT_Q  0
#define AT_K  18432
#define AT_VT 36864
#define ATTN_SMEM 54272

__global__ void __launch_bounds__(256)
attn_kernel()
{
    extern __shared__ char smem[];
    const int bh = blockIdx.y;
    const int b  = bh >> 4;
    const int hh = bh & 15;
    const int l0 = blockIdx.x * 128;
    const int tid  = threadIdx.x;
    const int wp   = tid >> 5;
    const int lane = tid & 31;
    const int lr   = lane & 15;
    const int lh   = lane >> 4;
    const int qrow = lane >> 2;
    const int qcol = (lane & 3) * 2;

    const size_t qbase = (size_t)(b * L_SEQ + l0) * 1024 + hh * 64;
#pragma unroll
    for (int t = 0; t < 4; t++) {
        int i = tid + t * 256;
        int r = i >> 3, c = i & 7;
        cpa16(sptr(smem + AT_Q + r * 144 + c * 16), g_q  + qbase + (size_t)r * 1024 + c * 8);
        cpa16(sptr(smem + AT_K + r * 144 + c * 16), g_kp + (size_t)bh * 8192 + r * 64 + c * 8);
        int rv = i >> 4, cv = i & 15;
        cpa16(sptr(smem + AT_VT + rv * 272 + cv * 16), g_vt + (size_t)bh * 8192 + rv * 128 + cv * 8);
    }
    asm volatile("cp.async.commit_group;" ::: "memory");
    asm volatile("cp.async.wait_group 0;" ::: "memory");
    __syncthreads();

    float acc[16][4];
#pragma unroll
    for (int i = 0; i < 16; i++)
#pragma unroll
        for (int q = 0; q < 4; q++) acc[i][q] = 0.f;

#pragma unroll
    for (int ks = 0; ks < 4; ks++) {
        uint32_t aq[4];
        ldm4(aq, sptr(smem + AT_Q + (wp * 16 + lr) * 144 + ks * 32 + lh * 16));
#pragma unroll
        for (int g = 0; g < 8; g++) {
            uint32_t bk[4];
            ldm4(bk, sptr(smem + AT_K + (g * 16 + lr) * 144 + ks * 32 + lh * 16));
            mma_f16(acc[2*g],   aq, bk[0], bk[2]);
            mma_f16(acc[2*g+1], aq, bk[1], bk[3]);
        }
    }

#pragma unroll
    for (int i = 0; i < 16; i++)
#pragma unroll
        for (int q = 0; q < 4; q++) acc[i][q] *= 0.125f;

    if (blockIdx.x == 0) {
        const int r0 = wp * 16 + qrow;
        const int r1 = r0 + 8;
#pragma unroll
        for (int nf = 0; nf < 16; nf++) {
            int p0 = nf * 8 + qcol;
            if (p0 > r0)     acc[nf][0] = -1e30f;
            if (p0 + 1 > r0) acc[nf][1] = -1e30f;
            if (p0 > r1)     acc[nf][2] = -1e30f;
            if (p0 + 1 > r1) acc[nf][3] = -1e30f;
        }
    }

    float mx0 = -1e30f, mx1 = -1e30f;
#pragma unroll
    for (int nf = 0; nf < 16; nf++) {
        mx0 = fmaxf(mx0, fmaxf(acc[nf][0], acc[nf][1]));
        mx1 = fmaxf(mx1, fmaxf(acc[nf][2], acc[nf][3]));
    }
    mx0 = fmaxf(mx0, __shfl_xor_sync(0xffffffffu, mx0, 1));
    mx0 = fmaxf(mx0, __shfl_xor_sync(0xffffffffu, mx0, 2));
    mx1 = fmaxf(mx1, __shfl_xor_sync(0xffffffffu, mx1, 1));
    mx1 = fmaxf(mx1, __shfl_xor_sync(0xffffffffu, mx1, 2));

    float s0 = 0.f, s1 = 0.f;
#pragma unroll
    for (int nf = 0; nf < 16; nf++) {
        acc[nf][0] = __expf(acc[nf][0] - mx0);
        acc[nf][1] = __expf(acc[nf][1] - mx0);
        acc[nf][2] = __expf(acc[nf][2] - mx1);
        acc[nf][3] = __expf(acc[nf][3] - mx1);
        s0 += acc[nf][0] + acc[nf][1];
        s1 += acc[nf][2] + acc[nf][3];
    }
    s0 += __shfl_xor_sync(0xffffffffu, s0, 1);
    s0 += __shfl_xor_sync(0xffffffffu, s0, 2);
    s1 += __shfl_xor_sync(0xffffffffu, s1, 1);
    s1 += __shfl_xor_sync(0xffffffffu, s1, 2);
    const float inv0 = 1.0f / s0;
    const float inv1 = 1.0f / s1;

    float o[8][4];
#pragma unroll
    for (int i = 0; i < 8; i++)
#pragma unroll
        for (int q = 0; q < 4; q++) o[i][q] = 0.f;

#pragma unroll
    for (int kc = 0; kc < 8; kc++) {
        // repack softmax weights as fp16 (C-layout == A-layout)
        uint32_t aw[4];
        aw[0] = pack2h(acc[2*kc][0],   acc[2*kc][1]);
        aw[1] = pack2h(acc[2*kc][2],   acc[2*kc][3]);
        aw[2] = pack2h(acc[2*kc+1][0], acc[2*kc+1][1]);
        aw[3] = pack2h(acc[2*kc+1][2], acc[2*kc+1][3]);
#pragma unroll
        for (int g = 0; g < 4; g++) {
            uint32_t bv[4];
            ldm4(bv, sptr(smem + AT_VT + (g * 16 + lr) * 272 + kc * 32 + lh * 16));
            mma_f16(o[2*g],   aw, bv[0], bv[2]);
            mma_f16(o[2*g+1], aw, bv[1], bv[3]);
        }
    }

    const size_t row0 = (size_t)(b * L_SEQ + l0 + wp * 16 + qrow);
    const size_t row1 = row0 + 8;
#pragma unroll
    for (int nf = 0; nf < 8; nf++) {
        int col = hh * 64 + nf * 8 + qcol;
        *(uint32_t*)(g_a + row0 * 1024 + col) = pack2h(o[nf][0] * inv0, o[nf][1] * inv0);
        *(uint32_t*)(g_a + row1 * 1024 + col) = pack2h(o[nf][2] * inv1, o[nf][3] * inv1);
    }
}

// ---------------------------------------------------------------------------
extern "C" void kernel_launch(void* const* d_in, const int* in_sizes, int n_in,
                              void* d_out, int out_size)
{
    const float* x    = (const float*)d_in[0];
    const float* fcos = (const float*)d_in[1];
    const float* fsin = (const float*)d_in[2];
    const float* Wq   = (const float*)d_in[3];
    const float* Wk   = (const float*)d_in[4];
    const float* Wv   = (const float*)d_in[5];
    const float* Wo   = (const float*)d_in[6];
    const float* kpm  = (const float*)d_in[7];
    const float* vpm  = (const float*)d_in[8];
    float* out = (float*)d_out;

    cudaFuncSetAttribute(attn_kernel,
                         cudaFuncAttributeMaxDynamicSharedMemorySize, ATTN_SMEM);
    cudaFuncSetAttribute(gemm_f16<1,0,0,0,0>, cudaFuncAttributeMaxDynamicSharedMemorySize, SM_GEMM);
    cudaFuncSetAttribute(gemm_kv_part,        cudaFuncAttributeMaxDynamicSharedMemorySize, SM_GEMM);
    cudaFuncSetAttribute(gemm_f16<0,0,1,3,3>, cudaFuncAttributeMaxDynamicSharedMemorySize, SM_GEMM);

    dim3 blk(256);
    // fp32 -> fp16 converts
    convert_x <<<4096, blk>>>(x, (size_t)M_FULL * D_MODEL / 4);
    convert_w4<<<2048, blk>>>(Wq, Wk, Wv, Wo);

    // K/V split-K partial GEMMs + reduce w/ RoPE(K)
    gemm_kv_part<<<dim3(8, 4, 8), blk, SM_GEMM>>>();
    reduce_kv<<<512, blk>>>(fcos, fsin);

    // Q = rope(x @ Wq^T) -> fp16
    gemm_f16<1,0,0,0,0><<<dim3(8, 128), blk, SM_GEMM>>>(fcos, fsin, nullptr, L_SEQ - 1);

    // Linformer tril projections -> fp16
    proj_kernel<<<dim3(BH, 8), blk>>>(kpm, vpm);
    // flash-style mma attention
    attn_kernel<<<dim3(L_SEQ / 128, BH), blk, ATTN_SMEM>>>();
    // out = attn @ Wo^T
    gemm_f16<0,0,1,3,3><<<dim3(8, 128), blk, SM_GEMM>>>(nullptr, nullptr, out, 0);
}

// round 15
// speedup vs baseline: 3.3092x; 1.0217x over previous
#include <cuda_runtime.h>
#include <cuda_fp16.h>
#include <math.h>
#include <stdint.h>

#define L_SEQ   4096
#define D_MODEL 1024
#define N_HEADS 16
#define HEAD_DIM 64
#define P_DIM   128
#define B_SIZE  4
#define M_FULL  (B_SIZE * L_SEQ)   // 16384
#define M_KV    (B_SIZE * P_DIM)   // 512
#define BH      (B_SIZE * N_HEADS) // 64
#define KSLICE  ((size_t)M_KV * D_MODEL)

// ---------------- scratch (static device arrays) ---------------------------
__device__ __half g_x [(size_t)M_FULL * D_MODEL];
__device__ __half g_w [4 * (size_t)D_MODEL * D_MODEL];
__device__ __half g_a [(size_t)M_FULL * D_MODEL];
__device__ __half g_q [(size_t)M_FULL * D_MODEL];

__device__ float g_kvpart[8 * KSLICE];   // [kv*4+ks][m][n]

__device__ __half g_kp[BH * P_DIM * HEAD_DIM];   // K_proj [bh][p][d]
__device__ __half g_vt[BH * HEAD_DIM * P_DIM];   // V_proj^T [bh][d][p]

// ---------------------------------------------------------------------------
// fp32 -> fp16 convert: x (4M float4) + 4 weights (1M float4), one launch.
// ---------------------------------------------------------------------------
__global__ void __launch_bounds__(256)
convert_all(const float* __restrict__ x,
            const float* __restrict__ w0, const float* __restrict__ w1,
            const float* __restrict__ w2, const float* __restrict__ w3)
{
    const size_t nx = (size_t)M_FULL * D_MODEL / 4;            // 4194304
    const size_t pw = (size_t)D_MODEL * D_MODEL / 4;           // 262144
    const size_t total = nx + 4 * pw;
    const float* ws[4] = {w0, w1, w2, w3};
    for (size_t i = blockIdx.x * (size_t)blockDim.x + threadIdx.x; i < total;
         i += (size_t)gridDim.x * blockDim.x) {
        float4 v;
        uint2* dst;
        if (i < nx) {
            v = ((const float4*)x)[i];
            dst = (uint2*)g_x + i;
        } else {
            size_t j = i - nx;
            int slot = (int)(j / pw);
            v = ((const float4*)ws[slot])[j - (size_t)slot * pw];
            dst = (uint2*)g_w + j;
        }
        union { __half b[4]; uint2 u; } h;
        h.b[0] = __float2half_rn(v.x); h.b[1] = __float2half_rn(v.y);
        h.b[2] = __float2half_rn(v.z); h.b[3] = __float2half_rn(v.w);
        *dst = h.u;
    }
}

// ---------------------------------------------------------------------------
// mma.sync helpers
// ---------------------------------------------------------------------------
__device__ __forceinline__ uint32_t sptr(const void* p) {
    return (uint32_t)__cvta_generic_to_shared(p);
}
__device__ __forceinline__ void ldm4(uint32_t* r, uint32_t a) {
    asm volatile("ldmatrix.sync.aligned.m8n8.x4.shared.b16 {%0,%1,%2,%3}, [%4];"
                 : "=r"(r[0]), "=r"(r[1]), "=r"(r[2]), "=r"(r[3]) : "r"(a));
}
__device__ __forceinline__ void mma_f16(float* c, const uint32_t* a, uint32_t b0, uint32_t b1) {
    asm volatile(
        "mma.sync.aligned.m16n8k16.row.col.f32.f16.f16.f32 "
        "{%0,%1,%2,%3}, {%4,%5,%6,%7}, {%8,%9}, {%0,%1,%2,%3};"
        : "+f"(c[0]), "+f"(c[1]), "+f"(c[2]), "+f"(c[3])
        : "r"(a[0]), "r"(a[1]), "r"(a[2]), "r"(a[3]), "r"(b0), "r"(b1));
}
__device__ __forceinline__ void cpa16(uint32_t s, const void* g) {
    asm volatile("cp.async.ca.shared.global [%0], [%1], 16;" :: "r"(s), "l"(g));
}
__device__ __forceinline__ void cpa16cg(uint32_t s, const void* g) {
    asm volatile("cp.async.cg.shared.global [%0], [%1], 16;" :: "r"(s), "l"(g));
}
__device__ __forceinline__ uint32_t pack2h(float x, float y) {
    union { __half2 v; uint32_t u; } H;
    H.v = __halves2half2(__float2half_rn(x), __float2half_rn(y));
    return H.u;
}

// ---------------------------------------------------------------------------
// GEMM tile constants: stage = {A, B} x 8192 B; 4 stages = 65536 B.
// ---------------------------------------------------------------------------
#define MAT_BYTES 8192
#define STG_BYTES (2 * MAT_BYTES)
#define N_STAGE   4
#define SM_GEMM   (N_STAGE * STG_BYTES)   // 65536 -> 2 CTAs/SM

__device__ __forceinline__ uint32_t swzoff(int row, int c16) {
    return (uint32_t)(row * 64 + ((c16 ^ ((row >> 1) & 3)) << 4));
}

__device__ __forceinline__ void mma_pass1(
    float acc[2][8][4], uint32_t A[2][4], uint32_t B[4][4])
{
#pragma unroll
    for (int g = 0; g < 4; g++)
#pragma unroll
        for (int mf = 0; mf < 2; mf++) {
            mma_f16(acc[mf][2*g],   A[mf], B[g][0], B[g][2]);
            mma_f16(acc[mf][2*g+1], A[mf], B[g][1], B[g][3]);
        }
}

// Shared GEMM mainloop body: runtime-parameterized (uniform per CTA).
// acc += A[rows(m_tile..+128)][kbase..+nch*32] . B[n_tile..+128][...]^T
__device__ __forceinline__ void gemm_mainloop(
    char* sbuf, float acc[2][8][4],
    const __half* A, const __half* Bw,
    int m_tile, int n_tile, int kbase, int nch, int gather,
    int tid, int wm, int wn, int lr, int lh)
{
    auto load_chunk = [&](int st, int k0) {
#pragma unroll
        for (int t = 0; t < 4; t++) {
            int idx = tid + t * 256;
            int mtx = idx >> 9;               // 0=A 1=B
            int rem = idx & 511;
            int row = rem >> 2;
            int c16 = rem & 3;
            int grow;
            if (mtx == 0) {
                int m = m_tile + row;
                grow = gather ? ((m >> 7) * L_SEQ + (m & 127)) : m;
            } else {
                grow = n_tile + row;
            }
            const __half* src = (mtx == 0) ? A : Bw;
            cpa16cg(sptr(sbuf + st * STG_BYTES + mtx * MAT_BYTES + swzoff(row, c16)),
                    src + (size_t)grow * 1024 + k0 + c16 * 8);
        }
    };

    load_chunk(0, kbase);
    asm volatile("cp.async.commit_group;" ::: "memory");
    load_chunk(1, kbase + 32);
    asm volatile("cp.async.commit_group;" ::: "memory");
    load_chunk(2, kbase + 64);
    asm volatile("cp.async.commit_group;" ::: "memory");

    for (int i = 0; i < nch; i++) {
        if (i < nch - 2)       asm volatile("cp.async.wait_group 2;" ::: "memory");
        else if (i == nch - 2) asm volatile("cp.async.wait_group 1;" ::: "memory");
        else                   asm volatile("cp.async.wait_group 0;" ::: "memory");
        __syncthreads();
        if (i + 3 < nch) {
            load_chunk((i + 3) & 3, kbase + (i + 3) * 32);
            asm volatile("cp.async.commit_group;" ::: "memory");
        }

        const char* stg = sbuf + (i & 3) * STG_BYTES;

#pragma unroll
        for (int ks = 0; ks < 2; ks++) {
            const int cb = ks * 2 + lh;
            uint32_t af[2][4];
#pragma unroll
            for (int mf = 0; mf < 2; mf++) {
                int row = wm * 32 + mf * 16 + lr;
                ldm4(af[mf], sptr(stg + 0 * MAT_BYTES + swzoff(row, cb)));
            }
            uint32_t bf[4][4];
#pragma unroll
            for (int g = 0; g < 4; g++) {
                int row = wn * 64 + g * 16 + lr;
                ldm4(bf[g], sptr(stg + 1 * MAT_BYTES + swzoff(row, cb)));
            }
            mma_pass1(acc, af, bf);
        }
    }
}

// ---------------------------------------------------------------------------
// Fused Q-GEMM + split-K KV partial GEMM.  Grid (8, 160):
//   y <  128: Q tile (x, y): Q = rope(x @ Wq^T) -> g_q fp16
//   y >= 128: kv CTA idx = (y-128)*8 + x in [0,256):
//             z = idx>>5 (kv*4+ks), m_t = (idx>>3)&3, n_t = idx&7
//             partial (x[gather] @ W_{k/v}^T over k-slice) -> g_kvpart fp32
// ---------------------------------------------------------------------------
__global__ void __launch_bounds__(256, 2)
gemm_q_kv(const float* __restrict__ fcos, const float* __restrict__ fsin)
{
    extern __shared__ char sbuf[];

    const int tid  = threadIdx.x;
    const int warp = tid >> 5;
    const int lane = tid & 31;
    const int wm   = warp & 3;
    const int wn   = warp >> 2;
    const int lr = lane & 15;
    const int lh = lane >> 4;

    float acc[2][8][4];
#pragma unroll
    for (int i = 0; i < 2; i++)
#pragma unroll
        for (int j = 0; j < 8; j++)
#pragma unroll
            for (int q = 0; q < 4; q++) acc[i][j][q] = 0.f;

    const int qpath = (blockIdx.y < 128);
    int m_tile, n_tile, kbase, nch, gather, z = 0;
    const __half* Bw;
    if (qpath) {
        m_tile = blockIdx.y * 128;
        n_tile = blockIdx.x * 128;
        kbase = 0; nch = 32; gather = 0;
        Bw = g_w;                                        // Wq
    } else {
        int idx = (blockIdx.y - 128) * 8 + blockIdx.x;   // 0..255
        z = idx >> 5;                                    // kv*4+ks
        int kv = z >> 2, ks = z & 3;
        m_tile = ((idx >> 3) & 3) * 128;
        n_tile = (idx & 7) * 128;
        kbase = ks * 256; nch = 8; gather = 1;
        Bw = g_w + (size_t)(1 + kv) * D_MODEL * D_MODEL;
    }

    gemm_mainloop(sbuf, acc, g_x, Bw, m_tile, n_tile, kbase, nch, gather,
                  tid, wm, wn, lr, lh);

    const int qrow = lane >> 2;
    const int qcol = (lane & 3) * 2;
    if (qpath) {
#pragma unroll
        for (int mf = 0; mf < 2; mf++)
#pragma unroll
            for (int nf = 0; nf < 8; nf++) {
                int n = n_tile + wn * 64 + nf * 8 + qcol;
#pragma unroll
                for (int hhalf = 0; hhalf < 2; hhalf++) {
                    int m = m_tile + wm * 32 + mf * 16 + qrow + hhalf * 8;
                    float v0 = acc[mf][nf][hhalf * 2];
                    float v1 = acc[mf][nf][hhalf * 2 + 1];
                    int pos = m & (L_SEQ - 1);
                    int j   = (n & 63) >> 1;
                    float c = __ldg(fcos + pos * 32 + j);
                    float s = __ldg(fsin + pos * 32 + j);
                    float o0 = v0 * c - v1 * s;
                    float o1 = v0 * s + v1 * c;
                    *(uint32_t*)(g_q + (size_t)m * 1024 + n) = pack2h(o0, o1);
                }
            }
    } else {
        float* P = g_kvpart + (size_t)z * KSLICE;
#pragma unroll
        for (int mf = 0; mf < 2; mf++)
#pragma unroll
            for (int nf = 0; nf < 8; nf++) {
                int n = n_tile + wn * 64 + nf * 8 + qcol;
#pragma unroll
                for (int hhalf = 0; hhalf < 2; hhalf++) {
                    int m = m_tile + wm * 32 + mf * 16 + qrow + hhalf * 8;
                    *(float2*)(P + (size_t)m * 1024 + n) =
                        make_float2(acc[mf][nf][hhalf * 2], acc[mf][nf][hhalf * 2 + 1]);
                }
            }
    }
}

// ---------------------------------------------------------------------------
// Standalone Wo GEMM: out = attn @ Wo^T (fp32 out).  Grid (8, 128).
// ---------------------------------------------------------------------------
__global__ void __launch_bounds__(256, 2)
gemm_wo(float* __restrict__ C)
{
    extern __shared__ char sbuf[];

    const int tid  = threadIdx.x;
    const int warp = tid >> 5;
    const int lane = tid & 31;
    const int wm   = warp & 3;
    const int wn   = warp >> 2;
    const int lr = lane & 15;
    const int lh = lane >> 4;
    const int m_tile = blockIdx.y * 128;
    const int n_tile = blockIdx.x * 128;

    float acc[2][8][4];
#pragma unroll
    for (int i = 0; i < 2; i++)
#pragma unroll
        for (int j = 0; j < 8; j++)
#pragma unroll
            for (int q = 0; q < 4; q++) acc[i][j][q] = 0.f;

    gemm_mainloop(sbuf, acc, g_a, g_w + (size_t)3 * D_MODEL * D_MODEL,
                  m_tile, n_tile, 0, 32, 0, tid, wm, wn, lr, lh);

    const int qrow = lane >> 2;
    const int qcol = (lane & 3) * 2;
#pragma unroll
    for (int mf = 0; mf < 2; mf++)
#pragma unroll
        for (int nf = 0; nf < 8; nf++) {
            int n = n_tile + wn * 64 + nf * 8 + qcol;
#pragma unroll
            for (int hhalf = 0; hhalf < 2; hhalf++) {
                int m = m_tile + wm * 32 + mf * 16 + qrow + hhalf * 8;
                *(float2*)(C + (size_t)m * 1024 + n) =
                    make_float2(acc[mf][nf][hhalf * 2], acc[mf][nf][hhalf * 2 + 1]);
            }
        }
}

// ---------------------------------------------------------------------------
// K_proj / V_proj with inline 4-partial reduce + RoPE(K).  Grid (BH, 8).
// Same summation/RoPE order as the old reduce_kv + proj pair.
// ---------------------------------------------------------------------------
__global__ void __launch_bounds__(256)
proj_kernel(const float* __restrict__ kpm, const float* __restrict__ vpm,
            const float* __restrict__ fcos, const float* __restrict__ fsin)
{
    __shared__ float Ts[128][9];
    const int bh = blockIdx.x;
    const int b  = bh >> 4;
    const int hh = bh & 15;
    const int d0 = blockIdx.y * 8;
    const int tid = threadIdx.x;

    // ---- K: sum 4 k-split partials, RoPE pairs ----
    for (int idx = tid; idx < 128 * 4; idx += 256) {
        int l = idx >> 2, dp = (idx & 3) * 2;
        size_t rem = (size_t)(b * 128 + l) * 1024 + hh * 64 + d0 + dp;
        float2 s  = *(const float2*)(g_kvpart + rem);
        float2 p1 = *(const float2*)(g_kvpart + KSLICE + rem);
        float2 p2 = *(const float2*)(g_kvpart + 2 * KSLICE + rem);
        float2 p3 = *(const float2*)(g_kvpart + 3 * KSLICE + rem);
        s.x += p1.x; s.y += p1.y;
        s.x += p2.x; s.y += p2.y;
        s.x += p3.x; s.y += p3.y;
        int j = (d0 + dp) >> 1;
        float c0 = __ldg(fcos + l * 32 + j);
        float s0 = __ldg(fsin + l * 32 + j);
        Ts[l][dp]     = s.x * c0 - s.y * s0;
        Ts[l][dp + 1] = s.x * s0 + s.y * c0;
    }
    __syncthreads();
#pragma unroll
    for (int t = 0; t < 4; t++) {
        int o = tid + t * 256;
        int p = o >> 3, d = o & 7;
        const float* pr = kpm + (size_t)p * 4096;
        float s = 0.f;
        for (int l = 0; l <= p; l++) s = fmaf(pr[l], Ts[l][d], s);
        g_kp[(size_t)bh * 8192 + p * 64 + (d0 + d)] = __float2half_rn(s);
    }
    __syncthreads();

    // ---- V: sum 4 partials ----
    for (int idx = tid; idx < 128 * 8; idx += 256) {
        int l = idx >> 3, d = idx & 7;
        size_t rem = (size_t)(b * 128 + l) * 1024 + hh * 64 + d0 + d;
        float s = g_kvpart[4 * KSLICE + rem];
        s += g_kvpart[5 * KSLICE + rem];
        s += g_kvpart[6 * KSLICE + rem];
        s += g_kvpart[7 * KSLICE + rem];
        Ts[l][d] = s;
    }
    __syncthreads();
#pragma unroll
    for (int t = 0; t < 4; t++) {
        int o = tid + t * 256;
        int p = o >> 3, d = o & 7;
        const float* pr = vpm + (size_t)p * 4096;
        float s = 0.f;
        for (int l = 0; l <= p; l++) s = fmaf(pr[l], Ts[l][d], s);
        g_vt[(size_t)bh * 8192 + (d0 + d) * 128 + p] = __float2half_rn(s);
    }
}

// ---------------------------------------------------------------------------
// Flash-style mma attention (unchanged from R14, passing).
// ---------------------------------------------------------------------------
#define AT_Q  0
#define AT_K  18432
#define AT_VT 36864
#define ATTN_SMEM 54272

__global__ void __launch_bounds__(256)
attn_kernel()
{
    extern __shared__ char smem[];
    const int bh = blockIdx.y;
    const int b  = bh >> 4;
    const int hh = bh & 15;
    const int l0 = blockIdx.x * 128;
    const int tid  = threadIdx.x;
    const int wp   = tid >> 5;
    const int lane = tid & 31;
    const int lr   = lane & 15;
    const int lh   = lane >> 4;
    const int qrow = lane >> 2;
    const int qcol = (lane & 3) * 2;

    const size_t qbase = (size_t)(b * L_SEQ + l0) * 1024 + hh * 64;
#pragma unroll
    for (int t = 0; t < 4; t++) {
        int i = tid + t * 256;
        int r = i >> 3, c = i & 7;
        cpa16(sptr(smem + AT_Q + r * 144 + c * 16), g_q  + qbase + (size_t)r * 1024 + c * 8);
        cpa16(sptr(smem + AT_K + r * 144 + c * 16), g_kp + (size_t)bh * 8192 + r * 64 + c * 8);
        int rv = i >> 4, cv = i & 15;
        cpa16(sptr(smem + AT_VT + rv * 272 + cv * 16), g_vt + (size_t)bh * 8192 + rv * 128 + cv * 8);
    }
    asm volatile("cp.async.commit_group;" ::: "memory");
    asm volatile("cp.async.wait_group 0;" ::: "memory");
    __syncthreads();

    float acc[16][4];
#pragma unroll
    for (int i = 0; i < 16; i++)
#pragma unroll
        for (int q = 0; q < 4; q++) acc[i][q] = 0.f;

#pragma unroll
    for (int ks = 0; ks < 4; ks++) {
        uint32_t aq[4];
        ldm4(aq, sptr(smem + AT_Q + (wp * 16 + lr) * 144 + ks * 32 + lh * 16));
#pragma unroll
        for (int g = 0; g < 8; g++) {
            uint32_t bk[4];
            ldm4(bk, sptr(smem + AT_K + (g * 16 + lr) * 144 + ks * 32 + lh * 16));
            mma_f16(acc[2*g],   aq, bk[0], bk[2]);
            mma_f16(acc[2*g+1], aq, bk[1], bk[3]);
        }
    }

#pragma unroll
    for (int i = 0; i < 16; i++)
#pragma unroll
        for (int q = 0; q < 4; q++) acc[i][q] *= 0.125f;

    if (blockIdx.x == 0) {
        const int r0 = wp * 16 + qrow;
        const int r1 = r0 + 8;
#pragma unroll
        for (int nf = 0; nf < 16; nf++) {
            int p0 = nf * 8 + qcol;
            if (p0 > r0)     acc[nf][0] = -1e30f;
            if (p0 + 1 > r0) acc[nf][1] = -1e30f;
            if (p0 > r1)     acc[nf][2] = -1e30f;
            if (p0 + 1 > r1) acc[nf][3] = -1e30f;
        }
    }

    float mx0 = -1e30f, mx1 = -1e30f;
#pragma unroll
    for (int nf = 0; nf < 16; nf++) {
        mx0 = fmaxf(mx0, fmaxf(acc[nf][0], acc[nf][1]));
        mx1 = fmaxf(mx1, fmaxf(acc[nf][2], acc[nf][3]));
    }
    mx0 = fmaxf(mx0, __shfl_xor_sync(0xffffffffu, mx0, 1));
    mx0 = fmaxf(mx0, __shfl_xor_sync(0xffffffffu, mx0, 2));
    mx1 = fmaxf(mx1, __shfl_xor_sync(0xffffffffu, mx1, 1));
    mx1 = fmaxf(mx1, __shfl_xor_sync(0xffffffffu, mx1, 2));

    float s0 = 0.f, s1 = 0.f;
#pragma unroll
    for (int nf = 0; nf < 16; nf++) {
        acc[nf][0] = __expf(acc[nf][0] - mx0);
        acc[nf][1] = __expf(acc[nf][1] - mx0);
        acc[nf][2] = __expf(acc[nf][2] - mx1);
        acc[nf][3] = __expf(acc[nf][3] - mx1);
        s0 += acc[nf][0] + acc[nf][1];
        s1 += acc[nf][2] + acc[nf][3];
    }
    s0 += __shfl_xor_sync(0xffffffffu, s0, 1);
    s0 += __shfl_xor_sync(0xffffffffu, s0, 2);
    s1 += __shfl_xor_sync(0xffffffffu, s1, 1);
    s1 += __shfl_xor_sync(0xffffffffu, s1, 2);
    const float inv0 = 1.0f / s0;
    const float inv1 = 1.0f / s1;

    float o[8][4];
#pragma unroll
    for (int i = 0; i < 8; i++)
#pragma unroll
        for (int q = 0; q < 4; q++) o[i][q] = 0.f;

#pragma unroll
    for (int kc = 0; kc < 8; kc++) {
        uint32_t aw[4];
        aw[0] = pack2h(acc[2*kc][0],   acc[2*kc][1]);
        aw[1] = pack2h(acc[2*kc][2],   acc[2*kc][3]);
        aw[2] = pack2h(acc[2*kc+1][0], acc[2*kc+1][1]);
        aw[3] = pack2h(acc[2*kc+1][2], acc[2*kc+1][3]);
#pragma unroll
        for (int g = 0; g < 4; g++) {
            uint32_t bv[4];
            ldm4(bv, sptr(smem + AT_VT + (g * 16 + lr) * 272 + kc * 32 + lh * 16));
            mma_f16(o[2*g],   aw, bv[0], bv[2]);
            mma_f16(o[2*g+1], aw, bv[1], bv[3]);
        }
    }

    const size_t row0 = (size_t)(b * L_SEQ + l0 + wp * 16 + qrow);
    const size_t row1 = row0 + 8;
#pragma unroll
    for (int nf = 0; nf < 8; nf++) {
        int col = hh * 64 + nf * 8 + qcol;
        *(uint32_t*)(g_a + row0 * 1024 + col) = pack2h(o[nf][0] * inv0, o[nf][1] * inv0);
        *(uint32_t*)(g_a + row1 * 1024 + col) = pack2h(o[nf][2] * inv1, o[nf][3] * inv1);
    }
}

// ---------------------------------------------------------------------------
extern "C" void kernel_launch(void* const* d_in, const int* in_sizes, int n_in,
                              void* d_out, int out_size)
{
    const float* x    = (const float*)d_in[0];
    const float* fcos = (const float*)d_in[1];
    const float* fsin = (const float*)d_in[2];
    const float* Wq   = (const float*)d_in[3];
    const float* Wk   = (const float*)d_in[4];
    const float* Wv   = (const float*)d_in[5];
    const float* Wo   = (const float*)d_in[6];
    const float* kpm  = (const float*)d_in[7];
    const float* vpm  = (const float*)d_in[8];
    float* out = (float*)d_out;

    cudaFuncSetAttribute(attn_kernel,
                         cudaFuncAttributeMaxDynamicSharedMemorySize, ATTN_SMEM);
    cudaFuncSetAttribute(gemm_q_kv,
                         cudaFuncAttributeMaxDynamicSharedMemorySize, SM_GEMM);
    cudaFuncSetAttribute(gemm_wo,
                         cudaFuncAttributeMaxDynamicSharedMemorySize, SM_GEMM);

    dim3 blk(256);
    // fp32 -> fp16 converts (one launch)
    convert_all<<<4096, blk>>>(x, Wq, Wk, Wv, Wo);

    // fused: Q = rope(x @ Wq^T)  +  split-K KV partials (tail-filled)
    gemm_q_kv<<<dim3(8, 160), blk, SM_GEMM>>>(fcos, fsin);

    // Linformer tril projections (inline 4-partial reduce + RoPE(K))
    proj_kernel<<<dim3(BH, 8), blk>>>(kpm, vpm, fcos, fsin);

    // flash-style mma attention
    attn_kernel<<<dim3(L_SEQ / 128, BH), blk, ATTN_SMEM>>>();

    // out = attn @ Wo^T
    gemm_wo<<<dim3(8, 128), blk, SM_GEMM>>>(out);
}

// round 16
// speedup vs baseline: 3.5608x; 1.0760x over previous
#include <cuda_runtime.h>
#include <cuda_fp16.h>
#include <math.h>
#include <stdint.h>

#define L_SEQ   4096
#define D_MODEL 1024
#define N_HEADS 16
#define HEAD_DIM 64
#define P_DIM   128
#define B_SIZE  4
#define M_FULL  (B_SIZE * L_SEQ)   // 16384
#define M_KV    (B_SIZE * P_DIM)   // 512
#define BH      (B_SIZE * N_HEADS) // 64
#define KSLICE  ((size_t)M_KV * D_MODEL)

// ---------------- scratch (static device arrays) ---------------------------
__device__ __half g_x [(size_t)M_FULL * D_MODEL];
__device__ __half g_w [4 * (size_t)D_MODEL * D_MODEL];
__device__ __half g_a [(size_t)M_FULL * D_MODEL];
__device__ __half g_q [(size_t)M_FULL * D_MODEL];

__device__ float g_kvpart[8 * KSLICE];   // [kv*4+ks][m][n]

__device__ __half g_kp[BH * P_DIM * HEAD_DIM];   // K_proj [bh][p][d]
__device__ __half g_vt[BH * HEAD_DIM * P_DIM];   // V_proj^T [bh][d][p]

// ---------------------------------------------------------------------------
// fp32 -> fp16 convert: x + 4 weights in one launch.
// ---------------------------------------------------------------------------
__global__ void __launch_bounds__(256)
convert_all(const float* __restrict__ x,
            const float* __restrict__ w0, const float* __restrict__ w1,
            const float* __restrict__ w2, const float* __restrict__ w3)
{
    const size_t nx = (size_t)M_FULL * D_MODEL / 4;
    const size_t pw = (size_t)D_MODEL * D_MODEL / 4;
    const size_t total = nx + 4 * pw;
    const float* ws[4] = {w0, w1, w2, w3};
    for (size_t i = blockIdx.x * (size_t)blockDim.x + threadIdx.x; i < total;
         i += (size_t)gridDim.x * blockDim.x) {
        float4 v;
        uint2* dst;
        if (i < nx) {
            v = ((const float4*)x)[i];
            dst = (uint2*)g_x + i;
        } else {
            size_t j = i - nx;
            int slot = (int)(j / pw);
            v = ((const float4*)ws[slot])[j - (size_t)slot * pw];
            dst = (uint2*)g_w + j;
        }
        union { __half b[4]; uint2 u; } h;
        h.b[0] = __float2half_rn(v.x); h.b[1] = __float2half_rn(v.y);
        h.b[2] = __float2half_rn(v.z); h.b[3] = __float2half_rn(v.w);
        *dst = h.u;
    }
}

// ---------------------------------------------------------------------------
// mma.sync helpers
// ---------------------------------------------------------------------------
__device__ __forceinline__ uint32_t sptr(const void* p) {
    return (uint32_t)__cvta_generic_to_shared(p);
}
__device__ __forceinline__ void ldm4(uint32_t* r, uint32_t a) {
    asm volatile("ldmatrix.sync.aligned.m8n8.x4.shared.b16 {%0,%1,%2,%3}, [%4];"
                 : "=r"(r[0]), "=r"(r[1]), "=r"(r[2]), "=r"(r[3]) : "r"(a));
}
__device__ __forceinline__ void mma_f16(float* c, const uint32_t* a, uint32_t b0, uint32_t b1) {
    asm volatile(
        "mma.sync.aligned.m16n8k16.row.col.f32.f16.f16.f32 "
        "{%0,%1,%2,%3}, {%4,%5,%6,%7}, {%8,%9}, {%0,%1,%2,%3};"
        : "+f"(c[0]), "+f"(c[1]), "+f"(c[2]), "+f"(c[3])
        : "r"(a[0]), "r"(a[1]), "r"(a[2]), "r"(a[3]), "r"(b0), "r"(b1));
}
__device__ __forceinline__ void cpa16(uint32_t s, const void* g) {
    asm volatile("cp.async.ca.shared.global [%0], [%1], 16;" :: "r"(s), "l"(g));
}
__device__ __forceinline__ void cpa16cg(uint32_t s, const void* g) {
    asm volatile("cp.async.cg.shared.global [%0], [%1], 16;" :: "r"(s), "l"(g));
}
__device__ __forceinline__ uint32_t pack2h(float x, float y) {
    union { __half2 v; uint32_t u; } H;
    H.v = __halves2half2(__float2half_rn(x), __float2half_rn(y));
    return H.u;
}

// ---------------------------------------------------------------------------
// GEMM tile constants: BK=64, stage = {A, B} x 16384 B; 3 stages = 98304 B.
// 128B rows, XOR swizzle c16 ^ (row & 7): conflict-free cp.async stores and
// 8-row ldmatrix phases.
// ---------------------------------------------------------------------------
#define MAT_BYTES 16384
#define STG_BYTES (2 * MAT_BYTES)
#define N_STAGE   3
#define SM_GEMM   (N_STAGE * STG_BYTES)   // 98304 -> 2 CTAs/SM

__device__ __forceinline__ uint32_t swz128(int row, int c16) {
    return (uint32_t)(row * 128 + ((c16 ^ (row & 7)) << 4));
}

__device__ __forceinline__ void mma_pass1(
    float acc[2][8][4], uint32_t A[2][4], uint32_t B[4][4])
{
#pragma unroll
    for (int g = 0; g < 4; g++)
#pragma unroll
        for (int mf = 0; mf < 2; mf++) {
            mma_f16(acc[mf][2*g],   A[mf], B[g][0], B[g][2]);
            mma_f16(acc[mf][2*g+1], A[mf], B[g][1], B[g][3]);
        }
}

// Shared GEMM mainloop: BK=64 chunks.  nch = number of 64-wide chunks.
__device__ __forceinline__ void gemm_mainloop(
    char* sbuf, float acc[2][8][4],
    const __half* A, const __half* Bw,
    int m_tile, int n_tile, int kbase, int nch, int gather,
    int tid, int wm, int wn, int lr, int lh)
{
    // per chunk: 2 mats x 128 rows x 8 c16 = 2048 copies; 8/thread
    auto load_chunk = [&](int st, int k0) {
#pragma unroll
        for (int t = 0; t < 8; t++) {
            int idx = tid + t * 256;
            int mtx = idx >> 10;              // 0=A 1=B
            int rem = idx & 1023;
            int row = rem >> 3;
            int c16 = rem & 7;
            int grow;
            if (mtx == 0) {
                int m = m_tile + row;
                grow = gather ? ((m >> 7) * L_SEQ + (m & 127)) : m;
            } else {
                grow = n_tile + row;
            }
            const __half* src = (mtx == 0) ? A : Bw;
            cpa16cg(sptr(sbuf + st * STG_BYTES + mtx * MAT_BYTES + swz128(row, c16)),
                    src + (size_t)grow * 1024 + k0 + c16 * 8);
        }
    };

    load_chunk(0, kbase);
    asm volatile("cp.async.commit_group;" ::: "memory");
    load_chunk(1, kbase + 64);
    asm volatile("cp.async.commit_group;" ::: "memory");

    for (int i = 0; i < nch; i++) {
        if (i < nch - 1) asm volatile("cp.async.wait_group 1;" ::: "memory");
        else             asm volatile("cp.async.wait_group 0;" ::: "memory");
        __syncthreads();
        if (i + 2 < nch) {
            load_chunk((i + 2) % 3, kbase + (i + 2) * 64);
            asm volatile("cp.async.commit_group;" ::: "memory");
        }

        const char* stg = sbuf + (i % 3) * STG_BYTES;

#pragma unroll
        for (int ks = 0; ks < 4; ks++) {          // 4 k16-steps per chunk
            const int cb = ks * 2 + lh;
            uint32_t af[2][4];
#pragma unroll
            for (int mf = 0; mf < 2; mf++) {
                int row = wm * 32 + mf * 16 + lr;
                ldm4(af[mf], sptr(stg + 0 * MAT_BYTES + swz128(row, cb)));
            }
            uint32_t bf[4][4];
#pragma unroll
            for (int g = 0; g < 4; g++) {
                int row = wn * 64 + g * 16 + lr;
                ldm4(bf[g], sptr(stg + 1 * MAT_BYTES + swz128(row, cb)));
            }
            mma_pass1(acc, af, bf);
        }
    }
}

// ---------------------------------------------------------------------------
// Fused Q-GEMM + split-K KV partials.  Grid (8, 160).
// ---------------------------------------------------------------------------
__global__ void __launch_bounds__(256, 2)
gemm_q_kv(const float* __restrict__ fcos, const float* __restrict__ fsin)
{
    extern __shared__ char sbuf[];

    const int tid  = threadIdx.x;
    const int warp = tid >> 5;
    const int lane = tid & 31;
    const int wm   = warp & 3;
    const int wn   = warp >> 2;
    const int lr = lane & 15;
    const int lh = lane >> 4;

    float acc[2][8][4];
#pragma unroll
    for (int i = 0; i < 2; i++)
#pragma unroll
        for (int j = 0; j < 8; j++)
#pragma unroll
            for (int q = 0; q < 4; q++) acc[i][j][q] = 0.f;

    const int qpath = (blockIdx.y < 128);
    int m_tile, n_tile, kbase, nch, gather, z = 0;
    const __half* Bw;
    if (qpath) {
        m_tile = blockIdx.y * 128;
        n_tile = blockIdx.x * 128;
        kbase = 0; nch = 16; gather = 0;
        Bw = g_w;                                        // Wq
    } else {
        int idx = (blockIdx.y - 128) * 8 + blockIdx.x;   // 0..255
        z = idx >> 5;                                    // kv*4+ks
        int kv = z >> 2, ks = z & 3;
        m_tile = ((idx >> 3) & 3) * 128;
        n_tile = (idx & 7) * 128;
        kbase = ks * 256; nch = 4; gather = 1;
        Bw = g_w + (size_t)(1 + kv) * D_MODEL * D_MODEL;
    }

    gemm_mainloop(sbuf, acc, g_x, Bw, m_tile, n_tile, kbase, nch, gather,
                  tid, wm, wn, lr, lh);

    const int qrow = lane >> 2;
    const int qcol = (lane & 3) * 2;
    if (qpath) {
#pragma unroll
        for (int mf = 0; mf < 2; mf++)
#pragma unroll
            for (int nf = 0; nf < 8; nf++) {
                int n = n_tile + wn * 64 + nf * 8 + qcol;
#pragma unroll
                for (int hhalf = 0; hhalf < 2; hhalf++) {
                    int m = m_tile + wm * 32 + mf * 16 + qrow + hhalf * 8;
                    float v0 = acc[mf][nf][hhalf * 2];
                    float v1 = acc[mf][nf][hhalf * 2 + 1];
                    int pos = m & (L_SEQ - 1);
                    int j   = (n & 63) >> 1;
                    float c = __ldg(fcos + pos * 32 + j);
                    float s = __ldg(fsin + pos * 32 + j);
                    float o0 = v0 * c - v1 * s;
                    float o1 = v0 * s + v1 * c;
                    *(uint32_t*)(g_q + (size_t)m * 1024 + n) = pack2h(o0, o1);
                }
            }
    } else {
        float* P = g_kvpart + (size_t)z * KSLICE;
#pragma unroll
        for (int mf = 0; mf < 2; mf++)
#pragma unroll
            for (int nf = 0; nf < 8; nf++) {
                int n = n_tile + wn * 64 + nf * 8 + qcol;
#pragma unroll
                for (int hhalf = 0; hhalf < 2; hhalf++) {
                    int m = m_tile + wm * 32 + mf * 16 + qrow + hhalf * 8;
                    *(float2*)(P + (size_t)m * 1024 + n) =
                        make_float2(acc[mf][nf][hhalf * 2], acc[mf][nf][hhalf * 2 + 1]);
                }
            }
    }
}

// ---------------------------------------------------------------------------
// Standalone Wo GEMM: out = attn @ Wo^T (fp32 out).  Grid (8, 128).
// ---------------------------------------------------------------------------
__global__ void __launch_bounds__(256, 2)
gemm_wo(float* __restrict__ C)
{
    extern __shared__ char sbuf[];

    const int tid  = threadIdx.x;
    const int warp = tid >> 5;
    const int lane = tid & 31;
    const int wm   = warp & 3;
    const int wn   = warp >> 2;
    const int lr = lane & 15;
    const int lh = lane >> 4;
    const int m_tile = blockIdx.y * 128;
    const int n_tile = blockIdx.x * 128;

    float acc[2][8][4];
#pragma unroll
    for (int i = 0; i < 2; i++)
#pragma unroll
        for (int j = 0; j < 8; j++)
#pragma unroll
            for (int q = 0; q < 4; q++) acc[i][j][q] = 0.f;

    gemm_mainloop(sbuf, acc, g_a, g_w + (size_t)3 * D_MODEL * D_MODEL,
                  m_tile, n_tile, 0, 16, 0, tid, wm, wn, lr, lh);

    const int qrow = lane >> 2;
    const int qcol = (lane & 3) * 2;
#pragma unroll
    for (int mf = 0; mf < 2; mf++)
#pragma unroll
        for (int nf = 0; nf < 8; nf++) {
            int n = n_tile + wn * 64 + nf * 8 + qcol;
#pragma unroll
            for (int hhalf = 0; hhalf < 2; hhalf++) {
                int m = m_tile + wm * 32 + mf * 16 + qrow + hhalf * 8;
                *(float2*)(C + (size_t)m * 1024 + n) =
                    make_float2(acc[mf][nf][hhalf * 2], acc[mf][nf][hhalf * 2 + 1]);
            }
        }
}

// ---------------------------------------------------------------------------
// K_proj / V_proj with inline reduce + RoPE(K).  Grid (BH, 8).
// tril dot products use 4 independent accumulation strands (ILP).
// ---------------------------------------------------------------------------
__device__ __forceinline__ float tril_dot(const float* __restrict__ pr,
                                          const float Ts[128][9], int d, int p)
{
    float s0 = 0.f, s1 = 0.f, s2 = 0.f, s3 = 0.f;
    int l = 0;
    for (; l + 3 <= p; l += 4) {
        s0 = fmaf(pr[l],     Ts[l][d],     s0);
        s1 = fmaf(pr[l + 1], Ts[l + 1][d], s1);
        s2 = fmaf(pr[l + 2], Ts[l + 2][d], s2);
        s3 = fmaf(pr[l + 3], Ts[l + 3][d], s3);
    }
    for (; l <= p; l++) s0 = fmaf(pr[l], Ts[l][d], s0);
    return (s0 + s1) + (s2 + s3);
}

__global__ void __launch_bounds__(256)
proj_kernel(const float* __restrict__ kpm, const float* __restrict__ vpm,
            const float* __restrict__ fcos, const float* __restrict__ fsin)
{
    __shared__ float Ts[128][9];
    const int bh = blockIdx.x;
    const int b  = bh >> 4;
    const int hh = bh & 15;
    const int d0 = blockIdx.y * 8;
    const int tid = threadIdx.x;

    // ---- K: sum 4 k-split partials, RoPE pairs ----
    for (int idx = tid; idx < 128 * 4; idx += 256) {
        int l = idx >> 2, dp = (idx & 3) * 2;
        size_t rem = (size_t)(b * 128 + l) * 1024 + hh * 64 + d0 + dp;
        float2 s  = *(const float2*)(g_kvpart + rem);
        float2 p1 = *(const float2*)(g_kvpart + KSLICE + rem);
        float2 p2 = *(const float2*)(g_kvpart + 2 * KSLICE + rem);
        float2 p3 = *(const float2*)(g_kvpart + 3 * KSLICE + rem);
        s.x += p1.x; s.y += p1.y;
        s.x += p2.x; s.y += p2.y;
        s.x += p3.x; s.y += p3.y;
        int j = (d0 + dp) >> 1;
        float c0 = __ldg(fcos + l * 32 + j);
        float s0 = __ldg(fsin + l * 32 + j);
        Ts[l][dp]     = s.x * c0 - s.y * s0;
        Ts[l][dp + 1] = s.x * s0 + s.y * c0;
    }
    __syncthreads();
#pragma unroll
    for (int t = 0; t < 4; t++) {
        int o = tid + t * 256;
        int p = o >> 3, d = o & 7;
        float s = tril_dot(kpm + (size_t)p * 4096, Ts, d, p);
        g_kp[(size_t)bh * 8192 + p * 64 + (d0 + d)] = __float2half_rn(s);
    }
    __syncthreads();

    // ---- V: sum 4 partials ----
    for (int idx = tid; idx < 128 * 8; idx += 256) {
        int l = idx >> 3, d = idx & 7;
        size_t rem = (size_t)(b * 128 + l) * 1024 + hh * 64 + d0 + d;
        float s = g_kvpart[4 * KSLICE + rem];
        s += g_kvpart[5 * KSLICE + rem];
        s += g_kvpart[6 * KSLICE + rem];
        s += g_kvpart[7 * KSLICE + rem];
        Ts[l][d] = s;
    }
    __syncthreads();
#pragma unroll
    for (int t = 0; t < 4; t++) {
        int o = tid + t * 256;
        int p = o >> 3, d = o & 7;
        float s = tril_dot(vpm + (size_t)p * 4096, Ts, d, p);
        g_vt[(size_t)bh * 8192 + (d0 + d) * 128 + p] = __float2half_rn(s);
    }
}

// ---------------------------------------------------------------------------
// Flash-style mma attention (unchanged from R15, passing).
// ---------------------------------------------------------------------------
#define AT_Q  0
#define AT_K  18432
#define AT_VT 36864
#define ATTN_SMEM 54272

__global__ void __launch_bounds__(256)
attn_kernel()
{
    extern __shared__ char smem[];
    const int bh = blockIdx.y;
    const int b  = bh >> 4;
    const int hh = bh & 15;
    const int l0 = blockIdx.x * 128;
    const int tid  = threadIdx.x;
    const int wp   = tid >> 5;
    const int lane = tid & 31;
    const int lr   = lane & 15;
    const int lh   = lane >> 4;
    const int qrow = lane >> 2;
    const int qcol = (lane & 3) * 2;

    const size_t qbase = (size_t)(b * L_SEQ + l0) * 1024 + hh * 64;
#pragma unroll
    for (int t = 0; t < 4; t++) {
        int i = tid + t * 256;
        int r = i >> 3, c = i & 7;
        cpa16(sptr(smem + AT_Q + r * 144 + c * 16), g_q  + qbase + (size_t)r * 1024 + c * 8);
        cpa16(sptr(smem + AT_K + r * 144 + c * 16), g_kp + (size_t)bh * 8192 + r * 64 + c * 8);
        int rv = i >> 4, cv = i & 15;
        cpa16(sptr(smem + AT_VT + rv * 272 + cv * 16), g_vt + (size_t)bh * 8192 + rv * 128 + cv * 8);
    }
    asm volatile("cp.async.commit_group;" ::: "memory");
    asm volatile("cp.async.wait_group 0;" ::: "memory");
    __syncthreads();

    float acc[16][4];
#pragma unroll
    for (int i = 0; i < 16; i++)
#pragma unroll
        for (int q = 0; q < 4; q++) acc[i][q] = 0.f;

#pragma unroll
    for (int ks = 0; ks < 4; ks++) {
        uint32_t aq[4];
        ldm4(aq, sptr(smem + AT_Q + (wp * 16 + lr) * 144 + ks * 32 + lh * 16));
#pragma unroll
        for (int g = 0; g < 8; g++) {
            uint32_t bk[4];
            ldm4(bk, sptr(smem + AT_K + (g * 16 + lr) * 144 + ks * 32 + lh * 16));
            mma_f16(acc[2*g],   aq, bk[0], bk[2]);
            mma_f16(acc[2*g+1], aq, bk[1], bk[3]);
        }
    }

#pragma unroll
    for (int i = 0; i < 16; i++)
#pragma unroll
        for (int q = 0; q < 4; q++) acc[i][q] *= 0.125f;

    if (blockIdx.x == 0) {
        const int r0 = wp * 16 + qrow;
        const int r1 = r0 + 8;
#pragma unroll
        for (int nf = 0; nf < 16; nf++) {
            int p0 = nf * 8 + qcol;
            if (p0 > r0)     acc[nf][0] = -1e30f;
            if (p0 + 1 > r0) acc[nf][1] = -1e30f;
            if (p0 > r1)     acc[nf][2] = -1e30f;
            if (p0 + 1 > r1) acc[nf][3] = -1e30f;
        }
    }

    float mx0 = -1e30f, mx1 = -1e30f;
#pragma unroll
    for (int nf = 0; nf < 16; nf++) {
        mx0 = fmaxf(mx0, fmaxf(acc[nf][0], acc[nf][1]));
        mx1 = fmaxf(mx1, fmaxf(acc[nf][2], acc[nf][3]));
    }
    mx0 = fmaxf(mx0, __shfl_xor_sync(0xffffffffu, mx0, 1));
    mx0 = fmaxf(mx0, __shfl_xor_sync(0xffffffffu, mx0, 2));
    mx1 = fmaxf(mx1, __shfl_xor_sync(0xffffffffu, mx1, 1));
    mx1 = fmaxf(mx1, __shfl_xor_sync(0xffffffffu, mx1, 2));

    float s0 = 0.f, s1 = 0.f;
#pragma unroll
    for (int nf = 0; nf < 16; nf++) {
        acc[nf][0] = __expf(acc[nf][0] - mx0);
        acc[nf][1] = __expf(acc[nf][1] - mx0);
        acc[nf][2] = __expf(acc[nf][2] - mx1);
        acc[nf][3] = __expf(acc[nf][3] - mx1);
        s0 += acc[nf][0] + acc[nf][1];
        s1 += acc[nf][2] + acc[nf][3];
    }
    s0 += __shfl_xor_sync(0xffffffffu, s0, 1);
    s0 += __shfl_xor_sync(0xffffffffu, s0, 2);
    s1 += __shfl_xor_sync(0xffffffffu, s1, 1);
    s1 += __shfl_xor_sync(0xffffffffu, s1, 2);
    const float inv0 = 1.0f / s0;
    const float inv1 = 1.0f / s1;

    float o[8][4];
#pragma unroll
    for (int i = 0; i < 8; i++)
#pragma unroll
        for (int q = 0; q < 4; q++) o[i][q] = 0.f;

#pragma unroll
    for (int kc = 0; kc < 8; kc++) {
        uint32_t aw[4];
        aw[0] = pack2h(acc[2*kc][0],   acc[2*kc][1]);
        aw[1] = pack2h(acc[2*kc][2],   acc[2*kc][3]);
        aw[2] = pack2h(acc[2*kc+1][0], acc[2*kc+1][1]);
        aw[3] = pack2h(acc[2*kc+1][2], acc[2*kc+1][3]);
#pragma unroll
        for (int g = 0; g < 4; g++) {
            uint32_t bv[4];
            ldm4(bv, sptr(smem + AT_VT + (g * 16 + lr) * 272 + kc * 32 + lh * 16));
            mma_f16(o[2*g],   aw, bv[0], bv[2]);
            mma_f16(o[2*g+1], aw, bv[1], bv[3]);
        }
    }

    const size_t row0 = (size_t)(b * L_SEQ + l0 + wp * 16 + qrow);
    const size_t row1 = row0 + 8;
#pragma unroll
    for (int nf = 0; nf < 8; nf++) {
        int col = hh * 64 + nf * 8 + qcol;
        *(uint32_t*)(g_a + row0 * 1024 + col) = pack2h(o[nf][0] * inv0, o[nf][1] * inv0);
        *(uint32_t*)(g_a + row1 * 1024 + col) = pack2h(o[nf][2] * inv1, o[nf][3] * inv1);
    }
}

// ---------------------------------------------------------------------------
extern "C" void kernel_launch(void* const* d_in, const int* in_sizes, int n_in,
                              void* d_out, int out_size)
{
    const float* x    = (const float*)d_in[0];
    const float* fcos = (const float*)d_in[1];
    const float* fsin = (const float*)d_in[2];
    const float* Wq   = (const float*)d_in[3];
    const float* Wk   = (const float*)d_in[4];
    const float* Wv   = (const float*)d_in[5];
    const float* Wo   = (const float*)d_in[6];
    const float* kpm  = (const float*)d_in[7];
    const float* vpm  = (const float*)d_in[8];
    float* out = (float*)d_out;

    cudaFuncSetAttribute(attn_kernel,
                         cudaFuncAttributeMaxDynamicSharedMemorySize, ATTN_SMEM);
    cudaFuncSetAttribute(gemm_q_kv,
                         cudaFuncAttributeMaxDynamicSharedMemorySize, SM_GEMM);
    cudaFuncSetAttribute(gemm_wo,
                         cudaFuncAttributeMaxDynamicSharedMemorySize, SM_GEMM);

    dim3 blk(256);
    // fp32 -> fp16 converts (one launch)
    convert_all<<<4096, blk>>>(x, Wq, Wk, Wv, Wo);

    // fused: Q = rope(x @ Wq^T)  +  split-K KV partials (tail-filled)
    gemm_q_kv<<<dim3(8, 160), blk, SM_GEMM>>>(fcos, fsin);

    // Linformer tril projections (inline reduce + RoPE(K), 4-strand ILP)
    proj_kernel<<<dim3(BH, 8), blk>>>(kpm, vpm, fcos, fsin);

    // flash-style mma attention
    attn_kernel<<<dim3(L_SEQ / 128, BH), blk, ATTN_SMEM>>>();

    // out = attn @ Wo^T
    gemm_wo<<<dim3(8, 128), blk, SM_GEMM>>>(out);
}